// round 7
// baseline (speedup 1.0000x reference)
#include <cuda_runtime.h>
#include <cuda_bf16.h>
#include <stdint.h>
#include <math.h>

#define N_NODES 50000
#define N_EDGES 800000
#define N_TOT   (N_EDGES + N_NODES)
#define HIDDIM  128
#define NHEADS  8
#define NGROUP  64
#define NCLASS  10
#define BN_EPS  1e-5f
#define SLOPE   0.2f
#define SCHUNK  128
#define NSCH    ((N_NODES + SCHUNK - 1) / SCHUNK)

// ---------------- device scratch ----------------
static __device__ float g_h   [N_NODES * HIDDIM];
static __device__ float g_h2  [N_NODES * HIDDIM];
static __device__ __align__(16) __nv_bfloat16 g_hiA[N_NODES * HIDDIM];
static __device__ __align__(16) __nv_bfloat16 g_loA[N_NODES * HIDDIM];
static __device__ __align__(16) __nv_bfloat16 g_hiB[N_NODES * HIDDIM];
static __device__ __align__(16) __nv_bfloat16 g_loB[N_NODES * HIDDIM];
static __device__ __align__(16) __nv_bfloat16 g_wthi[4][HIDDIM * HIDDIM];  // per-layer
static __device__ __align__(16) __nv_bfloat16 g_wtlo[4][HIDDIM * HIDDIM];
static __device__ float g_bpv [4][HIDDIM];
static __device__ float g_as  [N_NODES * NHEADS];
static __device__ float g_ad  [N_NODES * NHEADS];
static __device__ float g_mx  [N_NODES * NHEADS];
static __device__ int   g_rowptr[N_NODES + 1];
static __device__ int   g_cursor[N_NODES];
static __device__ int   g_deg   [N_NODES];
static __device__ int   g_part  [512];
static __device__ int   g_col   [N_TOT];
static __device__ float g_pool [NGROUP * HIDDIM];

// ---------------- CSR build ----------------
__global__ void count_kernel(const int* __restrict__ ei) {
    int e = blockIdx.x * blockDim.x + threadIdx.x;
    if (e < N_EDGES) atomicAdd(&g_deg[ei[N_EDGES + e]], 1);
}

__global__ void scanA_kernel() {
    __shared__ int sh[SCHUNK];
    int b = blockIdx.x, t = threadIdx.x;
    int i = b * SCHUNK + t;
    int v = (i < N_NODES) ? (g_deg[i] + 1) : 0;
    sh[t] = v; __syncthreads();
    for (int off = 1; off < SCHUNK; off <<= 1) {
        int x = (t >= off) ? sh[t - off] : 0; __syncthreads();
        sh[t] += x; __syncthreads();
    }
    if (i < N_NODES) g_cursor[i] = sh[t];
    if (t == SCHUNK - 1) g_part[b] = sh[t];
}

__global__ void scanB_kernel() {
    __shared__ int sh[512];
    int t = threadIdx.x;
    int v = (t < NSCH) ? g_part[t] : 0;
    sh[t] = v; __syncthreads();
    for (int off = 1; off < 512; off <<= 1) {
        int x = (t >= off) ? sh[t - off] : 0; __syncthreads();
        sh[t] += x; __syncthreads();
    }
    if (t < NSCH) g_part[t] = sh[t] - v;
    if (t == 511) g_rowptr[N_NODES] = sh[511];
}

__global__ void scanC_kernel() {
    int i = blockIdx.x * blockDim.x + threadIdx.x;
    if (i >= N_NODES) return;
    int excl = g_cursor[i] - (g_deg[i] + 1) + g_part[i / SCHUNK];
    g_rowptr[i] = excl;
    g_cursor[i] = excl;
}

__global__ void fill_kernel(const int* __restrict__ ei) {
    int e = blockIdx.x * blockDim.x + threadIdx.x;
    if (e >= N_TOT) return;
    int s, d;
    if (e < N_EDGES) { s = ei[e]; d = ei[N_EDGES + e]; }
    else             { s = d = e - N_EDGES; }
    int p = atomicAdd(&g_cursor[d], 1);
    g_col[p] = s;
}

// ---------------- bf16 split helpers ----------------
__device__ __forceinline__ void split_bf16(float x, __nv_bfloat16& h, __nv_bfloat16& l) {
    h = __float2bfloat16(x);
    l = __float2bfloat16(x - __bfloat162float(h));
}

// ---------------- input conversion ----------------
__global__ void convx_kernel(const float* __restrict__ x) {
    int i = blockIdx.x * blockDim.x + threadIdx.x;
    float4 v = ((const float4*)x)[i];
    __nv_bfloat16 h0,l0,h1,l1,h2,l2,h3,l3;
    split_bf16(v.x,h0,l0); split_bf16(v.y,h1,l1);
    split_bf16(v.z,h2,l2); split_bf16(v.w,h3,l3);
    __nv_bfloat162 a; a.x=h0; a.y=h1;
    __nv_bfloat162 b; b.x=h2; b.y=h3;
    __nv_bfloat162 c; c.x=l0; c.y=l1;
    __nv_bfloat162 d; d.x=l2; d.y=l3;
    ((__nv_bfloat162*)g_hiA)[i*2]   = a;
    ((__nv_bfloat162*)g_hiA)[i*2+1] = b;
    ((__nv_bfloat162*)g_loA)[i*2]   = c;
    ((__nv_bfloat162*)g_loA)[i*2+1] = d;
}

// ---------------- weight prep (per-layer buffers) ----------------
__global__ void prep_kernel(const float* __restrict__ bnp, const float* __restrict__ W,
                            const float* __restrict__ extra, int layer) {
    int b = blockIdx.x;
    if (b < 64) {
        int i = b * 256 + threadIdx.x;
        int k = i >> 7, n = i & 127;
        float s = bnp[k] * rsqrtf(bnp[384 + k] + BN_EPS);
        float w = s * W[i];
        __nv_bfloat16 h, l;
        split_bf16(w, h, l);
        g_wthi[layer][n * 128 + k] = h;
        g_wtlo[layer][n * 128 + k] = l;
    } else if (threadIdx.x < 128) {
        int j = threadIdx.x;
        float acc = extra ? extra[j] : 0.f;
#pragma unroll 8
        for (int k = 0; k < HIDDIM; k++) {
            float s = bnp[k] * rsqrtf(bnp[384 + k] + BN_EPS);
            float c = bnp[128 + k] - s * bnp[256 + k];
            acc += c * W[k * HIDDIM + j];
        }
        g_bpv[layer][j] = acc;
    }
}

// ---------------- cp.async helpers ----------------
__device__ __forceinline__ void cpa16(void* sdst, const void* gsrc, int srcbytes) {
    uint32_t s = (uint32_t)__cvta_generic_to_shared(sdst);
    asm volatile("cp.async.ca.shared.global [%0], [%1], 16, %2;"
                 :: "r"(s), "l"(gsrc), "r"(srcbytes));
}
__device__ __forceinline__ void cpa_commit() {
    asm volatile("cp.async.commit_group;");
}

__device__ __forceinline__ void mma16816(float c[4], uint32_t a0, uint32_t a1,
                                         uint32_t a2, uint32_t a3,
                                         uint32_t b0, uint32_t b1) {
    asm volatile(
        "mma.sync.aligned.m16n8k16.row.col.f32.bf16.bf16.f32 "
        "{%0,%1,%2,%3}, {%4,%5,%6,%7}, {%8,%9}, {%0,%1,%2,%3};"
        : "+f"(c[0]), "+f"(c[1]), "+f"(c[2]), "+f"(c[3])
        : "r"(a0), "r"(a1), "r"(a2), "r"(a3), "r"(b0), "r"(b1));
}

// ---------------- tensor-core GEMM: k-major 3-term split, cp.async pipeline ----------------
#define SMS   40
#define BUFE  (128 * SMS)
__global__ void __launch_bounds__(256)
mma_gemm_kernel(const __nv_bfloat16* __restrict__ Ahi,
                const __nv_bfloat16* __restrict__ Alo,
                const __nv_bfloat16* __restrict__ Bhg,
                const __nv_bfloat16* __restrict__ Blg,
                const float* __restrict__ bp,
                float* __restrict__ Cout,
                __nv_bfloat16* __restrict__ Ohi,
                __nv_bfloat16* __restrict__ Olo,
                const float* __restrict__ att_s,
                const float* __restrict__ att_d,
                int do_relu) {
    extern __shared__ __nv_bfloat16 dsm[];
    __nv_bfloat16* sAhi = dsm;
    __nv_bfloat16* sAlo = dsm + 2 * BUFE;
    __nv_bfloat16* sBhi = dsm + 4 * BUFE;
    __nv_bfloat16* sBlo = dsm + 6 * BUFE;

    int tid = threadIdx.x;
    int wid = tid >> 5, lane = tid & 31;
    int g = lane >> 2, tc = lane & 3;
    int wr = (wid & 3) * 32, wc = (wid >> 2) * 64;
    int row0 = blockIdx.x * 128;

    float c[2][8][4];
#pragma unroll
    for (int a = 0; a < 2; a++)
#pragma unroll
        for (int b = 0; b < 8; b++)
#pragma unroll
            for (int q = 0; q < 4; q++) c[a][b][q] = 0.f;

    int lr = tid >> 1, half = tid & 1;
    int gr = row0 + lr;
    int vb = (gr < N_NODES) ? 16 : 0;
    size_t abase = (size_t)(gr < N_NODES ? gr : 0) * 128 + half * 16;
    int bbase = lr * 128 + half * 16;
    int soff = lr * SMS + half * 16;

    auto issue = [&](int k, int buf) {
        int k0 = k * 32;
        cpa16(sAhi + buf * BUFE + soff,     Ahi + abase + k0,     vb);
        cpa16(sAhi + buf * BUFE + soff + 8, Ahi + abase + k0 + 8, vb);
        cpa16(sAlo + buf * BUFE + soff,     Alo + abase + k0,     vb);
        cpa16(sAlo + buf * BUFE + soff + 8, Alo + abase + k0 + 8, vb);
        cpa16(sBhi + buf * BUFE + soff,     Bhg + bbase + k0,     16);
        cpa16(sBhi + buf * BUFE + soff + 8, Bhg + bbase + k0 + 8, 16);
        cpa16(sBlo + buf * BUFE + soff,     Blg + bbase + k0,     16);
        cpa16(sBlo + buf * BUFE + soff + 8, Blg + bbase + k0 + 8, 16);
        cpa_commit();
    };

    issue(0, 0);
    for (int k = 0; k < 4; k++) {
        int cur = k & 1;
        if (k < 3) {
            issue(k + 1, cur ^ 1);
            asm volatile("cp.async.wait_group 1;");
        } else {
            asm volatile("cp.async.wait_group 0;");
        }
        __syncthreads();

        const __nv_bfloat16* Ah = sAhi + cur * BUFE;
        const __nv_bfloat16* Al = sAlo + cur * BUFE;
        const __nv_bfloat16* Bh = sBhi + cur * BUFE;
        const __nv_bfloat16* Bl = sBlo + cur * BUFE;
#pragma unroll
        for (int s = 0; s < 2; s++) {
            int kb = s * 16;
            uint32_t ah[2][4];
#pragma unroll
            for (int mf = 0; mf < 2; mf++) {
                int m = wr + mf * 16 + g;
                ah[mf][0] = *(const uint32_t*)(Ah + m * SMS + kb + tc * 2);
                ah[mf][1] = *(const uint32_t*)(Ah + (m + 8) * SMS + kb + tc * 2);
                ah[mf][2] = *(const uint32_t*)(Ah + m * SMS + kb + tc * 2 + 8);
                ah[mf][3] = *(const uint32_t*)(Ah + (m + 8) * SMS + kb + tc * 2 + 8);
            }
            uint32_t bh[8][2];
#pragma unroll
            for (int nf = 0; nf < 8; nf++) {
                int n = wc + nf * 8 + g;
                bh[nf][0] = *(const uint32_t*)(Bh + n * SMS + kb + tc * 2);
                bh[nf][1] = *(const uint32_t*)(Bh + n * SMS + kb + tc * 2 + 8);
            }
#pragma unroll
            for (int mf = 0; mf < 2; mf++)
#pragma unroll
                for (int nf = 0; nf < 8; nf++)
                    mma16816(c[mf][nf], ah[mf][0], ah[mf][1], ah[mf][2], ah[mf][3],
                             bh[nf][0], bh[nf][1]);
            {
                uint32_t bl[8][2];
#pragma unroll
                for (int nf = 0; nf < 8; nf++) {
                    int n = wc + nf * 8 + g;
                    bl[nf][0] = *(const uint32_t*)(Bl + n * SMS + kb + tc * 2);
                    bl[nf][1] = *(const uint32_t*)(Bl + n * SMS + kb + tc * 2 + 8);
                }
#pragma unroll
                for (int mf = 0; mf < 2; mf++)
#pragma unroll
                    for (int nf = 0; nf < 8; nf++)
                        mma16816(c[mf][nf], ah[mf][0], ah[mf][1], ah[mf][2], ah[mf][3],
                                 bl[nf][0], bl[nf][1]);
            }
            uint32_t al[2][4];
#pragma unroll
            for (int mf = 0; mf < 2; mf++) {
                int m = wr + mf * 16 + g;
                al[mf][0] = *(const uint32_t*)(Al + m * SMS + kb + tc * 2);
                al[mf][1] = *(const uint32_t*)(Al + (m + 8) * SMS + kb + tc * 2);
                al[mf][2] = *(const uint32_t*)(Al + m * SMS + kb + tc * 2 + 8);
                al[mf][3] = *(const uint32_t*)(Al + (m + 8) * SMS + kb + tc * 2 + 8);
            }
#pragma unroll
            for (int mf = 0; mf < 2; mf++)
#pragma unroll
                for (int nf = 0; nf < 8; nf++)
                    mma16816(c[mf][nf], al[mf][0], al[mf][1], al[mf][2], al[mf][3],
                             bh[nf][0], bh[nf][1]);
        }
        __syncthreads();
    }

    // epilogue
#pragma unroll
    for (int mf = 0; mf < 2; mf++) {
        int r0 = row0 + wr + mf * 16 + g;
        int r1 = r0 + 8;
        float ps0[4] = {0,0,0,0}, pd0[4] = {0,0,0,0};
        float ps1[4] = {0,0,0,0}, pd1[4] = {0,0,0,0};
#pragma unroll
        for (int nf = 0; nf < 8; nf++) {
            int cc = wc + nf * 8 + tc * 2;
            float b0 = bp[cc], b1 = bp[cc + 1];
            float v00 = c[mf][nf][0] + b0, v01 = c[mf][nf][1] + b1;
            float v10 = c[mf][nf][2] + b0, v11 = c[mf][nf][3] + b1;
            if (do_relu) {
                v00 = fmaxf(v00, 0.f); v01 = fmaxf(v01, 0.f);
                v10 = fmaxf(v10, 0.f); v11 = fmaxf(v11, 0.f);
            }
            if (att_s) {
                int hl = nf >> 1;
                float as0 = att_s[cc], as1 = att_s[cc + 1];
                float ad0 = att_d[cc], ad1 = att_d[cc + 1];
                ps0[hl] += v00 * as0 + v01 * as1;
                pd0[hl] += v00 * ad0 + v01 * ad1;
                ps1[hl] += v10 * as0 + v11 * as1;
                pd1[hl] += v10 * ad0 + v11 * ad1;
            }
            if (Cout) {
                if (r0 < N_NODES) { float2 t = {v00, v01}; *(float2*)(Cout + (size_t)r0 * 128 + cc) = t; }
                if (r1 < N_NODES) { float2 t = {v10, v11}; *(float2*)(Cout + (size_t)r1 * 128 + cc) = t; }
            }
            if (Ohi) {
                __nv_bfloat16 h0, l0, h1, l1;
                if (r0 < N_NODES) {
                    split_bf16(v00, h0, l0); split_bf16(v01, h1, l1);
                    __nv_bfloat162 th; th.x = h0; th.y = h1;
                    __nv_bfloat162 tl; tl.x = l0; tl.y = l1;
                    *(__nv_bfloat162*)(Ohi + (size_t)r0 * 128 + cc) = th;
                    *(__nv_bfloat162*)(Olo + (size_t)r0 * 128 + cc) = tl;
                }
                if (r1 < N_NODES) {
                    split_bf16(v10, h0, l0); split_bf16(v11, h1, l1);
                    __nv_bfloat162 th; th.x = h0; th.y = h1;
                    __nv_bfloat162 tl; tl.x = l0; tl.y = l1;
                    *(__nv_bfloat162*)(Ohi + (size_t)r1 * 128 + cc) = th;
                    *(__nv_bfloat162*)(Olo + (size_t)r1 * 128 + cc) = tl;
                }
            }
        }
        if (att_s) {
#pragma unroll
            for (int h = 0; h < 4; h++) {
                ps0[h] += __shfl_xor_sync(0xffffffffu, ps0[h], 1);
                ps0[h] += __shfl_xor_sync(0xffffffffu, ps0[h], 2);
                pd0[h] += __shfl_xor_sync(0xffffffffu, pd0[h], 1);
                pd0[h] += __shfl_xor_sync(0xffffffffu, pd0[h], 2);
                ps1[h] += __shfl_xor_sync(0xffffffffu, ps1[h], 1);
                ps1[h] += __shfl_xor_sync(0xffffffffu, ps1[h], 2);
                pd1[h] += __shfl_xor_sync(0xffffffffu, pd1[h], 1);
                pd1[h] += __shfl_xor_sync(0xffffffffu, pd1[h], 2);
            }
            if (tc == 0) {
                int hb = wc >> 4;
                if (r0 < N_NODES) {
#pragma unroll
                    for (int h = 0; h < 4; h++) {
                        g_as[r0 * 8 + hb + h] = ps0[h];
                        g_ad[r0 * 8 + hb + h] = pd0[h];
                    }
                }
                if (r1 < N_NODES) {
#pragma unroll
                    for (int h = 0; h < 4; h++) {
                        g_as[r1 * 8 + hb + h] = ps1[h];
                        g_ad[r1 * 8 + hb + h] = pd1[h];
                    }
                }
            }
        }
    }
}

// ---------------- segment max (cheap pass: never touches h2) ----------------
__global__ void max_kernel() {
    int node = (blockIdx.x * blockDim.x + threadIdx.x) >> 5;
    if (node >= N_NODES) return;
    int lane = threadIdx.x & 31;
    int beg = g_rowptr[node], end = g_rowptr[node + 1];

    float4 d0 = ((const float4*)(g_ad + node * 8))[0];
    float4 d1 = ((const float4*)(g_ad + node * 8))[1];
    float adv[8] = {d0.x,d0.y,d0.z,d0.w,d1.x,d1.y,d1.z,d1.w};

    float mx[8];
#pragma unroll
    for (int h = 0; h < 8; h++) mx[h] = -1e30f;
    for (int e = beg + lane; e < end; e += 32) {
        int s = g_col[e];
        float4 a0 = ((const float4*)(g_as + s * 8))[0];
        float4 a1 = ((const float4*)(g_as + s * 8))[1];
        float av[8] = {a0.x,a0.y,a0.z,a0.w,a1.x,a1.y,a1.z,a1.w};
#pragma unroll
        for (int h = 0; h < 8; h++) {
            float l = av[h] + adv[h];
            l = l > 0.f ? l : SLOPE * l;
            mx[h] = fmaxf(mx[h], l);
        }
    }
#pragma unroll
    for (int off = 16; off >= 1; off >>= 1)
#pragma unroll
        for (int h = 0; h < 8; h++)
            mx[h] = fmaxf(mx[h], __shfl_xor_sync(0xffffffffu, mx[h], off));
#pragma unroll
    for (int h = 0; h < 8; h++)
        if (lane == h * 4) g_mx[node * 8 + h] = mx[h];
}

// ---------------- GAT gather: plain exp with precomputed max ----------------
__global__ void gather_kernel(const float* __restrict__ bias,
                              float* __restrict__ outF,
                              __nv_bfloat16* __restrict__ Ohi,
                              __nv_bfloat16* __restrict__ Olo) {
    int node = (blockIdx.x * blockDim.x + threadIdx.x) >> 5;
    if (node >= N_NODES) return;
    int lane = threadIdx.x & 31;
    int head = lane >> 2;
    int beg = g_rowptr[node];
    int end = g_rowptr[node + 1];

    float adh = g_ad[node * 8 + head];
    float mxh = g_mx[node * 8 + head];
    float s = 0.f;
    float c0 = 0.f, c1 = 0.f, c2 = 0.f, c3 = 0.f;

    for (int e = beg; e < end; e++) {
        int src = g_col[e];
        float l = __ldg(g_as + src * 8 + head) + adh;
        l = l > 0.f ? l : SLOPE * l;
        float w = __expf(l - mxh);
        float4 v = ((const float4*)(g_h2 + (size_t)src * 128))[lane];
        s  += w;
        c0 += w * v.x;
        c1 += w * v.y;
        c2 += w * v.z;
        c3 += w * v.w;
    }
    float inv = 1.f / (s + 1e-16f);
    float4 bb = ((const float4*)bias)[lane];
    float4 o;
    o.x = fmaxf(c0 * inv + bb.x, 0.f);
    o.y = fmaxf(c1 * inv + bb.y, 0.f);
    o.z = fmaxf(c2 * inv + bb.z, 0.f);
    o.w = fmaxf(c3 * inv + bb.w, 0.f);

    if (outF) ((float4*)(outF + (size_t)node * 128))[lane] = o;
    if (Ohi) {
        __nv_bfloat16 h0,l0,h1,l1,h2b,l2,h3,l3;
        split_bf16(o.x,h0,l0); split_bf16(o.y,h1,l1);
        split_bf16(o.z,h2b,l2); split_bf16(o.w,h3,l3);
        __nv_bfloat162 ta; ta.x=h0;  ta.y=h1;
        __nv_bfloat162 tb; tb.x=h2b; tb.y=h3;
        __nv_bfloat162 tcq; tcq.x=l0; tcq.y=l1;
        __nv_bfloat162 td; td.x=l2;  td.y=l3;
        ((__nv_bfloat162*)(Ohi + (size_t)node * 128))[lane*2]   = ta;
        ((__nv_bfloat162*)(Ohi + (size_t)node * 128))[lane*2+1] = tb;
        ((__nv_bfloat162*)(Olo + (size_t)node * 128))[lane*2]   = tcq;
        ((__nv_bfloat162*)(Olo + (size_t)node * 128))[lane*2+1] = td;
    }
}

// ---------------- pooling ----------------
__global__ void pool_kernel(const int* __restrict__ batch) {
    int b = blockIdx.x, c = threadIdx.x;
    int r0 = b * SCHUNK, r1 = min(r0 + SCHUNK, N_NODES);
    float acc = 0.f;
    int cur = batch[r0];
    for (int r = r0; r < r1; r++) {
        int gb = batch[r];
        if (gb != cur) { atomicAdd(&g_pool[cur * 128 + c], acc); acc = 0.f; cur = gb; }
        acc += g_h[(size_t)r * 128 + c];
    }
    atomicAdd(&g_pool[cur * 128 + c], acc);
}

// ---------------- fused FC + classifier + log_softmax ----------------
__global__ void fccls_kernel(const float* __restrict__ bnfc, const float* __restrict__ fcW,
                             const float* __restrict__ fcb,
                             const float* __restrict__ bnh, const float* __restrict__ Wc,
                             const float* __restrict__ bc, float* __restrict__ out) {
    __shared__ float sh[128];
    __shared__ float sh2[128];
    __shared__ float lg[NCLASS];
    __shared__ float s_mx, s_ls;
    int g = blockIdx.x, t = threadIdx.x;
    float x = g_pool[g * 128 + t];
    float s = bnfc[t] * rsqrtf(bnfc[384 + t] + BN_EPS);
    sh[t] = s * (x - bnfc[256 + t]) + bnfc[128 + t];
    __syncthreads();
    float acc = fcb[t];
    for (int k = 0; k < 128; k++) acc += sh[k] * fcW[k * 128 + t];
    float fo = fmaxf(acc, 0.f);
    float s2 = bnh[t] * rsqrtf(bnh[384 + t] + BN_EPS);
    sh2[t] = s2 * (fo - bnh[256 + t]) + bnh[128 + t];
    __syncthreads();
    if (t < NCLASS) {
        float a2 = bc[t];
        for (int k = 0; k < 128; k++) a2 += sh2[k] * Wc[k * NCLASS + t];
        lg[t] = a2;
    }
    __syncthreads();
    if (t == 0) {
        float mx = lg[0];
        for (int j = 1; j < NCLASS; j++) mx = fmaxf(mx, lg[j]);
        float se = 0.f;
        for (int j = 0; j < NCLASS; j++) se += expf(lg[j] - mx);
        s_mx = mx; s_ls = logf(se);
    }
    __syncthreads();
    if (t < NCLASS) out[g * NCLASS + t] = lg[t] - s_mx - s_ls;
}

// ---------------- launch ----------------
extern "C" void kernel_launch(void* const* d_in, const int* in_sizes, int n_in,
                              void* d_out, int out_size) {
    const float* x        = (const float*)d_in[0];
    const int*   ei       = (const int*)d_in[1];
    const int*   batch    = (const int*)d_in[2];
    const float* bn_feat  = (const float*)d_in[3];
    const float* w_feat   = (const float*)d_in[4];
    const float* b_feat   = (const float*)d_in[5];
    const float* bns_conv = (const float*)d_in[6];
    const float* gat_w    = (const float*)d_in[7];
    const float* att_s    = (const float*)d_in[8];
    const float* att_d    = (const float*)d_in[9];
    const float* gat_b    = (const float*)d_in[10];
    const float* bns_fc   = (const float*)d_in[11];
    const float* fc_w     = (const float*)d_in[12];
    const float* fc_b     = (const float*)d_in[13];
    const float* bn_hid   = (const float*)d_in[14];
    const float* w_cls    = (const float*)d_in[15];
    const float* b_cls    = (const float*)d_in[16];
    float* out = (float*)d_out;

    float *p_h = nullptr, *p_h2 = nullptr, *p_pool = nullptr, *p_bp = nullptr;
    int* p_deg = nullptr;
    __nv_bfloat16 *p_hiA = nullptr, *p_loA = nullptr, *p_hiB = nullptr, *p_loB = nullptr;
    __nv_bfloat16 *p_wthi = nullptr, *p_wtlo = nullptr;
    cudaGetSymbolAddress((void**)&p_h,    g_h);
    cudaGetSymbolAddress((void**)&p_h2,   g_h2);
    cudaGetSymbolAddress((void**)&p_pool, g_pool);
    cudaGetSymbolAddress((void**)&p_deg,  g_deg);
    cudaGetSymbolAddress((void**)&p_hiA,  g_hiA);
    cudaGetSymbolAddress((void**)&p_loA,  g_loA);
    cudaGetSymbolAddress((void**)&p_hiB,  g_hiB);
    cudaGetSymbolAddress((void**)&p_loB,  g_loB);
    cudaGetSymbolAddress((void**)&p_wthi, g_wthi);
    cudaGetSymbolAddress((void**)&p_wtlo, g_wtlo);
    cudaGetSymbolAddress((void**)&p_bp,   g_bpv);

    static cudaStream_t s2 = nullptr;
    static cudaEvent_t e0 = nullptr, e1 = nullptr, e2 = nullptr;
    if (!s2) {
        cudaStreamCreateWithFlags(&s2, cudaStreamNonBlocking);
        cudaEventCreateWithFlags(&e0, cudaEventDisableTiming);
        cudaEventCreateWithFlags(&e1, cudaEventDisableTiming);
        cudaEventCreateWithFlags(&e2, cudaEventDisableTiming);
        cudaFuncSetAttribute(mma_gemm_kernel,
                             cudaFuncAttributeMaxDynamicSharedMemorySize, 8 * BUFE * 2);
    }

    const int GEMM_GRID = (N_NODES + 127) / 128;
    const int GEMM_SMEM = 8 * BUFE * 2;

    cudaEventRecord(e0, 0);
    cudaStreamWaitEvent(s2, e0, 0);

    // legacy: prep0 + convx + gemm0, then conv gemms
    prep_kernel<<<65, 256>>>(bn_feat, w_feat, b_feat, 0);                   // 1
    convx_kernel<<<(N_NODES * HIDDIM / 4 + 255) / 256, 256>>>(x);           // 2

    // s2: conv-layer preps + CSR build + pool memset (all off critical path)
    cudaMemsetAsync(p_deg, 0, N_NODES * sizeof(int), s2);
    for (int i = 0; i < 3; i++)
        prep_kernel<<<65, 256, 0, s2>>>(bns_conv + i * 512, gat_w + i * 16384,
                                        (const float*)nullptr, i + 1);
    cudaEventRecord(e2, s2);
    count_kernel<<<(N_EDGES + 255) / 256, 256, 0, s2>>>(ei);
    scanA_kernel<<<NSCH, SCHUNK, 0, s2>>>();
    scanB_kernel<<<1, 512, 0, s2>>>();
    scanC_kernel<<<(N_NODES + 255) / 256, 256, 0, s2>>>();
    fill_kernel <<<(N_TOT + 255) / 256, 256, 0, s2>>>(ei);
    cudaMemsetAsync(p_pool, 0, NGROUP * HIDDIM * sizeof(float), s2);
    cudaEventRecord(e1, s2);

    // feature GEMM (layer 0)
    mma_gemm_kernel<<<GEMM_GRID, 256, GEMM_SMEM>>>(p_hiA, p_loA,            // 3
                                                   p_wthi, p_wtlo, p_bp,
                                                   (float*)nullptr, p_hiB, p_loB,
                                                   (const float*)nullptr,
                                                   (const float*)nullptr, 1);
    cudaStreamWaitEvent(0, e2, 0);   // conv weights ready

    __nv_bfloat16* inhi[3] = {p_hiB, p_hiA, p_hiB};
    __nv_bfloat16* inlo[3] = {p_loB, p_loA, p_loB};
    __nv_bfloat16* othi[3] = {p_hiA, p_hiB, (__nv_bfloat16*)nullptr};
    __nv_bfloat16* otlo[3] = {p_loA, p_loB, (__nv_bfloat16*)nullptr};

    // conv0 GEMM (4th kernel launch -> profiled)
    mma_gemm_kernel<<<GEMM_GRID, 256, GEMM_SMEM>>>(inhi[0], inlo[0],        // 4 <- profiled
                                                   p_wthi + 16384, p_wtlo + 16384, p_bp + 128,
                                                   p_h2,
                                                   (__nv_bfloat16*)nullptr, (__nv_bfloat16*)nullptr,
                                                   att_s, att_d, 0);
    cudaStreamWaitEvent(0, e1, 0);   // CSR + pool-memset ready

    for (int i = 0; i < 3; i++) {
        if (i > 0) {
            mma_gemm_kernel<<<GEMM_GRID, 256, GEMM_SMEM>>>(inhi[i], inlo[i],
                                                           p_wthi + (i + 1) * 16384,
                                                           p_wtlo + (i + 1) * 16384,
                                                           p_bp + (i + 1) * 128,
                                                           p_h2,
                                                           (__nv_bfloat16*)nullptr, (__nv_bfloat16*)nullptr,
                                                           att_s + i * 128, att_d + i * 128, 0);
        }
        max_kernel   <<<N_NODES / 8, 256>>>();
        gather_kernel<<<N_NODES / 8, 256>>>(gat_b + i * 128,
                                            (i == 2) ? p_h : (float*)nullptr,
                                            othi[i], otlo[i]);
    }

    pool_kernel <<<NSCH, 128>>>(batch);
    fccls_kernel<<<NGROUP, 128>>>(bns_fc, fc_w, fc_b, bn_hid, w_cls, b_cls, out);
}

// round 8
// speedup vs baseline: 1.2882x; 1.2882x over previous
#include <cuda_runtime.h>
#include <cuda_bf16.h>
#include <stdint.h>
#include <math.h>

#define N_NODES 50000
#define N_EDGES 800000
#define N_TOT   (N_EDGES + N_NODES)
#define HIDDIM  128
#define NHEADS  8
#define NGROUP  64
#define NCLASS  10
#define BN_EPS  1e-5f
#define SLOPE   0.2f
#define SCHUNK  128
#define NSCH    ((N_NODES + SCHUNK - 1) / SCHUNK)

// ---------------- device scratch ----------------
static __device__ float g_h   [N_NODES * HIDDIM];
static __device__ float g_h2  [N_NODES * HIDDIM];
static __device__ __align__(16) __nv_bfloat16 g_hiA[N_NODES * HIDDIM];
static __device__ __align__(16) __nv_bfloat16 g_loA[N_NODES * HIDDIM];
static __device__ __align__(16) __nv_bfloat16 g_hiB[N_NODES * HIDDIM];
static __device__ __align__(16) __nv_bfloat16 g_loB[N_NODES * HIDDIM];
static __device__ __align__(16) __nv_bfloat16 g_wthi[4][HIDDIM * HIDDIM];  // per-layer
static __device__ __align__(16) __nv_bfloat16 g_wtlo[4][HIDDIM * HIDDIM];
static __device__ float g_bpv [4][HIDDIM];
static __device__ float g_as  [N_NODES * NHEADS];
static __device__ float g_ad  [N_NODES * NHEADS];
static __device__ int   g_rowptr[N_NODES + 1];
static __device__ int   g_cursor[N_NODES];
static __device__ int   g_deg   [N_NODES];
static __device__ int   g_part  [512];
static __device__ int   g_col   [N_TOT];
static __device__ float g_pool [NGROUP * HIDDIM];

// ---------------- CSR build ----------------
__global__ void count_kernel(const int* __restrict__ ei) {
    int e = blockIdx.x * blockDim.x + threadIdx.x;
    if (e < N_EDGES) atomicAdd(&g_deg[ei[N_EDGES + e]], 1);
}

__global__ void scanA_kernel() {
    __shared__ int sh[SCHUNK];
    int b = blockIdx.x, t = threadIdx.x;
    int i = b * SCHUNK + t;
    int v = (i < N_NODES) ? (g_deg[i] + 1) : 0;
    sh[t] = v; __syncthreads();
    for (int off = 1; off < SCHUNK; off <<= 1) {
        int x = (t >= off) ? sh[t - off] : 0; __syncthreads();
        sh[t] += x; __syncthreads();
    }
    if (i < N_NODES) g_cursor[i] = sh[t];
    if (t == SCHUNK - 1) g_part[b] = sh[t];
}

__global__ void scanB_kernel() {
    __shared__ int sh[512];
    int t = threadIdx.x;
    int v = (t < NSCH) ? g_part[t] : 0;
    sh[t] = v; __syncthreads();
    for (int off = 1; off < 512; off <<= 1) {
        int x = (t >= off) ? sh[t - off] : 0; __syncthreads();
        sh[t] += x; __syncthreads();
    }
    if (t < NSCH) g_part[t] = sh[t] - v;
    if (t == 511) g_rowptr[N_NODES] = sh[511];
}

__global__ void scanC_kernel() {
    int i = blockIdx.x * blockDim.x + threadIdx.x;
    if (i >= N_NODES) return;
    int excl = g_cursor[i] - (g_deg[i] + 1) + g_part[i / SCHUNK];
    g_rowptr[i] = excl;
    g_cursor[i] = excl;
}

__global__ void fill_kernel(const int* __restrict__ ei) {
    int e = blockIdx.x * blockDim.x + threadIdx.x;
    if (e >= N_TOT) return;
    int s, d;
    if (e < N_EDGES) { s = ei[e]; d = ei[N_EDGES + e]; }
    else             { s = d = e - N_EDGES; }
    int p = atomicAdd(&g_cursor[d], 1);
    g_col[p] = s;
}

// ---------------- bf16 split helpers ----------------
__device__ __forceinline__ void split_bf16(float x, __nv_bfloat16& h, __nv_bfloat16& l) {
    h = __float2bfloat16(x);
    l = __float2bfloat16(x - __bfloat162float(h));
}

// ---------------- input conversion ----------------
__global__ void convx_kernel(const float* __restrict__ x) {
    int i = blockIdx.x * blockDim.x + threadIdx.x;
    float4 v = ((const float4*)x)[i];
    __nv_bfloat16 h0,l0,h1,l1,h2,l2,h3,l3;
    split_bf16(v.x,h0,l0); split_bf16(v.y,h1,l1);
    split_bf16(v.z,h2,l2); split_bf16(v.w,h3,l3);
    __nv_bfloat162 a; a.x=h0; a.y=h1;
    __nv_bfloat162 b; b.x=h2; b.y=h3;
    __nv_bfloat162 c; c.x=l0; c.y=l1;
    __nv_bfloat162 d; d.x=l2; d.y=l3;
    ((__nv_bfloat162*)g_hiA)[i*2]   = a;
    ((__nv_bfloat162*)g_hiA)[i*2+1] = b;
    ((__nv_bfloat162*)g_loA)[i*2]   = c;
    ((__nv_bfloat162*)g_loA)[i*2+1] = d;
}

// ---------------- weight prep: fast bias fold (smem coeffs, 2 threads/col) ----------------
__global__ void prep_kernel(const float* __restrict__ bnp, const float* __restrict__ W,
                            const float* __restrict__ extra, int layer) {
    int b = blockIdx.x;
    if (b < 64) {
        int i = b * 256 + threadIdx.x;
        int k = i >> 7, n = i & 127;
        float s = bnp[k] * rsqrtf(bnp[384 + k] + BN_EPS);
        float w = s * W[i];
        __nv_bfloat16 h, l;
        split_bf16(w, h, l);
        g_wthi[layer][n * 128 + k] = h;
        g_wtlo[layer][n * 128 + k] = l;
    } else {
        __shared__ float cs[128];
        __shared__ float part[256];
        int t = threadIdx.x;
        if (t < 128) {
            float s = bnp[t] * rsqrtf(bnp[384 + t] + BN_EPS);
            cs[t] = bnp[128 + t] - s * bnp[256 + t];
        }
        __syncthreads();
        int j = t & 127, half = t >> 7;
        float acc = 0.f;
        int k0 = half * 64;
#pragma unroll 8
        for (int k = k0; k < k0 + 64; k++) acc += cs[k] * W[k * HIDDIM + j];
        part[t] = acc;
        __syncthreads();
        if (t < 128) g_bpv[layer][j] = part[j] + part[j + 128] + (extra ? extra[j] : 0.f);
    }
}

// ---------------- cp.async helpers ----------------
__device__ __forceinline__ void cpa16(void* sdst, const void* gsrc, int srcbytes) {
    uint32_t s = (uint32_t)__cvta_generic_to_shared(sdst);
    asm volatile("cp.async.ca.shared.global [%0], [%1], 16, %2;"
                 :: "r"(s), "l"(gsrc), "r"(srcbytes));
}
__device__ __forceinline__ void cpa_commit() {
    asm volatile("cp.async.commit_group;");
}

__device__ __forceinline__ void mma16816(float c[4], uint32_t a0, uint32_t a1,
                                         uint32_t a2, uint32_t a3,
                                         uint32_t b0, uint32_t b1) {
    asm volatile(
        "mma.sync.aligned.m16n8k16.row.col.f32.bf16.bf16.f32 "
        "{%0,%1,%2,%3}, {%4,%5,%6,%7}, {%8,%9}, {%0,%1,%2,%3};"
        : "+f"(c[0]), "+f"(c[1]), "+f"(c[2]), "+f"(c[3])
        : "r"(a0), "r"(a1), "r"(a2), "r"(a3), "r"(b0), "r"(b1));
}

// ---------------- tensor-core GEMM: k-major 3-term split, cp.async pipeline ----------------
#define SMS   40
#define BUFE  (128 * SMS)
__global__ void __launch_bounds__(256)
mma_gemm_kernel(const __nv_bfloat16* __restrict__ Ahi,
                const __nv_bfloat16* __restrict__ Alo,
                const __nv_bfloat16* __restrict__ Bhg,
                const __nv_bfloat16* __restrict__ Blg,
                const float* __restrict__ bp,
                float* __restrict__ Cout,
                __nv_bfloat16* __restrict__ Ohi,
                __nv_bfloat16* __restrict__ Olo,
                const float* __restrict__ att_s,
                const float* __restrict__ att_d,
                int do_relu) {
    extern __shared__ __nv_bfloat16 dsm[];
    __nv_bfloat16* sAhi = dsm;
    __nv_bfloat16* sAlo = dsm + 2 * BUFE;
    __nv_bfloat16* sBhi = dsm + 4 * BUFE;
    __nv_bfloat16* sBlo = dsm + 6 * BUFE;

    int tid = threadIdx.x;
    int wid = tid >> 5, lane = tid & 31;
    int g = lane >> 2, tc = lane & 3;
    int wr = (wid & 3) * 32, wc = (wid >> 2) * 64;
    int row0 = blockIdx.x * 128;

    float c[2][8][4];
#pragma unroll
    for (int a = 0; a < 2; a++)
#pragma unroll
        for (int b = 0; b < 8; b++)
#pragma unroll
            for (int q = 0; q < 4; q++) c[a][b][q] = 0.f;

    int lr = tid >> 1, half = tid & 1;
    int gr = row0 + lr;
    int vb = (gr < N_NODES) ? 16 : 0;
    size_t abase = (size_t)(gr < N_NODES ? gr : 0) * 128 + half * 16;
    int bbase = lr * 128 + half * 16;
    int soff = lr * SMS + half * 16;

    auto issue = [&](int k, int buf) {
        int k0 = k * 32;
        cpa16(sAhi + buf * BUFE + soff,     Ahi + abase + k0,     vb);
        cpa16(sAhi + buf * BUFE + soff + 8, Ahi + abase + k0 + 8, vb);
        cpa16(sAlo + buf * BUFE + soff,     Alo + abase + k0,     vb);
        cpa16(sAlo + buf * BUFE + soff + 8, Alo + abase + k0 + 8, vb);
        cpa16(sBhi + buf * BUFE + soff,     Bhg + bbase + k0,     16);
        cpa16(sBhi + buf * BUFE + soff + 8, Bhg + bbase + k0 + 8, 16);
        cpa16(sBlo + buf * BUFE + soff,     Blg + bbase + k0,     16);
        cpa16(sBlo + buf * BUFE + soff + 8, Blg + bbase + k0 + 8, 16);
        cpa_commit();
    };

    issue(0, 0);
    for (int k = 0; k < 4; k++) {
        int cur = k & 1;
        if (k < 3) {
            issue(k + 1, cur ^ 1);
            asm volatile("cp.async.wait_group 1;");
        } else {
            asm volatile("cp.async.wait_group 0;");
        }
        __syncthreads();

        const __nv_bfloat16* Ah = sAhi + cur * BUFE;
        const __nv_bfloat16* Al = sAlo + cur * BUFE;
        const __nv_bfloat16* Bh = sBhi + cur * BUFE;
        const __nv_bfloat16* Bl = sBlo + cur * BUFE;
#pragma unroll
        for (int s = 0; s < 2; s++) {
            int kb = s * 16;
            uint32_t ah[2][4];
#pragma unroll
            for (int mf = 0; mf < 2; mf++) {
                int m = wr + mf * 16 + g;
                ah[mf][0] = *(const uint32_t*)(Ah + m * SMS + kb + tc * 2);
                ah[mf][1] = *(const uint32_t*)(Ah + (m + 8) * SMS + kb + tc * 2);
                ah[mf][2] = *(const uint32_t*)(Ah + m * SMS + kb + tc * 2 + 8);
                ah[mf][3] = *(const uint32_t*)(Ah + (m + 8) * SMS + kb + tc * 2 + 8);
            }
            uint32_t bh[8][2];
#pragma unroll
            for (int nf = 0; nf < 8; nf++) {
                int n = wc + nf * 8 + g;
                bh[nf][0] = *(const uint32_t*)(Bh + n * SMS + kb + tc * 2);
                bh[nf][1] = *(const uint32_t*)(Bh + n * SMS + kb + tc * 2 + 8);
            }
#pragma unroll
            for (int mf = 0; mf < 2; mf++)
#pragma unroll
                for (int nf = 0; nf < 8; nf++)
                    mma16816(c[mf][nf], ah[mf][0], ah[mf][1], ah[mf][2], ah[mf][3],
                             bh[nf][0], bh[nf][1]);
            {
                uint32_t bl[8][2];
#pragma unroll
                for (int nf = 0; nf < 8; nf++) {
                    int n = wc + nf * 8 + g;
                    bl[nf][0] = *(const uint32_t*)(Bl + n * SMS + kb + tc * 2);
                    bl[nf][1] = *(const uint32_t*)(Bl + n * SMS + kb + tc * 2 + 8);
                }
#pragma unroll
                for (int mf = 0; mf < 2; mf++)
#pragma unroll
                    for (int nf = 0; nf < 8; nf++)
                        mma16816(c[mf][nf], ah[mf][0], ah[mf][1], ah[mf][2], ah[mf][3],
                                 bl[nf][0], bl[nf][1]);
            }
            uint32_t al[2][4];
#pragma unroll
            for (int mf = 0; mf < 2; mf++) {
                int m = wr + mf * 16 + g;
                al[mf][0] = *(const uint32_t*)(Al + m * SMS + kb + tc * 2);
                al[mf][1] = *(const uint32_t*)(Al + (m + 8) * SMS + kb + tc * 2);
                al[mf][2] = *(const uint32_t*)(Al + m * SMS + kb + tc * 2 + 8);
                al[mf][3] = *(const uint32_t*)(Al + (m + 8) * SMS + kb + tc * 2 + 8);
            }
#pragma unroll
            for (int mf = 0; mf < 2; mf++)
#pragma unroll
                for (int nf = 0; nf < 8; nf++)
                    mma16816(c[mf][nf], al[mf][0], al[mf][1], al[mf][2], al[mf][3],
                             bh[nf][0], bh[nf][1]);
        }
        __syncthreads();
    }

    // epilogue
#pragma unroll
    for (int mf = 0; mf < 2; mf++) {
        int r0 = row0 + wr + mf * 16 + g;
        int r1 = r0 + 8;
        float ps0[4] = {0,0,0,0}, pd0[4] = {0,0,0,0};
        float ps1[4] = {0,0,0,0}, pd1[4] = {0,0,0,0};
#pragma unroll
        for (int nf = 0; nf < 8; nf++) {
            int cc = wc + nf * 8 + tc * 2;
            float b0 = bp[cc], b1 = bp[cc + 1];
            float v00 = c[mf][nf][0] + b0, v01 = c[mf][nf][1] + b1;
            float v10 = c[mf][nf][2] + b0, v11 = c[mf][nf][3] + b1;
            if (do_relu) {
                v00 = fmaxf(v00, 0.f); v01 = fmaxf(v01, 0.f);
                v10 = fmaxf(v10, 0.f); v11 = fmaxf(v11, 0.f);
            }
            if (att_s) {
                int hl = nf >> 1;
                float as0 = att_s[cc], as1 = att_s[cc + 1];
                float ad0 = att_d[cc], ad1 = att_d[cc + 1];
                ps0[hl] += v00 * as0 + v01 * as1;
                pd0[hl] += v00 * ad0 + v01 * ad1;
                ps1[hl] += v10 * as0 + v11 * as1;
                pd1[hl] += v10 * ad0 + v11 * ad1;
            }
            if (Cout) {
                if (r0 < N_NODES) { float2 t = {v00, v01}; *(float2*)(Cout + (size_t)r0 * 128 + cc) = t; }
                if (r1 < N_NODES) { float2 t = {v10, v11}; *(float2*)(Cout + (size_t)r1 * 128 + cc) = t; }
            }
            if (Ohi) {
                __nv_bfloat16 h0, l0, h1, l1;
                if (r0 < N_NODES) {
                    split_bf16(v00, h0, l0); split_bf16(v01, h1, l1);
                    __nv_bfloat162 th; th.x = h0; th.y = h1;
                    __nv_bfloat162 tl; tl.x = l0; tl.y = l1;
                    *(__nv_bfloat162*)(Ohi + (size_t)r0 * 128 + cc) = th;
                    *(__nv_bfloat162*)(Olo + (size_t)r0 * 128 + cc) = tl;
                }
                if (r1 < N_NODES) {
                    split_bf16(v10, h0, l0); split_bf16(v11, h1, l1);
                    __nv_bfloat162 th; th.x = h0; th.y = h1;
                    __nv_bfloat162 tl; tl.x = l0; tl.y = l1;
                    *(__nv_bfloat162*)(Ohi + (size_t)r1 * 128 + cc) = th;
                    *(__nv_bfloat162*)(Olo + (size_t)r1 * 128 + cc) = tl;
                }
            }
        }
        if (att_s) {
#pragma unroll
            for (int h = 0; h < 4; h++) {
                ps0[h] += __shfl_xor_sync(0xffffffffu, ps0[h], 1);
                ps0[h] += __shfl_xor_sync(0xffffffffu, ps0[h], 2);
                pd0[h] += __shfl_xor_sync(0xffffffffu, pd0[h], 1);
                pd0[h] += __shfl_xor_sync(0xffffffffu, pd0[h], 2);
                ps1[h] += __shfl_xor_sync(0xffffffffu, ps1[h], 1);
                ps1[h] += __shfl_xor_sync(0xffffffffu, ps1[h], 2);
                pd1[h] += __shfl_xor_sync(0xffffffffu, pd1[h], 1);
                pd1[h] += __shfl_xor_sync(0xffffffffu, pd1[h], 2);
            }
            if (tc == 0) {
                int hb = wc >> 4;
                if (r0 < N_NODES) {
#pragma unroll
                    for (int h = 0; h < 4; h++) {
                        g_as[r0 * 8 + hb + h] = ps0[h];
                        g_ad[r0 * 8 + hb + h] = pd0[h];
                    }
                }
                if (r1 < N_NODES) {
#pragma unroll
                    for (int h = 0; h < 4; h++) {
                        g_as[r1 * 8 + hb + h] = ps1[h];
                        g_ad[r1 * 8 + hb + h] = pd1[h];
                    }
                }
            }
        }
    }
}

// ---------------- GAT gather: single-pass online softmax (R6 form) ----------------
__global__ void gather_kernel(const float* __restrict__ bias,
                              float* __restrict__ outF,
                              __nv_bfloat16* __restrict__ Ohi,
                              __nv_bfloat16* __restrict__ Olo) {
    int node = (blockIdx.x * blockDim.x + threadIdx.x) >> 5;
    if (node >= N_NODES) return;
    int lane = threadIdx.x & 31;
    int head = lane >> 2;
    int beg = g_rowptr[node];
    int end = g_rowptr[node + 1];

    float adh = g_ad[node * 8 + head];
    float m = -1e30f, s = 0.f;
    float c0 = 0.f, c1 = 0.f, c2 = 0.f, c3 = 0.f;

    for (int e = beg; e < end; e++) {
        int src = g_col[e];
        float l = __ldg(g_as + src * 8 + head) + adh;
        l = l > 0.f ? l : SLOPE * l;
        float4 v = ((const float4*)(g_h2 + (size_t)src * 128))[lane];
        float mn = fmaxf(m, l);
        float sc = __expf(m - mn);
        float w  = __expf(l - mn);
        s = s * sc + w;
        c0 = c0 * sc + w * v.x;
        c1 = c1 * sc + w * v.y;
        c2 = c2 * sc + w * v.z;
        c3 = c3 * sc + w * v.w;
        m = mn;
    }
    float inv = 1.f / (s + 1e-16f);
    float4 bb = ((const float4*)bias)[lane];
    float4 o;
    o.x = fmaxf(c0 * inv + bb.x, 0.f);
    o.y = fmaxf(c1 * inv + bb.y, 0.f);
    o.z = fmaxf(c2 * inv + bb.z, 0.f);
    o.w = fmaxf(c3 * inv + bb.w, 0.f);

    if (outF) ((float4*)(outF + (size_t)node * 128))[lane] = o;
    if (Ohi) {
        __nv_bfloat16 h0,l0,h1,l1,h2b,l2,h3,l3;
        split_bf16(o.x,h0,l0); split_bf16(o.y,h1,l1);
        split_bf16(o.z,h2b,l2); split_bf16(o.w,h3,l3);
        __nv_bfloat162 ta; ta.x=h0;  ta.y=h1;
        __nv_bfloat162 tb; tb.x=h2b; tb.y=h3;
        __nv_bfloat162 tcq; tcq.x=l0; tcq.y=l1;
        __nv_bfloat162 td; td.x=l2;  td.y=l3;
        ((__nv_bfloat162*)(Ohi + (size_t)node * 128))[lane*2]   = ta;
        ((__nv_bfloat162*)(Ohi + (size_t)node * 128))[lane*2+1] = tb;
        ((__nv_bfloat162*)(Olo + (size_t)node * 128))[lane*2]   = tcq;
        ((__nv_bfloat162*)(Olo + (size_t)node * 128))[lane*2+1] = td;
    }
}

// ---------------- pooling ----------------
__global__ void pool_kernel(const int* __restrict__ batch) {
    int b = blockIdx.x, c = threadIdx.x;
    int r0 = b * SCHUNK, r1 = min(r0 + SCHUNK, N_NODES);
    float acc = 0.f;
    int cur = batch[r0];
    for (int r = r0; r < r1; r++) {
        int gb = batch[r];
        if (gb != cur) { atomicAdd(&g_pool[cur * 128 + c], acc); acc = 0.f; cur = gb; }
        acc += g_h[(size_t)r * 128 + c];
    }
    atomicAdd(&g_pool[cur * 128 + c], acc);
}

// ---------------- fused FC + classifier + log_softmax ----------------
__global__ void fccls_kernel(const float* __restrict__ bnfc, const float* __restrict__ fcW,
                             const float* __restrict__ fcb,
                             const float* __restrict__ bnh, const float* __restrict__ Wc,
                             const float* __restrict__ bc, float* __restrict__ out) {
    __shared__ float sh[128];
    __shared__ float sh2[128];
    __shared__ float lg[NCLASS];
    __shared__ float s_mx, s_ls;
    int g = blockIdx.x, t = threadIdx.x;
    float x = g_pool[g * 128 + t];
    float s = bnfc[t] * rsqrtf(bnfc[384 + t] + BN_EPS);
    sh[t] = s * (x - bnfc[256 + t]) + bnfc[128 + t];
    __syncthreads();
    float acc = fcb[t];
    for (int k = 0; k < 128; k++) acc += sh[k] * fcW[k * 128 + t];
    float fo = fmaxf(acc, 0.f);
    float s2 = bnh[t] * rsqrtf(bnh[384 + t] + BN_EPS);
    sh2[t] = s2 * (fo - bnh[256 + t]) + bnh[128 + t];
    __syncthreads();
    if (t < NCLASS) {
        float a2 = bc[t];
        for (int k = 0; k < 128; k++) a2 += sh2[k] * Wc[k * NCLASS + t];
        lg[t] = a2;
    }
    __syncthreads();
    if (t == 0) {
        float mx = lg[0];
        for (int j = 1; j < NCLASS; j++) mx = fmaxf(mx, lg[j]);
        float se = 0.f;
        for (int j = 0; j < NCLASS; j++) se += expf(lg[j] - mx);
        s_mx = mx; s_ls = logf(se);
    }
    __syncthreads();
    if (t < NCLASS) out[g * NCLASS + t] = lg[t] - s_mx - s_ls;
}

// ---------------- launch ----------------
extern "C" void kernel_launch(void* const* d_in, const int* in_sizes, int n_in,
                              void* d_out, int out_size) {
    const float* x        = (const float*)d_in[0];
    const int*   ei       = (const int*)d_in[1];
    const int*   batch    = (const int*)d_in[2];
    const float* bn_feat  = (const float*)d_in[3];
    const float* w_feat   = (const float*)d_in[4];
    const float* b_feat   = (const float*)d_in[5];
    const float* bns_conv = (const float*)d_in[6];
    const float* gat_w    = (const float*)d_in[7];
    const float* att_s    = (const float*)d_in[8];
    const float* att_d    = (const float*)d_in[9];
    const float* gat_b    = (const float*)d_in[10];
    const float* bns_fc   = (const float*)d_in[11];
    const float* fc_w     = (const float*)d_in[12];
    const float* fc_b     = (const float*)d_in[13];
    const float* bn_hid   = (const float*)d_in[14];
    const float* w_cls    = (const float*)d_in[15];
    const float* b_cls    = (const float*)d_in[16];
    float* out = (float*)d_out;

    float *p_h = nullptr, *p_h2 = nullptr, *p_pool = nullptr, *p_bp = nullptr;
    int* p_deg = nullptr;
    __nv_bfloat16 *p_hiA = nullptr, *p_loA = nullptr, *p_hiB = nullptr, *p_loB = nullptr;
    __nv_bfloat16 *p_wthi = nullptr, *p_wtlo = nullptr;
    cudaGetSymbolAddress((void**)&p_h,    g_h);
    cudaGetSymbolAddress((void**)&p_h2,   g_h2);
    cudaGetSymbolAddress((void**)&p_pool, g_pool);
    cudaGetSymbolAddress((void**)&p_deg,  g_deg);
    cudaGetSymbolAddress((void**)&p_hiA,  g_hiA);
    cudaGetSymbolAddress((void**)&p_loA,  g_loA);
    cudaGetSymbolAddress((void**)&p_hiB,  g_hiB);
    cudaGetSymbolAddress((void**)&p_loB,  g_loB);
    cudaGetSymbolAddress((void**)&p_wthi, g_wthi);
    cudaGetSymbolAddress((void**)&p_wtlo, g_wtlo);
    cudaGetSymbolAddress((void**)&p_bp,   g_bpv);

    static cudaStream_t s2 = nullptr;
    static cudaEvent_t e0 = nullptr, e1 = nullptr, e2 = nullptr;
    if (!s2) {
        cudaStreamCreateWithFlags(&s2, cudaStreamNonBlocking);
        cudaEventCreateWithFlags(&e0, cudaEventDisableTiming);
        cudaEventCreateWithFlags(&e1, cudaEventDisableTiming);
        cudaEventCreateWithFlags(&e2, cudaEventDisableTiming);
        cudaFuncSetAttribute(mma_gemm_kernel,
                             cudaFuncAttributeMaxDynamicSharedMemorySize, 8 * BUFE * 2);
    }

    const int GEMM_GRID = (N_NODES + 127) / 128;
    const int GEMM_SMEM = 8 * BUFE * 2;

    cudaEventRecord(e0, 0);
    cudaStreamWaitEvent(s2, e0, 0);

    // legacy: prep0 + convx + gemms (critical path)
    prep_kernel<<<65, 256>>>(bn_feat, w_feat, b_feat, 0);                   // 1
    convx_kernel<<<(N_NODES * HIDDIM / 4 + 255) / 256, 256>>>(x);           // 2

    // s2: conv preps (fast) then CSR build then pool memset
    cudaMemsetAsync(p_deg, 0, N_NODES * sizeof(int), s2);
    for (int i = 0; i < 3; i++)
        prep_kernel<<<65, 256, 0, s2>>>(bns_conv + i * 512, gat_w + i * 16384,
                                        (const float*)nullptr, i + 1);
    cudaEventRecord(e2, s2);
    count_kernel<<<(N_EDGES + 255) / 256, 256, 0, s2>>>(ei);
    scanA_kernel<<<NSCH, SCHUNK, 0, s2>>>();
    scanB_kernel<<<1, 512, 0, s2>>>();
    scanC_kernel<<<(N_NODES + 255) / 256, 256, 0, s2>>>();
    fill_kernel <<<(N_TOT + 255) / 256, 256, 0, s2>>>(ei);
    cudaMemsetAsync(p_pool, 0, NGROUP * HIDDIM * sizeof(float), s2);
    cudaEventRecord(e1, s2);

    // feature GEMM (layer 0)
    mma_gemm_kernel<<<GEMM_GRID, 256, GEMM_SMEM>>>(p_hiA, p_loA,
                                                   p_wthi, p_wtlo, p_bp,
                                                   (float*)nullptr, p_hiB, p_loB,
                                                   (const float*)nullptr,
                                                   (const float*)nullptr, 1);
    cudaStreamWaitEvent(0, e2, 0);   // conv weights ready

    __nv_bfloat16* inhi[3] = {p_hiB, p_hiA, p_hiB};
    __nv_bfloat16* inlo[3] = {p_loB, p_loA, p_loB};
    __nv_bfloat16* othi[3] = {p_hiA, p_hiB, (__nv_bfloat16*)nullptr};
    __nv_bfloat16* otlo[3] = {p_loA, p_loB, (__nv_bfloat16*)nullptr};

    // conv0 GEMM
    mma_gemm_kernel<<<GEMM_GRID, 256, GEMM_SMEM>>>(inhi[0], inlo[0],
                                                   p_wthi + 16384, p_wtlo + 16384, p_bp + 128,
                                                   p_h2,
                                                   (__nv_bfloat16*)nullptr, (__nv_bfloat16*)nullptr,
                                                   att_s, att_d, 0);
    cudaStreamWaitEvent(0, e1, 0);   // CSR + pool-memset ready

    for (int i = 0; i < 3; i++) {
        if (i > 0) {
            mma_gemm_kernel<<<GEMM_GRID, 256, GEMM_SMEM>>>(inhi[i], inlo[i],
                                                           p_wthi + (i + 1) * 16384,
                                                           p_wtlo + (i + 1) * 16384,
                                                           p_bp + (i + 1) * 128,
                                                           p_h2,
                                                           (__nv_bfloat16*)nullptr, (__nv_bfloat16*)nullptr,
                                                           att_s + i * 128, att_d + i * 128, 0);
        }
        gather_kernel<<<N_NODES / 8, 256>>>(gat_b + i * 128,
                                            (i == 2) ? p_h : (float*)nullptr,
                                            othi[i], otlo[i]);
    }

    pool_kernel <<<NSCH, 128>>>(batch);
    fccls_kernel<<<NGROUP, 128>>>(bns_fc, fc_w, fc_b, bn_hid, w_cls, b_cls, out);
}

// round 9
// speedup vs baseline: 1.3243x; 1.0280x over previous
#include <cuda_runtime.h>
#include <cuda_bf16.h>
#include <stdint.h>
#include <math.h>

#define N_NODES 50000
#define N_EDGES 800000
#define N_TOT   (N_EDGES + N_NODES)
#define HIDDIM  128
#define NHEADS  8
#define NGROUP  64
#define NCLASS  10
#define BN_EPS  1e-5f
#define SLOPE   0.2f
#define SCHUNK  128
#define NSCH    ((N_NODES + SCHUNK - 1) / SCHUNK)

// ---------------- device scratch ----------------
static __device__ float g_h   [N_NODES * HIDDIM];
static __device__ float g_h2  [N_NODES * HIDDIM];
static __device__ __align__(16) __nv_bfloat16 g_hiA[N_NODES * HIDDIM];
static __device__ __align__(16) __nv_bfloat16 g_loA[N_NODES * HIDDIM];
static __device__ __align__(16) __nv_bfloat16 g_hiB[N_NODES * HIDDIM];
static __device__ __align__(16) __nv_bfloat16 g_loB[N_NODES * HIDDIM];
static __device__ __align__(16) __nv_bfloat16 g_wthi[4][HIDDIM * HIDDIM];
static __device__ __align__(16) __nv_bfloat16 g_wtlo[4][HIDDIM * HIDDIM];
static __device__ float g_bpv [4][HIDDIM];
static __device__ float g_as  [N_NODES * NHEADS];
static __device__ float g_ad  [N_NODES * NHEADS];
static __device__ int   g_rowptr[N_NODES + 1];
static __device__ int   g_cursor[N_NODES];
static __device__ int   g_deg   [N_NODES];
static __device__ int   g_part  [512];
static __device__ int   g_col   [N_TOT];
static __device__ float g_pool [NGROUP * HIDDIM];

// ---------------- CSR build ----------------
__global__ void count_kernel(const int* __restrict__ ei) {
    int e = blockIdx.x * blockDim.x + threadIdx.x;
    if (e < N_EDGES) atomicAdd(&g_deg[ei[N_EDGES + e]], 1);
}

__global__ void scanA_kernel() {
    __shared__ int sh[SCHUNK];
    int b = blockIdx.x, t = threadIdx.x;
    int i = b * SCHUNK + t;
    int v = (i < N_NODES) ? (g_deg[i] + 1) : 0;
    sh[t] = v; __syncthreads();
    for (int off = 1; off < SCHUNK; off <<= 1) {
        int x = (t >= off) ? sh[t - off] : 0; __syncthreads();
        sh[t] += x; __syncthreads();
    }
    if (i < N_NODES) g_cursor[i] = sh[t];
    if (t == SCHUNK - 1) g_part[b] = sh[t];
}

__global__ void scanB_kernel() {
    __shared__ int sh[512];
    int t = threadIdx.x;
    int v = (t < NSCH) ? g_part[t] : 0;
    sh[t] = v; __syncthreads();
    for (int off = 1; off < 512; off <<= 1) {
        int x = (t >= off) ? sh[t - off] : 0; __syncthreads();
        sh[t] += x; __syncthreads();
    }
    if (t < NSCH) g_part[t] = sh[t] - v;
    if (t == 511) g_rowptr[N_NODES] = sh[511];
}

__global__ void scanC_kernel() {
    int i = blockIdx.x * blockDim.x + threadIdx.x;
    if (i >= N_NODES) return;
    int excl = g_cursor[i] - (g_deg[i] + 1) + g_part[i / SCHUNK];
    g_rowptr[i] = excl;
    g_cursor[i] = excl;
}

__global__ void fill_kernel(const int* __restrict__ ei) {
    int e = blockIdx.x * blockDim.x + threadIdx.x;
    if (e >= N_TOT) return;
    int s, d;
    if (e < N_EDGES) { s = ei[e]; d = ei[N_EDGES + e]; }
    else             { s = d = e - N_EDGES; }
    int p = atomicAdd(&g_cursor[d], 1);
    g_col[p] = s;
}

// ---------------- bf16 split helpers ----------------
__device__ __forceinline__ void split_bf16(float x, __nv_bfloat16& h, __nv_bfloat16& l) {
    h = __float2bfloat16(x);
    l = __float2bfloat16(x - __bfloat162float(h));
}

// ---------------- input conversion ----------------
__global__ void convx_kernel(const float* __restrict__ x) {
    int i = blockIdx.x * blockDim.x + threadIdx.x;
    float4 v = ((const float4*)x)[i];
    __nv_bfloat16 h0,l0,h1,l1,h2,l2,h3,l3;
    split_bf16(v.x,h0,l0); split_bf16(v.y,h1,l1);
    split_bf16(v.z,h2,l2); split_bf16(v.w,h3,l3);
    __nv_bfloat162 a; a.x=h0; a.y=h1;
    __nv_bfloat162 b; b.x=h2; b.y=h3;
    __nv_bfloat162 c; c.x=l0; c.y=l1;
    __nv_bfloat162 d; d.x=l2; d.y=l3;
    ((__nv_bfloat162*)g_hiA)[i*2]   = a;
    ((__nv_bfloat162*)g_hiA)[i*2+1] = b;
    ((__nv_bfloat162*)g_loA)[i*2]   = c;
    ((__nv_bfloat162*)g_loA)[i*2+1] = d;
}

// ---------------- weight prep: fast bias fold ----------------
__global__ void prep_kernel(const float* __restrict__ bnp, const float* __restrict__ W,
                            const float* __restrict__ extra, int layer) {
    int b = blockIdx.x;
    if (b < 64) {
        int i = b * 256 + threadIdx.x;
        int k = i >> 7, n = i & 127;
        float s = bnp[k] * rsqrtf(bnp[384 + k] + BN_EPS);
        float w = s * W[i];
        __nv_bfloat16 h, l;
        split_bf16(w, h, l);
        g_wthi[layer][n * 128 + k] = h;
        g_wtlo[layer][n * 128 + k] = l;
    } else {
        __shared__ float cs[128];
        __shared__ float part[256];
        int t = threadIdx.x;
        if (t < 128) {
            float s = bnp[t] * rsqrtf(bnp[384 + t] + BN_EPS);
            cs[t] = bnp[128 + t] - s * bnp[256 + t];
        }
        __syncthreads();
        int j = t & 127, half = t >> 7;
        float acc = 0.f;
        int k0 = half * 64;
#pragma unroll 8
        for (int k = k0; k < k0 + 64; k++) acc += cs[k] * W[k * HIDDIM + j];
        part[t] = acc;
        __syncthreads();
        if (t < 128) g_bpv[layer][j] = part[j] + part[j + 128] + (extra ? extra[j] : 0.f);
    }
}

// ---------------- cp.async helpers ----------------
__device__ __forceinline__ void cpa16(void* sdst, const void* gsrc, int srcbytes) {
    uint32_t s = (uint32_t)__cvta_generic_to_shared(sdst);
    asm volatile("cp.async.ca.shared.global [%0], [%1], 16, %2;"
                 :: "r"(s), "l"(gsrc), "r"(srcbytes));
}
__device__ __forceinline__ void cpa_commit() {
    asm volatile("cp.async.commit_group;");
}

__device__ __forceinline__ void mma16816(float c[4], uint32_t a0, uint32_t a1,
                                         uint32_t a2, uint32_t a3,
                                         uint32_t b0, uint32_t b1) {
    asm volatile(
        "mma.sync.aligned.m16n8k16.row.col.f32.bf16.bf16.f32 "
        "{%0,%1,%2,%3}, {%4,%5,%6,%7}, {%8,%9}, {%0,%1,%2,%3};"
        : "+f"(c[0]), "+f"(c[1]), "+f"(c[2]), "+f"(c[3])
        : "r"(a0), "r"(a1), "r"(a2), "r"(a3), "r"(b0), "r"(b1));
}

// ---------------- tensor-core GEMM: k-major 3-term split, cp.async pipeline ----------------
#define SMS   40
#define BUFE  (128 * SMS)
__global__ void __launch_bounds__(256)
mma_gemm_kernel(const __nv_bfloat16* __restrict__ Ahi,
                const __nv_bfloat16* __restrict__ Alo,
                const __nv_bfloat16* __restrict__ Bhg,
                const __nv_bfloat16* __restrict__ Blg,
                const float* __restrict__ bp,
                float* __restrict__ Cout,
                __nv_bfloat16* __restrict__ Ohi,
                __nv_bfloat16* __restrict__ Olo,
                const float* __restrict__ att_s,
                const float* __restrict__ att_d,
                int do_relu) {
    extern __shared__ __nv_bfloat16 dsm[];
    __nv_bfloat16* sAhi = dsm;
    __nv_bfloat16* sAlo = dsm + 2 * BUFE;
    __nv_bfloat16* sBhi = dsm + 4 * BUFE;
    __nv_bfloat16* sBlo = dsm + 6 * BUFE;

    int tid = threadIdx.x;
    int wid = tid >> 5, lane = tid & 31;
    int g = lane >> 2, tc = lane & 3;
    int wr = (wid & 3) * 32, wc = (wid >> 2) * 64;
    int row0 = blockIdx.x * 128;

    float c[2][8][4];
#pragma unroll
    for (int a = 0; a < 2; a++)
#pragma unroll
        for (int b = 0; b < 8; b++)
#pragma unroll
            for (int q = 0; q < 4; q++) c[a][b][q] = 0.f;

    int lr = tid >> 1, half = tid & 1;
    int gr = row0 + lr;
    int vb = (gr < N_NODES) ? 16 : 0;
    size_t abase = (size_t)(gr < N_NODES ? gr : 0) * 128 + half * 16;
    int bbase = lr * 128 + half * 16;
    int soff = lr * SMS + half * 16;

    auto issue = [&](int k, int buf) {
        int k0 = k * 32;
        cpa16(sAhi + buf * BUFE + soff,     Ahi + abase + k0,     vb);
        cpa16(sAhi + buf * BUFE + soff + 8, Ahi + abase + k0 + 8, vb);
        cpa16(sAlo + buf * BUFE + soff,     Alo + abase + k0,     vb);
        cpa16(sAlo + buf * BUFE + soff + 8, Alo + abase + k0 + 8, vb);
        cpa16(sBhi + buf * BUFE + soff,     Bhg + bbase + k0,     16);
        cpa16(sBhi + buf * BUFE + soff + 8, Bhg + bbase + k0 + 8, 16);
        cpa16(sBlo + buf * BUFE + soff,     Blg + bbase + k0,     16);
        cpa16(sBlo + buf * BUFE + soff + 8, Blg + bbase + k0 + 8, 16);
        cpa_commit();
    };

    issue(0, 0);
    for (int k = 0; k < 4; k++) {
        int cur = k & 1;
        if (k < 3) {
            issue(k + 1, cur ^ 1);
            asm volatile("cp.async.wait_group 1;");
        } else {
            asm volatile("cp.async.wait_group 0;");
        }
        __syncthreads();

        const __nv_bfloat16* Ah = sAhi + cur * BUFE;
        const __nv_bfloat16* Al = sAlo + cur * BUFE;
        const __nv_bfloat16* Bh = sBhi + cur * BUFE;
        const __nv_bfloat16* Bl = sBlo + cur * BUFE;
#pragma unroll
        for (int s = 0; s < 2; s++) {
            int kb = s * 16;
            uint32_t ah[2][4];
#pragma unroll
            for (int mf = 0; mf < 2; mf++) {
                int m = wr + mf * 16 + g;
                ah[mf][0] = *(const uint32_t*)(Ah + m * SMS + kb + tc * 2);
                ah[mf][1] = *(const uint32_t*)(Ah + (m + 8) * SMS + kb + tc * 2);
                ah[mf][2] = *(const uint32_t*)(Ah + m * SMS + kb + tc * 2 + 8);
                ah[mf][3] = *(const uint32_t*)(Ah + (m + 8) * SMS + kb + tc * 2 + 8);
            }
            uint32_t bh[8][2];
#pragma unroll
            for (int nf = 0; nf < 8; nf++) {
                int n = wc + nf * 8 + g;
                bh[nf][0] = *(const uint32_t*)(Bh + n * SMS + kb + tc * 2);
                bh[nf][1] = *(const uint32_t*)(Bh + n * SMS + kb + tc * 2 + 8);
            }
#pragma unroll
            for (int mf = 0; mf < 2; mf++)
#pragma unroll
                for (int nf = 0; nf < 8; nf++)
                    mma16816(c[mf][nf], ah[mf][0], ah[mf][1], ah[mf][2], ah[mf][3],
                             bh[nf][0], bh[nf][1]);
            {
                uint32_t bl[8][2];
#pragma unroll
                for (int nf = 0; nf < 8; nf++) {
                    int n = wc + nf * 8 + g;
                    bl[nf][0] = *(const uint32_t*)(Bl + n * SMS + kb + tc * 2);
                    bl[nf][1] = *(const uint32_t*)(Bl + n * SMS + kb + tc * 2 + 8);
                }
#pragma unroll
                for (int mf = 0; mf < 2; mf++)
#pragma unroll
                    for (int nf = 0; nf < 8; nf++)
                        mma16816(c[mf][nf], ah[mf][0], ah[mf][1], ah[mf][2], ah[mf][3],
                                 bl[nf][0], bl[nf][1]);
            }
            uint32_t al[2][4];
#pragma unroll
            for (int mf = 0; mf < 2; mf++) {
                int m = wr + mf * 16 + g;
                al[mf][0] = *(const uint32_t*)(Al + m * SMS + kb + tc * 2);
                al[mf][1] = *(const uint32_t*)(Al + (m + 8) * SMS + kb + tc * 2);
                al[mf][2] = *(const uint32_t*)(Al + m * SMS + kb + tc * 2 + 8);
                al[mf][3] = *(const uint32_t*)(Al + (m + 8) * SMS + kb + tc * 2 + 8);
            }
#pragma unroll
            for (int mf = 0; mf < 2; mf++)
#pragma unroll
                for (int nf = 0; nf < 8; nf++)
                    mma16816(c[mf][nf], al[mf][0], al[mf][1], al[mf][2], al[mf][3],
                             bh[nf][0], bh[nf][1]);
        }
        __syncthreads();
    }

    // epilogue
#pragma unroll
    for (int mf = 0; mf < 2; mf++) {
        int r0 = row0 + wr + mf * 16 + g;
        int r1 = r0 + 8;
        float ps0[4] = {0,0,0,0}, pd0[4] = {0,0,0,0};
        float ps1[4] = {0,0,0,0}, pd1[4] = {0,0,0,0};
#pragma unroll
        for (int nf = 0; nf < 8; nf++) {
            int cc = wc + nf * 8 + tc * 2;
            float b0 = bp[cc], b1 = bp[cc + 1];
            float v00 = c[mf][nf][0] + b0, v01 = c[mf][nf][1] + b1;
            float v10 = c[mf][nf][2] + b0, v11 = c[mf][nf][3] + b1;
            if (do_relu) {
                v00 = fmaxf(v00, 0.f); v01 = fmaxf(v01, 0.f);
                v10 = fmaxf(v10, 0.f); v11 = fmaxf(v11, 0.f);
            }
            if (att_s) {
                int hl = nf >> 1;
                float as0 = att_s[cc], as1 = att_s[cc + 1];
                float ad0 = att_d[cc], ad1 = att_d[cc + 1];
                ps0[hl] += v00 * as0 + v01 * as1;
                pd0[hl] += v00 * ad0 + v01 * ad1;
                ps1[hl] += v10 * as0 + v11 * as1;
                pd1[hl] += v10 * ad0 + v11 * ad1;
            }
            if (Cout) {
                if (r0 < N_NODES) { float2 t = {v00, v01}; *(float2*)(Cout + (size_t)r0 * 128 + cc) = t; }
                if (r1 < N_NODES) { float2 t = {v10, v11}; *(float2*)(Cout + (size_t)r1 * 128 + cc) = t; }
            }
            if (Ohi) {
                __nv_bfloat16 h0, l0, h1, l1;
                if (r0 < N_NODES) {
                    split_bf16(v00, h0, l0); split_bf16(v01, h1, l1);
                    __nv_bfloat162 th; th.x = h0; th.y = h1;
                    __nv_bfloat162 tl; tl.x = l0; tl.y = l1;
                    *(__nv_bfloat162*)(Ohi + (size_t)r0 * 128 + cc) = th;
                    *(__nv_bfloat162*)(Olo + (size_t)r0 * 128 + cc) = tl;
                }
                if (r1 < N_NODES) {
                    split_bf16(v10, h0, l0); split_bf16(v11, h1, l1);
                    __nv_bfloat162 th; th.x = h0; th.y = h1;
                    __nv_bfloat162 tl; tl.x = l0; tl.y = l1;
                    *(__nv_bfloat162*)(Ohi + (size_t)r1 * 128 + cc) = th;
                    *(__nv_bfloat162*)(Olo + (size_t)r1 * 128 + cc) = tl;
                }
            }
        }
        if (att_s) {
#pragma unroll
            for (int h = 0; h < 4; h++) {
                ps0[h] += __shfl_xor_sync(0xffffffffu, ps0[h], 1);
                ps0[h] += __shfl_xor_sync(0xffffffffu, ps0[h], 2);
                pd0[h] += __shfl_xor_sync(0xffffffffu, pd0[h], 1);
                pd0[h] += __shfl_xor_sync(0xffffffffu, pd0[h], 2);
                ps1[h] += __shfl_xor_sync(0xffffffffu, ps1[h], 1);
                ps1[h] += __shfl_xor_sync(0xffffffffu, ps1[h], 2);
                pd1[h] += __shfl_xor_sync(0xffffffffu, pd1[h], 1);
                pd1[h] += __shfl_xor_sync(0xffffffffu, pd1[h], 2);
            }
            if (tc == 0) {
                int hb = wc >> 4;
                if (r0 < N_NODES) {
#pragma unroll
                    for (int h = 0; h < 4; h++) {
                        g_as[r0 * 8 + hb + h] = ps0[h];
                        g_ad[r0 * 8 + hb + h] = pd0[h];
                    }
                }
                if (r1 < N_NODES) {
#pragma unroll
                    for (int h = 0; h < 4; h++) {
                        g_as[r1 * 8 + hb + h] = ps1[h];
                        g_ad[r1 * 8 + hb + h] = pd1[h];
                    }
                }
            }
        }
    }
}

// ---------------- GAT gather: 2 nodes per warp (16 lanes each), online softmax ----------------
__global__ void gather_kernel(const float* __restrict__ bias,
                              float* __restrict__ outF,
                              __nv_bfloat16* __restrict__ Ohi,
                              __nv_bfloat16* __restrict__ Olo) {
    int node = (blockIdx.x * blockDim.x + threadIdx.x) >> 4;
    if (node >= N_NODES) return;
    int l16 = threadIdx.x & 15;      // 16 lanes per node, 8 cols each
    int head = l16 >> 1;             // 2 lanes per head
    int beg = g_rowptr[node];
    int end = g_rowptr[node + 1];

    float adh = g_ad[node * 8 + head];
    float m = -1e30f, s = 0.f;
    float a0 = 0.f, a1 = 0.f, a2 = 0.f, a3 = 0.f;
    float a4 = 0.f, a5 = 0.f, a6 = 0.f, a7 = 0.f;

    for (int e = beg; e < end; e++) {
        int src = g_col[e];
        float l = __ldg(g_as + src * 8 + head) + adh;
        l = l > 0.f ? l : SLOPE * l;
        const float4* p = (const float4*)(g_h2 + (size_t)src * 128 + l16 * 8);
        float4 v0 = p[0], v1 = p[1];
        float mn = fmaxf(m, l);
        float sc = __expf(m - mn);
        float w  = __expf(l - mn);
        s = s * sc + w;
        a0 = a0 * sc + w * v0.x; a1 = a1 * sc + w * v0.y;
        a2 = a2 * sc + w * v0.z; a3 = a3 * sc + w * v0.w;
        a4 = a4 * sc + w * v1.x; a5 = a5 * sc + w * v1.y;
        a6 = a6 * sc + w * v1.z; a7 = a7 * sc + w * v1.w;
        m = mn;
    }
    float inv = 1.f / (s + 1e-16f);
    float4 b0 = ((const float4*)bias)[l16 * 2];
    float4 b1 = ((const float4*)bias)[l16 * 2 + 1];
    float4 o0, o1;
    o0.x = fmaxf(a0 * inv + b0.x, 0.f);
    o0.y = fmaxf(a1 * inv + b0.y, 0.f);
    o0.z = fmaxf(a2 * inv + b0.z, 0.f);
    o0.w = fmaxf(a3 * inv + b0.w, 0.f);
    o1.x = fmaxf(a4 * inv + b1.x, 0.f);
    o1.y = fmaxf(a5 * inv + b1.y, 0.f);
    o1.z = fmaxf(a6 * inv + b1.z, 0.f);
    o1.w = fmaxf(a7 * inv + b1.w, 0.f);

    if (outF) {
        ((float4*)(outF + (size_t)node * 128))[l16 * 2]     = o0;
        ((float4*)(outF + (size_t)node * 128))[l16 * 2 + 1] = o1;
    }
    if (Ohi) {
        __nv_bfloat16 hv[8], lv[8];
        split_bf16(o0.x, hv[0], lv[0]); split_bf16(o0.y, hv[1], lv[1]);
        split_bf16(o0.z, hv[2], lv[2]); split_bf16(o0.w, hv[3], lv[3]);
        split_bf16(o1.x, hv[4], lv[4]); split_bf16(o1.y, hv[5], lv[5]);
        split_bf16(o1.z, hv[6], lv[6]); split_bf16(o1.w, hv[7], lv[7]);
        *(uint4*)(Ohi + (size_t)node * 128 + l16 * 8) = *(const uint4*)hv;
        *(uint4*)(Olo + (size_t)node * 128 + l16 * 8) = *(const uint4*)lv;
    }
}

// ---------------- pooling ----------------
__global__ void pool_kernel(const int* __restrict__ batch) {
    int b = blockIdx.x, c = threadIdx.x;
    int r0 = b * SCHUNK, r1 = min(r0 + SCHUNK, N_NODES);
    float acc = 0.f;
    int cur = batch[r0];
    for (int r = r0; r < r1; r++) {
        int gb = batch[r];
        if (gb != cur) { atomicAdd(&g_pool[cur * 128 + c], acc); acc = 0.f; cur = gb; }
        acc += g_h[(size_t)r * 128 + c];
    }
    atomicAdd(&g_pool[cur * 128 + c], acc);
}

// ---------------- fused FC + classifier + log_softmax ----------------
__global__ void fccls_kernel(const float* __restrict__ bnfc, const float* __restrict__ fcW,
                             const float* __restrict__ fcb,
                             const float* __restrict__ bnh, const float* __restrict__ Wc,
                             const float* __restrict__ bc, float* __restrict__ out) {
    __shared__ float sh[128];
    __shared__ float sh2[128];
    __shared__ float lg[NCLASS];
    __shared__ float s_mx, s_ls;
    int g = blockIdx.x, t = threadIdx.x;
    float x = g_pool[g * 128 + t];
    float s = bnfc[t] * rsqrtf(bnfc[384 + t] + BN_EPS);
    sh[t] = s * (x - bnfc[256 + t]) + bnfc[128 + t];
    __syncthreads();
    float acc = fcb[t];
    for (int k = 0; k < 128; k++) acc += sh[k] * fcW[k * 128 + t];
    float fo = fmaxf(acc, 0.f);
    float s2 = bnh[t] * rsqrtf(bnh[384 + t] + BN_EPS);
    sh2[t] = s2 * (fo - bnh[256 + t]) + bnh[128 + t];
    __syncthreads();
    if (t < NCLASS) {
        float a2 = bc[t];
        for (int k = 0; k < 128; k++) a2 += sh2[k] * Wc[k * NCLASS + t];
        lg[t] = a2;
    }
    __syncthreads();
    if (t == 0) {
        float mx = lg[0];
        for (int j = 1; j < NCLASS; j++) mx = fmaxf(mx, lg[j]);
        float se = 0.f;
        for (int j = 0; j < NCLASS; j++) se += expf(lg[j] - mx);
        s_mx = mx; s_ls = logf(se);
    }
    __syncthreads();
    if (t < NCLASS) out[g * NCLASS + t] = lg[t] - s_mx - s_ls;
}

// ---------------- launch ----------------
extern "C" void kernel_launch(void* const* d_in, const int* in_sizes, int n_in,
                              void* d_out, int out_size) {
    const float* x        = (const float*)d_in[0];
    const int*   ei       = (const int*)d_in[1];
    const int*   batch    = (const int*)d_in[2];
    const float* bn_feat  = (const float*)d_in[3];
    const float* w_feat   = (const float*)d_in[4];
    const float* b_feat   = (const float*)d_in[5];
    const float* bns_conv = (const float*)d_in[6];
    const float* gat_w    = (const float*)d_in[7];
    const float* att_s    = (const float*)d_in[8];
    const float* att_d    = (const float*)d_in[9];
    const float* gat_b    = (const float*)d_in[10];
    const float* bns_fc   = (const float*)d_in[11];
    const float* fc_w     = (const float*)d_in[12];
    const float* fc_b     = (const float*)d_in[13];
    const float* bn_hid   = (const float*)d_in[14];
    const float* w_cls    = (const float*)d_in[15];
    const float* b_cls    = (const float*)d_in[16];
    float* out = (float*)d_out;

    float *p_h = nullptr, *p_h2 = nullptr, *p_pool = nullptr, *p_bp = nullptr;
    int* p_deg = nullptr;
    __nv_bfloat16 *p_hiA = nullptr, *p_loA = nullptr, *p_hiB = nullptr, *p_loB = nullptr;
    __nv_bfloat16 *p_wthi = nullptr, *p_wtlo = nullptr;
    cudaGetSymbolAddress((void**)&p_h,    g_h);
    cudaGetSymbolAddress((void**)&p_h2,   g_h2);
    cudaGetSymbolAddress((void**)&p_pool, g_pool);
    cudaGetSymbolAddress((void**)&p_deg,  g_deg);
    cudaGetSymbolAddress((void**)&p_hiA,  g_hiA);
    cudaGetSymbolAddress((void**)&p_loA,  g_loA);
    cudaGetSymbolAddress((void**)&p_hiB,  g_hiB);
    cudaGetSymbolAddress((void**)&p_loB,  g_loB);
    cudaGetSymbolAddress((void**)&p_wthi, g_wthi);
    cudaGetSymbolAddress((void**)&p_wtlo, g_wtlo);
    cudaGetSymbolAddress((void**)&p_bp,   g_bpv);

    static cudaStream_t s2 = nullptr;
    static cudaEvent_t e0 = nullptr, e1 = nullptr, e2 = nullptr, e3 = nullptr;
    if (!s2) {
        cudaStreamCreateWithFlags(&s2, cudaStreamNonBlocking);
        cudaEventCreateWithFlags(&e0, cudaEventDisableTiming);
        cudaEventCreateWithFlags(&e1, cudaEventDisableTiming);
        cudaEventCreateWithFlags(&e2, cudaEventDisableTiming);
        cudaEventCreateWithFlags(&e3, cudaEventDisableTiming);
        cudaFuncSetAttribute(mma_gemm_kernel,
                             cudaFuncAttributeMaxDynamicSharedMemorySize, 8 * BUFE * 2);
    }

    const int GEMM_GRID = (N_NODES + 127) / 128;
    const int GEMM_SMEM = 8 * BUFE * 2;

    cudaEventRecord(e0, 0);
    cudaStreamWaitEvent(s2, e0, 0);

    // legacy: convx; s2: prep0 concurrently
    convx_kernel<<<(N_NODES * HIDDIM / 4 + 255) / 256, 256>>>(x);
    prep_kernel<<<65, 256, 0, s2>>>(bn_feat, w_feat, b_feat, 0);
    cudaEventRecord(e3, s2);
    cudaMemsetAsync(p_deg, 0, N_NODES * sizeof(int), s2);
    for (int i = 0; i < 3; i++)
        prep_kernel<<<65, 256, 0, s2>>>(bns_conv + i * 512, gat_w + i * 16384,
                                        (const float*)nullptr, i + 1);
    cudaEventRecord(e2, s2);
    count_kernel<<<(N_EDGES + 255) / 256, 256, 0, s2>>>(ei);
    scanA_kernel<<<NSCH, SCHUNK, 0, s2>>>();
    scanB_kernel<<<1, 512, 0, s2>>>();
    scanC_kernel<<<(N_NODES + 255) / 256, 256, 0, s2>>>();
    fill_kernel <<<(N_TOT + 255) / 256, 256, 0, s2>>>(ei);
    cudaMemsetAsync(p_pool, 0, NGROUP * HIDDIM * sizeof(float), s2);
    cudaEventRecord(e1, s2);

    cudaStreamWaitEvent(0, e3, 0);   // prep0 ready
    // feature GEMM (layer 0)
    mma_gemm_kernel<<<GEMM_GRID, 256, GEMM_SMEM>>>(p_hiA, p_loA,
                                                   p_wthi, p_wtlo, p_bp,
                                                   (float*)nullptr, p_hiB, p_loB,
                                                   (const float*)nullptr,
                                                   (const float*)nullptr, 1);
    cudaStreamWaitEvent(0, e2, 0);   // conv weights ready

    __nv_bfloat16* inhi[3] = {p_hiB, p_hiA, p_hiB};
    __nv_bfloat16* inlo[3] = {p_loB, p_loA, p_loB};
    __nv_bfloat16* othi[3] = {p_hiA, p_hiB, (__nv_bfloat16*)nullptr};
    __nv_bfloat16* otlo[3] = {p_loA, p_loB, (__nv_bfloat16*)nullptr};

    // conv0 GEMM
    mma_gemm_kernel<<<GEMM_GRID, 256, GEMM_SMEM>>>(inhi[0], inlo[0],
                                                   p_wthi + 16384, p_wtlo + 16384, p_bp + 128,
                                                   p_h2,
                                                   (__nv_bfloat16*)nullptr, (__nv_bfloat16*)nullptr,
                                                   att_s, att_d, 0);
    cudaStreamWaitEvent(0, e1, 0);   // CSR + pool-memset ready

    for (int i = 0; i < 3; i++) {
        if (i > 0) {
            mma_gemm_kernel<<<GEMM_GRID, 256, GEMM_SMEM>>>(inhi[i], inlo[i],
                                                           p_wthi + (i + 1) * 16384,
                                                           p_wtlo + (i + 1) * 16384,
                                                           p_bp + (i + 1) * 128,
                                                           p_h2,
                                                           (__nv_bfloat16*)nullptr, (__nv_bfloat16*)nullptr,
                                                           att_s + i * 128, att_d + i * 128, 0);
        }
        gather_kernel<<<(N_NODES * 16 + 255) / 256, 256>>>(gat_b + i * 128,
                                            (i == 2) ? p_h : (float*)nullptr,
                                            othi[i], otlo[i]);
    }

    pool_kernel <<<NSCH, 128>>>(batch);
    fccls_kernel<<<NGROUP, 128>>>(bns_fc, fc_w, fc_b, bn_hid, w_cls, b_cls, out);
}

// round 10
// speedup vs baseline: 1.3702x; 1.0347x over previous
#include <cuda_runtime.h>
#include <cuda_bf16.h>
#include <cuda_fp16.h>
#include <stdint.h>
#include <math.h>

#define N_NODES 50000
#define N_EDGES 800000
#define N_TOT   (N_EDGES + N_NODES)
#define HIDDIM  128
#define NHEADS  8
#define NGROUP  64
#define NCLASS  10
#define BN_EPS  1e-5f
#define SLOPE   0.2f
#define SCHUNK  128
#define NSCH    ((N_NODES + SCHUNK - 1) / SCHUNK)

// ---------------- device scratch ----------------
static __device__ float g_h   [N_NODES * HIDDIM];
static __device__ __align__(16) __half g_hm [N_NODES * HIDDIM];   // fp16 messages
static __device__ __align__(16) __nv_bfloat16 g_hiA[N_NODES * HIDDIM];
static __device__ __align__(16) __nv_bfloat16 g_loA[N_NODES * HIDDIM];
static __device__ __align__(16) __nv_bfloat16 g_hiB[N_NODES * HIDDIM];
static __device__ __align__(16) __nv_bfloat16 g_loB[N_NODES * HIDDIM];
static __device__ __align__(16) __nv_bfloat16 g_wthi[4][HIDDIM * HIDDIM];
static __device__ __align__(16) __nv_bfloat16 g_wtlo[4][HIDDIM * HIDDIM];
static __device__ float g_bpv [4][HIDDIM];
static __device__ float g_as  [N_NODES * NHEADS];
static __device__ float g_ad  [N_NODES * NHEADS];
static __device__ int   g_rowptr[N_NODES + 1];
static __device__ int   g_cursor[N_NODES];
static __device__ int   g_deg   [N_NODES];
static __device__ int   g_part  [512];
static __device__ int   g_col   [N_TOT];
static __device__ float g_pool [NGROUP * HIDDIM];

// ---------------- CSR build ----------------
__global__ void count_kernel(const int* __restrict__ ei) {
    int e = blockIdx.x * blockDim.x + threadIdx.x;
    if (e < N_EDGES) atomicAdd(&g_deg[ei[N_EDGES + e]], 1);
}

__global__ void scanA_kernel() {
    __shared__ int sh[SCHUNK];
    int b = blockIdx.x, t = threadIdx.x;
    int i = b * SCHUNK + t;
    int v = (i < N_NODES) ? (g_deg[i] + 1) : 0;
    sh[t] = v; __syncthreads();
    for (int off = 1; off < SCHUNK; off <<= 1) {
        int x = (t >= off) ? sh[t - off] : 0; __syncthreads();
        sh[t] += x; __syncthreads();
    }
    if (i < N_NODES) g_cursor[i] = sh[t];
    if (t == SCHUNK - 1) g_part[b] = sh[t];
}

__global__ void scanB_kernel() {
    __shared__ int sh[512];
    int t = threadIdx.x;
    int v = (t < NSCH) ? g_part[t] : 0;
    sh[t] = v; __syncthreads();
    for (int off = 1; off < 512; off <<= 1) {
        int x = (t >= off) ? sh[t - off] : 0; __syncthreads();
        sh[t] += x; __syncthreads();
    }
    if (t < NSCH) g_part[t] = sh[t] - v;
    if (t == 511) g_rowptr[N_NODES] = sh[511];
}

__global__ void scanC_kernel() {
    int i = blockIdx.x * blockDim.x + threadIdx.x;
    if (i >= N_NODES) return;
    int excl = g_cursor[i] - (g_deg[i] + 1) + g_part[i / SCHUNK];
    g_rowptr[i] = excl;
    g_cursor[i] = excl;
}

__global__ void fill_kernel(const int* __restrict__ ei) {
    int e = blockIdx.x * blockDim.x + threadIdx.x;
    if (e >= N_TOT) return;
    int s, d;
    if (e < N_EDGES) { s = ei[e]; d = ei[N_EDGES + e]; }
    else             { s = d = e - N_EDGES; }
    int p = atomicAdd(&g_cursor[d], 1);
    g_col[p] = s;
}

// ---------------- bf16 split helpers ----------------
__device__ __forceinline__ void split_bf16(float x, __nv_bfloat16& h, __nv_bfloat16& l) {
    h = __float2bfloat16(x);
    l = __float2bfloat16(x - __bfloat162float(h));
}

// ---------------- input conversion ----------------
__global__ void convx_kernel(const float* __restrict__ x) {
    int i = blockIdx.x * blockDim.x + threadIdx.x;
    float4 v = ((const float4*)x)[i];
    __nv_bfloat16 h0,l0,h1,l1,h2,l2,h3,l3;
    split_bf16(v.x,h0,l0); split_bf16(v.y,h1,l1);
    split_bf16(v.z,h2,l2); split_bf16(v.w,h3,l3);
    __nv_bfloat162 a; a.x=h0; a.y=h1;
    __nv_bfloat162 b; b.x=h2; b.y=h3;
    __nv_bfloat162 c; c.x=l0; c.y=l1;
    __nv_bfloat162 d; d.x=l2; d.y=l3;
    ((__nv_bfloat162*)g_hiA)[i*2]   = a;
    ((__nv_bfloat162*)g_hiA)[i*2+1] = b;
    ((__nv_bfloat162*)g_loA)[i*2]   = c;
    ((__nv_bfloat162*)g_loA)[i*2+1] = d;
}

// ---------------- weight prep: fast bias fold ----------------
__global__ void prep_kernel(const float* __restrict__ bnp, const float* __restrict__ W,
                            const float* __restrict__ extra, int layer) {
    int b = blockIdx.x;
    if (b < 64) {
        int i = b * 256 + threadIdx.x;
        int k = i >> 7, n = i & 127;
        float s = bnp[k] * rsqrtf(bnp[384 + k] + BN_EPS);
        float w = s * W[i];
        __nv_bfloat16 h, l;
        split_bf16(w, h, l);
        g_wthi[layer][n * 128 + k] = h;
        g_wtlo[layer][n * 128 + k] = l;
    } else {
        __shared__ float cs[128];
        __shared__ float part[256];
        int t = threadIdx.x;
        if (t < 128) {
            float s = bnp[t] * rsqrtf(bnp[384 + t] + BN_EPS);
            cs[t] = bnp[128 + t] - s * bnp[256 + t];
        }
        __syncthreads();
        int j = t & 127, half = t >> 7;
        float acc = 0.f;
        int k0 = half * 64;
#pragma unroll 8
        for (int k = k0; k < k0 + 64; k++) acc += cs[k] * W[k * HIDDIM + j];
        part[t] = acc;
        __syncthreads();
        if (t < 128) g_bpv[layer][j] = part[j] + part[j + 128] + (extra ? extra[j] : 0.f);
    }
}

// ---------------- cp.async helpers ----------------
__device__ __forceinline__ void cpa16(void* sdst, const void* gsrc, int srcbytes) {
    uint32_t s = (uint32_t)__cvta_generic_to_shared(sdst);
    asm volatile("cp.async.ca.shared.global [%0], [%1], 16, %2;"
                 :: "r"(s), "l"(gsrc), "r"(srcbytes));
}
__device__ __forceinline__ void cpa_commit() {
    asm volatile("cp.async.commit_group;");
}

__device__ __forceinline__ void mma16816(float c[4], uint32_t a0, uint32_t a1,
                                         uint32_t a2, uint32_t a3,
                                         uint32_t b0, uint32_t b1) {
    asm volatile(
        "mma.sync.aligned.m16n8k16.row.col.f32.bf16.bf16.f32 "
        "{%0,%1,%2,%3}, {%4,%5,%6,%7}, {%8,%9}, {%0,%1,%2,%3};"
        : "+f"(c[0]), "+f"(c[1]), "+f"(c[2]), "+f"(c[3])
        : "r"(a0), "r"(a1), "r"(a2), "r"(a3), "r"(b0), "r"(b1));
}

// ---------------- tensor-core GEMM: k-major 3-term split, cp.async pipeline ----------------
#define SMS   40
#define BUFE  (128 * SMS)
__global__ void __launch_bounds__(256)
mma_gemm_kernel(const __nv_bfloat16* __restrict__ Ahi,
                const __nv_bfloat16* __restrict__ Alo,
                const __nv_bfloat16* __restrict__ Bhg,
                const __nv_bfloat16* __restrict__ Blg,
                const float* __restrict__ bp,
                __half* __restrict__ Cm,            // fp16 message output (convs)
                __nv_bfloat16* __restrict__ Ohi,
                __nv_bfloat16* __restrict__ Olo,
                const float* __restrict__ att_s,
                const float* __restrict__ att_d,
                int do_relu) {
    extern __shared__ __nv_bfloat16 dsm[];
    __nv_bfloat16* sAhi = dsm;
    __nv_bfloat16* sAlo = dsm + 2 * BUFE;
    __nv_bfloat16* sBhi = dsm + 4 * BUFE;
    __nv_bfloat16* sBlo = dsm + 6 * BUFE;

    int tid = threadIdx.x;
    int wid = tid >> 5, lane = tid & 31;
    int g = lane >> 2, tc = lane & 3;
    int wr = (wid & 3) * 32, wc = (wid >> 2) * 64;
    int row0 = blockIdx.x * 128;

    float c[2][8][4];
#pragma unroll
    for (int a = 0; a < 2; a++)
#pragma unroll
        for (int b = 0; b < 8; b++)
#pragma unroll
            for (int q = 0; q < 4; q++) c[a][b][q] = 0.f;

    int lr = tid >> 1, half = tid & 1;
    int gr = row0 + lr;
    int vb = (gr < N_NODES) ? 16 : 0;
    size_t abase = (size_t)(gr < N_NODES ? gr : 0) * 128 + half * 16;
    int bbase = lr * 128 + half * 16;
    int soff = lr * SMS + half * 16;

    auto issue = [&](int k, int buf) {
        int k0 = k * 32;
        cpa16(sAhi + buf * BUFE + soff,     Ahi + abase + k0,     vb);
        cpa16(sAhi + buf * BUFE + soff + 8, Ahi + abase + k0 + 8, vb);
        cpa16(sAlo + buf * BUFE + soff,     Alo + abase + k0,     vb);
        cpa16(sAlo + buf * BUFE + soff + 8, Alo + abase + k0 + 8, vb);
        cpa16(sBhi + buf * BUFE + soff,     Bhg + bbase + k0,     16);
        cpa16(sBhi + buf * BUFE + soff + 8, Bhg + bbase + k0 + 8, 16);
        cpa16(sBlo + buf * BUFE + soff,     Blg + bbase + k0,     16);
        cpa16(sBlo + buf * BUFE + soff + 8, Blg + bbase + k0 + 8, 16);
        cpa_commit();
    };

    issue(0, 0);
    for (int k = 0; k < 4; k++) {
        int cur = k & 1;
        if (k < 3) {
            issue(k + 1, cur ^ 1);
            asm volatile("cp.async.wait_group 1;");
        } else {
            asm volatile("cp.async.wait_group 0;");
        }
        __syncthreads();

        const __nv_bfloat16* Ah = sAhi + cur * BUFE;
        const __nv_bfloat16* Al = sAlo + cur * BUFE;
        const __nv_bfloat16* Bh = sBhi + cur * BUFE;
        const __nv_bfloat16* Bl = sBlo + cur * BUFE;
#pragma unroll
        for (int s = 0; s < 2; s++) {
            int kb = s * 16;
            uint32_t ah[2][4];
#pragma unroll
            for (int mf = 0; mf < 2; mf++) {
                int m = wr + mf * 16 + g;
                ah[mf][0] = *(const uint32_t*)(Ah + m * SMS + kb + tc * 2);
                ah[mf][1] = *(const uint32_t*)(Ah + (m + 8) * SMS + kb + tc * 2);
                ah[mf][2] = *(const uint32_t*)(Ah + m * SMS + kb + tc * 2 + 8);
                ah[mf][3] = *(const uint32_t*)(Ah + (m + 8) * SMS + kb + tc * 2 + 8);
            }
            uint32_t bh[8][2];
#pragma unroll
            for (int nf = 0; nf < 8; nf++) {
                int n = wc + nf * 8 + g;
                bh[nf][0] = *(const uint32_t*)(Bh + n * SMS + kb + tc * 2);
                bh[nf][1] = *(const uint32_t*)(Bh + n * SMS + kb + tc * 2 + 8);
            }
#pragma unroll
            for (int mf = 0; mf < 2; mf++)
#pragma unroll
                for (int nf = 0; nf < 8; nf++)
                    mma16816(c[mf][nf], ah[mf][0], ah[mf][1], ah[mf][2], ah[mf][3],
                             bh[nf][0], bh[nf][1]);
            {
                uint32_t bl[8][2];
#pragma unroll
                for (int nf = 0; nf < 8; nf++) {
                    int n = wc + nf * 8 + g;
                    bl[nf][0] = *(const uint32_t*)(Bl + n * SMS + kb + tc * 2);
                    bl[nf][1] = *(const uint32_t*)(Bl + n * SMS + kb + tc * 2 + 8);
                }
#pragma unroll
                for (int mf = 0; mf < 2; mf++)
#pragma unroll
                    for (int nf = 0; nf < 8; nf++)
                        mma16816(c[mf][nf], ah[mf][0], ah[mf][1], ah[mf][2], ah[mf][3],
                                 bl[nf][0], bl[nf][1]);
            }
            uint32_t al[2][4];
#pragma unroll
            for (int mf = 0; mf < 2; mf++) {
                int m = wr + mf * 16 + g;
                al[mf][0] = *(const uint32_t*)(Al + m * SMS + kb + tc * 2);
                al[mf][1] = *(const uint32_t*)(Al + (m + 8) * SMS + kb + tc * 2);
                al[mf][2] = *(const uint32_t*)(Al + m * SMS + kb + tc * 2 + 8);
                al[mf][3] = *(const uint32_t*)(Al + (m + 8) * SMS + kb + tc * 2 + 8);
            }
#pragma unroll
            for (int mf = 0; mf < 2; mf++)
#pragma unroll
                for (int nf = 0; nf < 8; nf++)
                    mma16816(c[mf][nf], al[mf][0], al[mf][1], al[mf][2], al[mf][3],
                             bh[nf][0], bh[nf][1]);
        }
        __syncthreads();
    }

    // epilogue
#pragma unroll
    for (int mf = 0; mf < 2; mf++) {
        int r0 = row0 + wr + mf * 16 + g;
        int r1 = r0 + 8;
        float ps0[4] = {0,0,0,0}, pd0[4] = {0,0,0,0};
        float ps1[4] = {0,0,0,0}, pd1[4] = {0,0,0,0};
#pragma unroll
        for (int nf = 0; nf < 8; nf++) {
            int cc = wc + nf * 8 + tc * 2;
            float b0 = bp[cc], b1 = bp[cc + 1];
            float v00 = c[mf][nf][0] + b0, v01 = c[mf][nf][1] + b1;
            float v10 = c[mf][nf][2] + b0, v11 = c[mf][nf][3] + b1;
            if (do_relu) {
                v00 = fmaxf(v00, 0.f); v01 = fmaxf(v01, 0.f);
                v10 = fmaxf(v10, 0.f); v11 = fmaxf(v11, 0.f);
            }
            if (att_s) {
                int hl = nf >> 1;
                float as0 = att_s[cc], as1 = att_s[cc + 1];
                float ad0 = att_d[cc], ad1 = att_d[cc + 1];
                ps0[hl] += v00 * as0 + v01 * as1;
                pd0[hl] += v00 * ad0 + v01 * ad1;
                ps1[hl] += v10 * as0 + v11 * as1;
                pd1[hl] += v10 * ad0 + v11 * ad1;
            }
            if (Cm) {
                if (r0 < N_NODES)
                    *(__half2*)(Cm + (size_t)r0 * 128 + cc) = __floats2half2_rn(v00, v01);
                if (r1 < N_NODES)
                    *(__half2*)(Cm + (size_t)r1 * 128 + cc) = __floats2half2_rn(v10, v11);
            }
            if (Ohi) {
                __nv_bfloat16 h0, l0, h1, l1;
                if (r0 < N_NODES) {
                    split_bf16(v00, h0, l0); split_bf16(v01, h1, l1);
                    __nv_bfloat162 th; th.x = h0; th.y = h1;
                    __nv_bfloat162 tl; tl.x = l0; tl.y = l1;
                    *(__nv_bfloat162*)(Ohi + (size_t)r0 * 128 + cc) = th;
                    *(__nv_bfloat162*)(Olo + (size_t)r0 * 128 + cc) = tl;
                }
                if (r1 < N_NODES) {
                    split_bf16(v10, h0, l0); split_bf16(v11, h1, l1);
                    __nv_bfloat162 th; th.x = h0; th.y = h1;
                    __nv_bfloat162 tl; tl.x = l0; tl.y = l1;
                    *(__nv_bfloat162*)(Ohi + (size_t)r1 * 128 + cc) = th;
                    *(__nv_bfloat162*)(Olo + (size_t)r1 * 128 + cc) = tl;
                }
            }
        }
        if (att_s) {
#pragma unroll
            for (int h = 0; h < 4; h++) {
                ps0[h] += __shfl_xor_sync(0xffffffffu, ps0[h], 1);
                ps0[h] += __shfl_xor_sync(0xffffffffu, ps0[h], 2);
                pd0[h] += __shfl_xor_sync(0xffffffffu, pd0[h], 1);
                pd0[h] += __shfl_xor_sync(0xffffffffu, pd0[h], 2);
                ps1[h] += __shfl_xor_sync(0xffffffffu, ps1[h], 1);
                ps1[h] += __shfl_xor_sync(0xffffffffu, ps1[h], 2);
                pd1[h] += __shfl_xor_sync(0xffffffffu, pd1[h], 1);
                pd1[h] += __shfl_xor_sync(0xffffffffu, pd1[h], 2);
            }
            if (tc == 0) {
                int hb = wc >> 4;
                if (r0 < N_NODES) {
#pragma unroll
                    for (int h = 0; h < 4; h++) {
                        g_as[r0 * 8 + hb + h] = ps0[h];
                        g_ad[r0 * 8 + hb + h] = pd0[h];
                    }
                }
                if (r1 < N_NODES) {
#pragma unroll
                    for (int h = 0; h < 4; h++) {
                        g_as[r1 * 8 + hb + h] = ps1[h];
                        g_ad[r1 * 8 + hb + h] = pd1[h];
                    }
                }
            }
        }
    }
}

// ---------------- GAT gather: 2 nodes/warp, fp16 messages (256B/row) ----------------
__global__ void gather_kernel(const float* __restrict__ bias,
                              float* __restrict__ outF,
                              __nv_bfloat16* __restrict__ Ohi,
                              __nv_bfloat16* __restrict__ Olo) {
    int node = (blockIdx.x * blockDim.x + threadIdx.x) >> 4;
    if (node >= N_NODES) return;
    int l16 = threadIdx.x & 15;      // 16 lanes per node, 8 cols each
    int head = l16 >> 1;
    int beg = g_rowptr[node];
    int end = g_rowptr[node + 1];

    float adh = g_ad[node * 8 + head];
    float m = -1e30f, s = 0.f;
    float a0 = 0.f, a1 = 0.f, a2 = 0.f, a3 = 0.f;
    float a4 = 0.f, a5 = 0.f, a6 = 0.f, a7 = 0.f;

    for (int e = beg; e < end; e++) {
        int src = g_col[e];
        float l = __ldg(g_as + src * 8 + head) + adh;
        l = l > 0.f ? l : SLOPE * l;
        uint4 raw = *(const uint4*)(g_hm + (size_t)src * 128 + l16 * 8);   // 8 fp16
        __half2* ph = (__half2*)&raw;
        float2 f0 = __half22float2(ph[0]);
        float2 f1 = __half22float2(ph[1]);
        float2 f2 = __half22float2(ph[2]);
        float2 f3 = __half22float2(ph[3]);
        float mn = fmaxf(m, l);
        float sc = __expf(m - mn);
        float w  = __expf(l - mn);
        s = s * sc + w;
        a0 = a0 * sc + w * f0.x; a1 = a1 * sc + w * f0.y;
        a2 = a2 * sc + w * f1.x; a3 = a3 * sc + w * f1.y;
        a4 = a4 * sc + w * f2.x; a5 = a5 * sc + w * f2.y;
        a6 = a6 * sc + w * f3.x; a7 = a7 * sc + w * f3.y;
        m = mn;
    }
    float inv = 1.f / (s + 1e-16f);
    float4 b0 = ((const float4*)bias)[l16 * 2];
    float4 b1 = ((const float4*)bias)[l16 * 2 + 1];
    float4 o0, o1;
    o0.x = fmaxf(a0 * inv + b0.x, 0.f);
    o0.y = fmaxf(a1 * inv + b0.y, 0.f);
    o0.z = fmaxf(a2 * inv + b0.z, 0.f);
    o0.w = fmaxf(a3 * inv + b0.w, 0.f);
    o1.x = fmaxf(a4 * inv + b1.x, 0.f);
    o1.y = fmaxf(a5 * inv + b1.y, 0.f);
    o1.z = fmaxf(a6 * inv + b1.z, 0.f);
    o1.w = fmaxf(a7 * inv + b1.w, 0.f);

    if (outF) {
        ((float4*)(outF + (size_t)node * 128))[l16 * 2]     = o0;
        ((float4*)(outF + (size_t)node * 128))[l16 * 2 + 1] = o1;
    }
    if (Ohi) {
        __nv_bfloat16 hv[8], lv[8];
        split_bf16(o0.x, hv[0], lv[0]); split_bf16(o0.y, hv[1], lv[1]);
        split_bf16(o0.z, hv[2], lv[2]); split_bf16(o0.w, hv[3], lv[3]);
        split_bf16(o1.x, hv[4], lv[4]); split_bf16(o1.y, hv[5], lv[5]);
        split_bf16(o1.z, hv[6], lv[6]); split_bf16(o1.w, hv[7], lv[7]);
        *(uint4*)(Ohi + (size_t)node * 128 + l16 * 8) = *(const uint4*)hv;
        *(uint4*)(Olo + (size_t)node * 128 + l16 * 8) = *(const uint4*)lv;
    }
}

// ---------------- pooling ----------------
__global__ void pool_kernel(const int* __restrict__ batch) {
    int b = blockIdx.x, c = threadIdx.x;
    int r0 = b * SCHUNK, r1 = min(r0 + SCHUNK, N_NODES);
    float acc = 0.f;
    int cur = batch[r0];
    for (int r = r0; r < r1; r++) {
        int gb = batch[r];
        if (gb != cur) { atomicAdd(&g_pool[cur * 128 + c], acc); acc = 0.f; cur = gb; }
        acc += g_h[(size_t)r * 128 + c];
    }
    atomicAdd(&g_pool[cur * 128 + c], acc);
}

// ---------------- fused FC + classifier + log_softmax ----------------
__global__ void fccls_kernel(const float* __restrict__ bnfc, const float* __restrict__ fcW,
                             const float* __restrict__ fcb,
                             const float* __restrict__ bnh, const float* __restrict__ Wc,
                             const float* __restrict__ bc, float* __restrict__ out) {
    __shared__ float sh[128];
    __shared__ float sh2[128];
    __shared__ float lg[NCLASS];
    __shared__ float s_mx, s_ls;
    int g = blockIdx.x, t = threadIdx.x;
    float x = g_pool[g * 128 + t];
    float s = bnfc[t] * rsqrtf(bnfc[384 + t] + BN_EPS);
    sh[t] = s * (x - bnfc[256 + t]) + bnfc[128 + t];
    __syncthreads();
    float acc = fcb[t];
    for (int k = 0; k < 128; k++) acc += sh[k] * fcW[k * 128 + t];
    float fo = fmaxf(acc, 0.f);
    float s2 = bnh[t] * rsqrtf(bnh[384 + t] + BN_EPS);
    sh2[t] = s2 * (fo - bnh[256 + t]) + bnh[128 + t];
    __syncthreads();
    if (t < NCLASS) {
        float a2 = bc[t];
        for (int k = 0; k < 128; k++) a2 += sh2[k] * Wc[k * NCLASS + t];
        lg[t] = a2;
    }
    __syncthreads();
    if (t == 0) {
        float mx = lg[0];
        for (int j = 1; j < NCLASS; j++) mx = fmaxf(mx, lg[j]);
        float se = 0.f;
        for (int j = 0; j < NCLASS; j++) se += expf(lg[j] - mx);
        s_mx = mx; s_ls = logf(se);
    }
    __syncthreads();
    if (t < NCLASS) out[g * NCLASS + t] = lg[t] - s_mx - s_ls;
}

// ---------------- launch ----------------
extern "C" void kernel_launch(void* const* d_in, const int* in_sizes, int n_in,
                              void* d_out, int out_size) {
    const float* x        = (const float*)d_in[0];
    const int*   ei       = (const int*)d_in[1];
    const int*   batch    = (const int*)d_in[2];
    const float* bn_feat  = (const float*)d_in[3];
    const float* w_feat   = (const float*)d_in[4];
    const float* b_feat   = (const float*)d_in[5];
    const float* bns_conv = (const float*)d_in[6];
    const float* gat_w    = (const float*)d_in[7];
    const float* att_s    = (const float*)d_in[8];
    const float* att_d    = (const float*)d_in[9];
    const float* gat_b    = (const float*)d_in[10];
    const float* bns_fc   = (const float*)d_in[11];
    const float* fc_w     = (const float*)d_in[12];
    const float* fc_b     = (const float*)d_in[13];
    const float* bn_hid   = (const float*)d_in[14];
    const float* w_cls    = (const float*)d_in[15];
    const float* b_cls    = (const float*)d_in[16];
    float* out = (float*)d_out;

    float *p_h = nullptr, *p_pool = nullptr, *p_bp = nullptr;
    __half* p_hm = nullptr;
    int* p_deg = nullptr;
    __nv_bfloat16 *p_hiA = nullptr, *p_loA = nullptr, *p_hiB = nullptr, *p_loB = nullptr;
    __nv_bfloat16 *p_wthi = nullptr, *p_wtlo = nullptr;
    cudaGetSymbolAddress((void**)&p_h,    g_h);
    cudaGetSymbolAddress((void**)&p_hm,   g_hm);
    cudaGetSymbolAddress((void**)&p_pool, g_pool);
    cudaGetSymbolAddress((void**)&p_deg,  g_deg);
    cudaGetSymbolAddress((void**)&p_hiA,  g_hiA);
    cudaGetSymbolAddress((void**)&p_loA,  g_loA);
    cudaGetSymbolAddress((void**)&p_hiB,  g_hiB);
    cudaGetSymbolAddress((void**)&p_loB,  g_loB);
    cudaGetSymbolAddress((void**)&p_wthi, g_wthi);
    cudaGetSymbolAddress((void**)&p_wtlo, g_wtlo);
    cudaGetSymbolAddress((void**)&p_bp,   g_bpv);

    static cudaStream_t s2 = nullptr;
    static cudaEvent_t e0 = nullptr, e1 = nullptr, e2 = nullptr, e3 = nullptr;
    if (!s2) {
        cudaStreamCreateWithFlags(&s2, cudaStreamNonBlocking);
        cudaEventCreateWithFlags(&e0, cudaEventDisableTiming);
        cudaEventCreateWithFlags(&e1, cudaEventDisableTiming);
        cudaEventCreateWithFlags(&e2, cudaEventDisableTiming);
        cudaEventCreateWithFlags(&e3, cudaEventDisableTiming);
        cudaFuncSetAttribute(mma_gemm_kernel,
                             cudaFuncAttributeMaxDynamicSharedMemorySize, 8 * BUFE * 2);
    }

    const int GEMM_GRID = (N_NODES + 127) / 128;
    const int GEMM_SMEM = 8 * BUFE * 2;

    cudaEventRecord(e0, 0);
    cudaStreamWaitEvent(s2, e0, 0);

    // legacy: convx; s2: prep0 concurrently
    convx_kernel<<<(N_NODES * HIDDIM / 4 + 255) / 256, 256>>>(x);
    prep_kernel<<<65, 256, 0, s2>>>(bn_feat, w_feat, b_feat, 0);
    cudaEventRecord(e3, s2);
    cudaMemsetAsync(p_deg, 0, N_NODES * sizeof(int), s2);
    for (int i = 0; i < 3; i++)
        prep_kernel<<<65, 256, 0, s2>>>(bns_conv + i * 512, gat_w + i * 16384,
                                        (const float*)nullptr, i + 1);
    cudaEventRecord(e2, s2);
    count_kernel<<<(N_EDGES + 255) / 256, 256, 0, s2>>>(ei);
    scanA_kernel<<<NSCH, SCHUNK, 0, s2>>>();
    scanB_kernel<<<1, 512, 0, s2>>>();
    scanC_kernel<<<(N_NODES + 255) / 256, 256, 0, s2>>>();
    fill_kernel <<<(N_TOT + 255) / 256, 256, 0, s2>>>(ei);
    cudaMemsetAsync(p_pool, 0, NGROUP * HIDDIM * sizeof(float), s2);
    cudaEventRecord(e1, s2);

    cudaStreamWaitEvent(0, e3, 0);   // prep0 ready
    // feature GEMM (layer 0): outputs bf16 hi/lo only
    mma_gemm_kernel<<<GEMM_GRID, 256, GEMM_SMEM>>>(p_hiA, p_loA,
                                                   p_wthi, p_wtlo, p_bp,
                                                   (__half*)nullptr, p_hiB, p_loB,
                                                   (const float*)nullptr,
                                                   (const float*)nullptr, 1);
    cudaStreamWaitEvent(0, e2, 0);   // conv weights ready

    __nv_bfloat16* inhi[3] = {p_hiB, p_hiA, p_hiB};
    __nv_bfloat16* inlo[3] = {p_loB, p_loA, p_loB};
    __nv_bfloat16* othi[3] = {p_hiA, p_hiB, (__nv_bfloat16*)nullptr};
    __nv_bfloat16* otlo[3] = {p_loA, p_loB, (__nv_bfloat16*)nullptr};

    // conv0 GEMM: fp16 messages + att coefficients
    mma_gemm_kernel<<<GEMM_GRID, 256, GEMM_SMEM>>>(inhi[0], inlo[0],
                                                   p_wthi + 16384, p_wtlo + 16384, p_bp + 128,
                                                   p_hm,
                                                   (__nv_bfloat16*)nullptr, (__nv_bfloat16*)nullptr,
                                                   att_s, att_d, 0);
    cudaStreamWaitEvent(0, e1, 0);   // CSR + pool-memset ready

    for (int i = 0; i < 3; i++) {
        if (i > 0) {
            mma_gemm_kernel<<<GEMM_GRID, 256, GEMM_SMEM>>>(inhi[i], inlo[i],
                                                           p_wthi + (i + 1) * 16384,
                                                           p_wtlo + (i + 1) * 16384,
                                                           p_bp + (i + 1) * 128,
                                                           p_hm,
                                                           (__nv_bfloat16*)nullptr, (__nv_bfloat16*)nullptr,
                                                           att_s + i * 128, att_d + i * 128, 0);
        }
        gather_kernel<<<(N_NODES * 16 + 255) / 256, 256>>>(gat_b + i * 128,
                                            (i == 2) ? p_h : (float*)nullptr,
                                            othi[i], otlo[i]);
    }

    pool_kernel <<<NSCH, 128>>>(batch);
    fccls_kernel<<<NGROUP, 128>>>(bns_fc, fc_w, fc_b, bn_hid, w_cls, b_cls, out);
}

// round 11
// speedup vs baseline: 1.4844x; 1.0833x over previous
#include <cuda_runtime.h>
#include <cuda_bf16.h>
#include <cuda_fp16.h>
#include <stdint.h>
#include <math.h>

#define N_NODES 50000
#define N_EDGES 800000
#define N_TOT   (N_EDGES + N_NODES)
#define HIDDIM  128
#define NHEADS  8
#define NGROUP  64
#define NCLASS  10
#define BN_EPS  1e-5f
#define SLOPE   0.2f
#define SCHUNK  128
#define NSCH    ((N_NODES + SCHUNK - 1) / SCHUNK)

// ---------------- device scratch ----------------
static __device__ float g_h   [N_NODES * HIDDIM];
static __device__ __align__(16) __half g_hm [N_NODES * HIDDIM];   // fp16 messages
static __device__ __align__(16) __nv_bfloat16 g_hiA[N_NODES * HIDDIM];
static __device__ __align__(16) __nv_bfloat16 g_loA[N_NODES * HIDDIM];
static __device__ __align__(16) __nv_bfloat16 g_hiB[N_NODES * HIDDIM];
static __device__ __align__(16) __nv_bfloat16 g_loB[N_NODES * HIDDIM];
static __device__ __align__(16) __nv_bfloat16 g_wthi[4][HIDDIM * HIDDIM];
static __device__ __align__(16) __nv_bfloat16 g_wtlo[4][HIDDIM * HIDDIM];
static __device__ float g_bpv [4][HIDDIM];
static __device__ float g_as  [N_NODES * NHEADS];
static __device__ float g_ad  [N_NODES * NHEADS];
static __device__ unsigned g_asmax[3][NHEADS];    // per-layer per-head global max of as (encoded)
static __device__ int   g_rowptr[N_NODES + 1];
static __device__ int   g_cursor[N_NODES];
static __device__ int   g_deg   [N_NODES];
static __device__ int   g_part  [512];
static __device__ int   g_col   [N_TOT];
static __device__ float g_pool [NGROUP * HIDDIM];

// order-preserving float<->uint encoding for atomicMax
__device__ __forceinline__ unsigned fenc(float f) {
    unsigned u = __float_as_uint(f);
    return (u & 0x80000000u) ? ~u : (u | 0x80000000u);
}
__device__ __forceinline__ float fdec(unsigned e) {
    return (e & 0x80000000u) ? __uint_as_float(e ^ 0x80000000u) : __uint_as_float(~e);
}

// ---------------- CSR build ----------------
__global__ void count_kernel(const int* __restrict__ ei) {
    int e = blockIdx.x * blockDim.x + threadIdx.x;
    if (e < N_EDGES) atomicAdd(&g_deg[ei[N_EDGES + e]], 1);
}

__global__ void scanA_kernel() {
    __shared__ int sh[SCHUNK];
    int b = blockIdx.x, t = threadIdx.x;
    int i = b * SCHUNK + t;
    int v = (i < N_NODES) ? (g_deg[i] + 1) : 0;
    sh[t] = v; __syncthreads();
    for (int off = 1; off < SCHUNK; off <<= 1) {
        int x = (t >= off) ? sh[t - off] : 0; __syncthreads();
        sh[t] += x; __syncthreads();
    }
    if (i < N_NODES) g_cursor[i] = sh[t];
    if (t == SCHUNK - 1) g_part[b] = sh[t];
}

__global__ void scanB_kernel() {
    __shared__ int sh[512];
    int t = threadIdx.x;
    int v = (t < NSCH) ? g_part[t] : 0;
    sh[t] = v; __syncthreads();
    for (int off = 1; off < 512; off <<= 1) {
        int x = (t >= off) ? sh[t - off] : 0; __syncthreads();
        sh[t] += x; __syncthreads();
    }
    if (t < NSCH) g_part[t] = sh[t] - v;
    if (t == 511) g_rowptr[N_NODES] = sh[511];
}

__global__ void scanC_kernel() {
    int i = blockIdx.x * blockDim.x + threadIdx.x;
    if (i >= N_NODES) return;
    int excl = g_cursor[i] - (g_deg[i] + 1) + g_part[i / SCHUNK];
    g_rowptr[i] = excl;
    g_cursor[i] = excl;
}

__global__ void fill_kernel(const int* __restrict__ ei) {
    int e = blockIdx.x * blockDim.x + threadIdx.x;
    if (e >= N_TOT) return;
    int s, d;
    if (e < N_EDGES) { s = ei[e]; d = ei[N_EDGES + e]; }
    else             { s = d = e - N_EDGES; }
    int p = atomicAdd(&g_cursor[d], 1);
    g_col[p] = s;
}

// ---------------- bf16 split helpers ----------------
__device__ __forceinline__ void split_bf16(float x, __nv_bfloat16& h, __nv_bfloat16& l) {
    h = __float2bfloat16(x);
    l = __float2bfloat16(x - __bfloat162float(h));
}

// ---------------- input conversion ----------------
__global__ void convx_kernel(const float* __restrict__ x) {
    int i = blockIdx.x * blockDim.x + threadIdx.x;
    float4 v = ((const float4*)x)[i];
    __nv_bfloat16 h0,l0,h1,l1,h2,l2,h3,l3;
    split_bf16(v.x,h0,l0); split_bf16(v.y,h1,l1);
    split_bf16(v.z,h2,l2); split_bf16(v.w,h3,l3);
    __nv_bfloat162 a; a.x=h0; a.y=h1;
    __nv_bfloat162 b; b.x=h2; b.y=h3;
    __nv_bfloat162 c; c.x=l0; c.y=l1;
    __nv_bfloat162 d; d.x=l2; d.y=l3;
    ((__nv_bfloat162*)g_hiA)[i*2]   = a;
    ((__nv_bfloat162*)g_hiA)[i*2+1] = b;
    ((__nv_bfloat162*)g_loA)[i*2]   = c;
    ((__nv_bfloat162*)g_loA)[i*2+1] = d;
}

// ---------------- weight prep: fast bias fold ----------------
__global__ void prep_kernel(const float* __restrict__ bnp, const float* __restrict__ W,
                            const float* __restrict__ extra, int layer) {
    int b = blockIdx.x;
    if (b < 64) {
        int i = b * 256 + threadIdx.x;
        int k = i >> 7, n = i & 127;
        float s = bnp[k] * rsqrtf(bnp[384 + k] + BN_EPS);
        float w = s * W[i];
        __nv_bfloat16 h, l;
        split_bf16(w, h, l);
        g_wthi[layer][n * 128 + k] = h;
        g_wtlo[layer][n * 128 + k] = l;
    } else {
        __shared__ float cs[128];
        __shared__ float part[256];
        int t = threadIdx.x;
        if (t < 128) {
            float s = bnp[t] * rsqrtf(bnp[384 + t] + BN_EPS);
            cs[t] = bnp[128 + t] - s * bnp[256 + t];
        }
        __syncthreads();
        int j = t & 127, half = t >> 7;
        float acc = 0.f;
        int k0 = half * 64;
#pragma unroll 8
        for (int k = k0; k < k0 + 64; k++) acc += cs[k] * W[k * HIDDIM + j];
        part[t] = acc;
        __syncthreads();
        if (t < 128) g_bpv[layer][j] = part[j] + part[j + 128] + (extra ? extra[j] : 0.f);
    }
}

// ---------------- cp.async helpers ----------------
__device__ __forceinline__ void cpa16(void* sdst, const void* gsrc, int srcbytes) {
    uint32_t s = (uint32_t)__cvta_generic_to_shared(sdst);
    asm volatile("cp.async.ca.shared.global [%0], [%1], 16, %2;"
                 :: "r"(s), "l"(gsrc), "r"(srcbytes));
}
__device__ __forceinline__ void cpa_commit() {
    asm volatile("cp.async.commit_group;");
}

__device__ __forceinline__ void mma16816(float c[4], uint32_t a0, uint32_t a1,
                                         uint32_t a2, uint32_t a3,
                                         uint32_t b0, uint32_t b1) {
    asm volatile(
        "mma.sync.aligned.m16n8k16.row.col.f32.bf16.bf16.f32 "
        "{%0,%1,%2,%3}, {%4,%5,%6,%7}, {%8,%9}, {%0,%1,%2,%3};"
        : "+f"(c[0]), "+f"(c[1]), "+f"(c[2]), "+f"(c[3])
        : "r"(a0), "r"(a1), "r"(a2), "r"(a3), "r"(b0), "r"(b1));
}

// ---------------- tensor-core GEMM: k-major 3-term split, cp.async pipeline ----------------
#define SMS   40
#define BUFE  (128 * SMS)
__global__ void __launch_bounds__(256)
mma_gemm_kernel(const __nv_bfloat16* __restrict__ Ahi,
                const __nv_bfloat16* __restrict__ Alo,
                const __nv_bfloat16* __restrict__ Bhg,
                const __nv_bfloat16* __restrict__ Blg,
                const float* __restrict__ bp,
                __half* __restrict__ Cm,
                __nv_bfloat16* __restrict__ Ohi,
                __nv_bfloat16* __restrict__ Olo,
                const float* __restrict__ att_s,
                const float* __restrict__ att_d,
                unsigned* __restrict__ asmax,
                int do_relu) {
    extern __shared__ __nv_bfloat16 dsm[];
    __nv_bfloat16* sAhi = dsm;
    __nv_bfloat16* sAlo = dsm + 2 * BUFE;
    __nv_bfloat16* sBhi = dsm + 4 * BUFE;
    __nv_bfloat16* sBlo = dsm + 6 * BUFE;
    __shared__ unsigned smax[NHEADS];

    int tid = threadIdx.x;
    int wid = tid >> 5, lane = tid & 31;
    int g = lane >> 2, tc = lane & 3;
    int wr = (wid & 3) * 32, wc = (wid >> 2) * 64;
    int row0 = blockIdx.x * 128;

    if (tid < NHEADS) smax[tid] = 0u;

    float c[2][8][4];
#pragma unroll
    for (int a = 0; a < 2; a++)
#pragma unroll
        for (int b = 0; b < 8; b++)
#pragma unroll
            for (int q = 0; q < 4; q++) c[a][b][q] = 0.f;

    int lr = tid >> 1, half = tid & 1;
    int gr = row0 + lr;
    int vb = (gr < N_NODES) ? 16 : 0;
    size_t abase = (size_t)(gr < N_NODES ? gr : 0) * 128 + half * 16;
    int bbase = lr * 128 + half * 16;
    int soff = lr * SMS + half * 16;

    auto issue = [&](int k, int buf) {
        int k0 = k * 32;
        cpa16(sAhi + buf * BUFE + soff,     Ahi + abase + k0,     vb);
        cpa16(sAhi + buf * BUFE + soff + 8, Ahi + abase + k0 + 8, vb);
        cpa16(sAlo + buf * BUFE + soff,     Alo + abase + k0,     vb);
        cpa16(sAlo + buf * BUFE + soff + 8, Alo + abase + k0 + 8, vb);
        cpa16(sBhi + buf * BUFE + soff,     Bhg + bbase + k0,     16);
        cpa16(sBhi + buf * BUFE + soff + 8, Bhg + bbase + k0 + 8, 16);
        cpa16(sBlo + buf * BUFE + soff,     Blg + bbase + k0,     16);
        cpa16(sBlo + buf * BUFE + soff + 8, Blg + bbase + k0 + 8, 16);
        cpa_commit();
    };

    issue(0, 0);
    for (int k = 0; k < 4; k++) {
        int cur = k & 1;
        if (k < 3) {
            issue(k + 1, cur ^ 1);
            asm volatile("cp.async.wait_group 1;");
        } else {
            asm volatile("cp.async.wait_group 0;");
        }
        __syncthreads();

        const __nv_bfloat16* Ah = sAhi + cur * BUFE;
        const __nv_bfloat16* Al = sAlo + cur * BUFE;
        const __nv_bfloat16* Bh = sBhi + cur * BUFE;
        const __nv_bfloat16* Bl = sBlo + cur * BUFE;
#pragma unroll
        for (int s = 0; s < 2; s++) {
            int kb = s * 16;
            uint32_t ah[2][4];
#pragma unroll
            for (int mf = 0; mf < 2; mf++) {
                int m = wr + mf * 16 + g;
                ah[mf][0] = *(const uint32_t*)(Ah + m * SMS + kb + tc * 2);
                ah[mf][1] = *(const uint32_t*)(Ah + (m + 8) * SMS + kb + tc * 2);
                ah[mf][2] = *(const uint32_t*)(Ah + m * SMS + kb + tc * 2 + 8);
                ah[mf][3] = *(const uint32_t*)(Ah + (m + 8) * SMS + kb + tc * 2 + 8);
            }
            uint32_t bh[8][2];
#pragma unroll
            for (int nf = 0; nf < 8; nf++) {
                int n = wc + nf * 8 + g;
                bh[nf][0] = *(const uint32_t*)(Bh + n * SMS + kb + tc * 2);
                bh[nf][1] = *(const uint32_t*)(Bh + n * SMS + kb + tc * 2 + 8);
            }
#pragma unroll
            for (int mf = 0; mf < 2; mf++)
#pragma unroll
                for (int nf = 0; nf < 8; nf++)
                    mma16816(c[mf][nf], ah[mf][0], ah[mf][1], ah[mf][2], ah[mf][3],
                             bh[nf][0], bh[nf][1]);
            {
                uint32_t bl[8][2];
#pragma unroll
                for (int nf = 0; nf < 8; nf++) {
                    int n = wc + nf * 8 + g;
                    bl[nf][0] = *(const uint32_t*)(Bl + n * SMS + kb + tc * 2);
                    bl[nf][1] = *(const uint32_t*)(Bl + n * SMS + kb + tc * 2 + 8);
                }
#pragma unroll
                for (int mf = 0; mf < 2; mf++)
#pragma unroll
                    for (int nf = 0; nf < 8; nf++)
                        mma16816(c[mf][nf], ah[mf][0], ah[mf][1], ah[mf][2], ah[mf][3],
                                 bl[nf][0], bl[nf][1]);
            }
            uint32_t al[2][4];
#pragma unroll
            for (int mf = 0; mf < 2; mf++) {
                int m = wr + mf * 16 + g;
                al[mf][0] = *(const uint32_t*)(Al + m * SMS + kb + tc * 2);
                al[mf][1] = *(const uint32_t*)(Al + (m + 8) * SMS + kb + tc * 2);
                al[mf][2] = *(const uint32_t*)(Al + m * SMS + kb + tc * 2 + 8);
                al[mf][3] = *(const uint32_t*)(Al + (m + 8) * SMS + kb + tc * 2 + 8);
            }
#pragma unroll
            for (int mf = 0; mf < 2; mf++)
#pragma unroll
                for (int nf = 0; nf < 8; nf++)
                    mma16816(c[mf][nf], al[mf][0], al[mf][1], al[mf][2], al[mf][3],
                             bh[nf][0], bh[nf][1]);
        }
        __syncthreads();
    }

    // epilogue
#pragma unroll
    for (int mf = 0; mf < 2; mf++) {
        int r0 = row0 + wr + mf * 16 + g;
        int r1 = r0 + 8;
        float ps0[4] = {0,0,0,0}, pd0[4] = {0,0,0,0};
        float ps1[4] = {0,0,0,0}, pd1[4] = {0,0,0,0};
#pragma unroll
        for (int nf = 0; nf < 8; nf++) {
            int cc = wc + nf * 8 + tc * 2;
            float b0 = bp[cc], b1 = bp[cc + 1];
            float v00 = c[mf][nf][0] + b0, v01 = c[mf][nf][1] + b1;
            float v10 = c[mf][nf][2] + b0, v11 = c[mf][nf][3] + b1;
            if (do_relu) {
                v00 = fmaxf(v00, 0.f); v01 = fmaxf(v01, 0.f);
                v10 = fmaxf(v10, 0.f); v11 = fmaxf(v11, 0.f);
            }
            if (att_s) {
                int hl = nf >> 1;
                float as0 = att_s[cc], as1 = att_s[cc + 1];
                float ad0 = att_d[cc], ad1 = att_d[cc + 1];
                ps0[hl] += v00 * as0 + v01 * as1;
                pd0[hl] += v00 * ad0 + v01 * ad1;
                ps1[hl] += v10 * as0 + v11 * as1;
                pd1[hl] += v10 * ad0 + v11 * ad1;
            }
            if (Cm) {
                if (r0 < N_NODES)
                    *(__half2*)(Cm + (size_t)r0 * 128 + cc) = __floats2half2_rn(v00, v01);
                if (r1 < N_NODES)
                    *(__half2*)(Cm + (size_t)r1 * 128 + cc) = __floats2half2_rn(v10, v11);
            }
            if (Ohi) {
                __nv_bfloat16 h0, l0, h1, l1;
                if (r0 < N_NODES) {
                    split_bf16(v00, h0, l0); split_bf16(v01, h1, l1);
                    __nv_bfloat162 th; th.x = h0; th.y = h1;
                    __nv_bfloat162 tl; tl.x = l0; tl.y = l1;
                    *(__nv_bfloat162*)(Ohi + (size_t)r0 * 128 + cc) = th;
                    *(__nv_bfloat162*)(Olo + (size_t)r0 * 128 + cc) = tl;
                }
                if (r1 < N_NODES) {
                    split_bf16(v10, h0, l0); split_bf16(v11, h1, l1);
                    __nv_bfloat162 th; th.x = h0; th.y = h1;
                    __nv_bfloat162 tl; tl.x = l0; tl.y = l1;
                    *(__nv_bfloat162*)(Ohi + (size_t)r1 * 128 + cc) = th;
                    *(__nv_bfloat162*)(Olo + (size_t)r1 * 128 + cc) = tl;
                }
            }
        }
        if (att_s) {
#pragma unroll
            for (int h = 0; h < 4; h++) {
                ps0[h] += __shfl_xor_sync(0xffffffffu, ps0[h], 1);
                ps0[h] += __shfl_xor_sync(0xffffffffu, ps0[h], 2);
                pd0[h] += __shfl_xor_sync(0xffffffffu, pd0[h], 1);
                pd0[h] += __shfl_xor_sync(0xffffffffu, pd0[h], 2);
                ps1[h] += __shfl_xor_sync(0xffffffffu, ps1[h], 1);
                ps1[h] += __shfl_xor_sync(0xffffffffu, ps1[h], 2);
                pd1[h] += __shfl_xor_sync(0xffffffffu, pd1[h], 1);
                pd1[h] += __shfl_xor_sync(0xffffffffu, pd1[h], 2);
            }
            if (tc == 0) {
                int hb = wc >> 4;
                if (r0 < N_NODES) {
#pragma unroll
                    for (int h = 0; h < 4; h++) {
                        g_as[r0 * 8 + hb + h] = ps0[h];
                        g_ad[r0 * 8 + hb + h] = pd0[h];
                        atomicMax(&smax[hb + h], fenc(ps0[h]));
                    }
                }
                if (r1 < N_NODES) {
#pragma unroll
                    for (int h = 0; h < 4; h++) {
                        g_as[r1 * 8 + hb + h] = ps1[h];
                        g_ad[r1 * 8 + hb + h] = pd1[h];
                        atomicMax(&smax[hb + h], fenc(ps1[h]));
                    }
                }
            }
        }
    }
    if (att_s) {
        __syncthreads();
        if (tid < NHEADS) atomicMax(&asmax[tid], smax[tid]);
    }
}

// ---------------- GAT gather: bound-based softmax (no rescale chain) ----------------
__global__ void gather_kernel(const float* __restrict__ bias,
                              const unsigned* __restrict__ asmax,
                              float* __restrict__ outF,
                              __nv_bfloat16* __restrict__ Ohi,
                              __nv_bfloat16* __restrict__ Olo) {
    int node = (blockIdx.x * blockDim.x + threadIdx.x) >> 4;
    if (node >= N_NODES) return;
    int l16 = threadIdx.x & 15;      // 16 lanes per node, 8 cols each
    int head = l16 >> 1;
    int beg = g_rowptr[node];
    int end = g_rowptr[node + 1];

    float adh = g_ad[node * 8 + head];
    // upper bound on all logits of this node (leaky_relu is monotone)
    float bnd = fdec(asmax[head]) + adh;
    bnd = bnd > 0.f ? bnd : SLOPE * bnd;

    float s = 0.f;
    float a0 = 0.f, a1 = 0.f, a2 = 0.f, a3 = 0.f;
    float a4 = 0.f, a5 = 0.f, a6 = 0.f, a7 = 0.f;

#pragma unroll 2
    for (int e = beg; e < end; e++) {
        int src = g_col[e];
        float l = __ldg(g_as + src * 8 + head) + adh;
        l = l > 0.f ? l : SLOPE * l;
        float w = __expf(l - bnd);
        uint4 raw = *(const uint4*)(g_hm + (size_t)src * 128 + l16 * 8);   // 8 fp16
        __half2* ph = (__half2*)&raw;
        float2 f0 = __half22float2(ph[0]);
        float2 f1 = __half22float2(ph[1]);
        float2 f2 = __half22float2(ph[2]);
        float2 f3 = __half22float2(ph[3]);
        s  += w;
        a0 += w * f0.x; a1 += w * f0.y;
        a2 += w * f1.x; a3 += w * f1.y;
        a4 += w * f2.x; a5 += w * f2.y;
        a6 += w * f3.x; a7 += w * f3.y;
    }
    float inv = 1.f / (s + 1e-16f);
    float4 b0 = ((const float4*)bias)[l16 * 2];
    float4 b1 = ((const float4*)bias)[l16 * 2 + 1];
    float4 o0, o1;
    o0.x = fmaxf(a0 * inv + b0.x, 0.f);
    o0.y = fmaxf(a1 * inv + b0.y, 0.f);
    o0.z = fmaxf(a2 * inv + b0.z, 0.f);
    o0.w = fmaxf(a3 * inv + b0.w, 0.f);
    o1.x = fmaxf(a4 * inv + b1.x, 0.f);
    o1.y = fmaxf(a5 * inv + b1.y, 0.f);
    o1.z = fmaxf(a6 * inv + b1.z, 0.f);
    o1.w = fmaxf(a7 * inv + b1.w, 0.f);

    if (outF) {
        ((float4*)(outF + (size_t)node * 128))[l16 * 2]     = o0;
        ((float4*)(outF + (size_t)node * 128))[l16 * 2 + 1] = o1;
    }
    if (Ohi) {
        __nv_bfloat16 hv[8], lv[8];
        split_bf16(o0.x, hv[0], lv[0]); split_bf16(o0.y, hv[1], lv[1]);
        split_bf16(o0.z, hv[2], lv[2]); split_bf16(o0.w, hv[3], lv[3]);
        split_bf16(o1.x, hv[4], lv[4]); split_bf16(o1.y, hv[5], lv[5]);
        split_bf16(o1.z, hv[6], lv[6]); split_bf16(o1.w, hv[7], lv[7]);
        *(uint4*)(Ohi + (size_t)node * 128 + l16 * 8) = *(const uint4*)hv;
        *(uint4*)(Olo + (size_t)node * 128 + l16 * 8) = *(const uint4*)lv;
    }
}

// ---------------- pooling ----------------
__global__ void pool_kernel(const int* __restrict__ batch) {
    int b = blockIdx.x, c = threadIdx.x;
    int r0 = b * SCHUNK, r1 = min(r0 + SCHUNK, N_NODES);
    float acc = 0.f;
    int cur = batch[r0];
    for (int r = r0; r < r1; r++) {
        int gb = batch[r];
        if (gb != cur) { atomicAdd(&g_pool[cur * 128 + c], acc); acc = 0.f; cur = gb; }
        acc += g_h[(size_t)r * 128 + c];
    }
    atomicAdd(&g_pool[cur * 128 + c], acc);
}

// ---------------- fused FC + classifier + log_softmax ----------------
__global__ void fccls_kernel(const float* __restrict__ bnfc, const float* __restrict__ fcW,
                             const float* __restrict__ fcb,
                             const float* __restrict__ bnh, const float* __restrict__ Wc,
                             const float* __restrict__ bc, float* __restrict__ out) {
    __shared__ float sh[128];
    __shared__ float sh2[128];
    __shared__ float lg[NCLASS];
    __shared__ float s_mx, s_ls;
    int g = blockIdx.x, t = threadIdx.x;
    float x = g_pool[g * 128 + t];
    float s = bnfc[t] * rsqrtf(bnfc[384 + t] + BN_EPS);
    sh[t] = s * (x - bnfc[256 + t]) + bnfc[128 + t];
    __syncthreads();
    float acc = fcb[t];
    for (int k = 0; k < 128; k++) acc += sh[k] * fcW[k * 128 + t];
    float fo = fmaxf(acc, 0.f);
    float s2 = bnh[t] * rsqrtf(bnh[384 + t] + BN_EPS);
    sh2[t] = s2 * (fo - bnh[256 + t]) + bnh[128 + t];
    __syncthreads();
    if (t < NCLASS) {
        float a2 = bc[t];
        for (int k = 0; k < 128; k++) a2 += sh2[k] * Wc[k * NCLASS + t];
        lg[t] = a2;
    }
    __syncthreads();
    if (t == 0) {
        float mx = lg[0];
        for (int j = 1; j < NCLASS; j++) mx = fmaxf(mx, lg[j]);
        float se = 0.f;
        for (int j = 0; j < NCLASS; j++) se += expf(lg[j] - mx);
        s_mx = mx; s_ls = logf(se);
    }
    __syncthreads();
    if (t < NCLASS) out[g * NCLASS + t] = lg[t] - s_mx - s_ls;
}

// ---------------- launch ----------------
extern "C" void kernel_launch(void* const* d_in, const int* in_sizes, int n_in,
                              void* d_out, int out_size) {
    const float* x        = (const float*)d_in[0];
    const int*   ei       = (const int*)d_in[1];
    const int*   batch    = (const int*)d_in[2];
    const float* bn_feat  = (const float*)d_in[3];
    const float* w_feat   = (const float*)d_in[4];
    const float* b_feat   = (const float*)d_in[5];
    const float* bns_conv = (const float*)d_in[6];
    const float* gat_w    = (const float*)d_in[7];
    const float* att_s    = (const float*)d_in[8];
    const float* att_d    = (const float*)d_in[9];
    const float* gat_b    = (const float*)d_in[10];
    const float* bns_fc   = (const float*)d_in[11];
    const float* fc_w     = (const float*)d_in[12];
    const float* fc_b     = (const float*)d_in[13];
    const float* bn_hid   = (const float*)d_in[14];
    const float* w_cls    = (const float*)d_in[15];
    const float* b_cls    = (const float*)d_in[16];
    float* out = (float*)d_out;

    float *p_h = nullptr, *p_pool = nullptr, *p_bp = nullptr;
    __half* p_hm = nullptr;
    int* p_deg = nullptr;
    unsigned* p_asmax = nullptr;
    __nv_bfloat16 *p_hiA = nullptr, *p_loA = nullptr, *p_hiB = nullptr, *p_loB = nullptr;
    __nv_bfloat16 *p_wthi = nullptr, *p_wtlo = nullptr;
    cudaGetSymbolAddress((void**)&p_h,    g_h);
    cudaGetSymbolAddress((void**)&p_hm,   g_hm);
    cudaGetSymbolAddress((void**)&p_pool, g_pool);
    cudaGetSymbolAddress((void**)&p_deg,  g_deg);
    cudaGetSymbolAddress((void**)&p_asmax, g_asmax);
    cudaGetSymbolAddress((void**)&p_hiA,  g_hiA);
    cudaGetSymbolAddress((void**)&p_loA,  g_loA);
    cudaGetSymbolAddress((void**)&p_hiB,  g_hiB);
    cudaGetSymbolAddress((void**)&p_loB,  g_loB);
    cudaGetSymbolAddress((void**)&p_wthi, g_wthi);
    cudaGetSymbolAddress((void**)&p_wtlo, g_wtlo);
    cudaGetSymbolAddress((void**)&p_bp,   g_bpv);

    static cudaStream_t s2 = nullptr;
    static cudaEvent_t e0 = nullptr, e1 = nullptr, e2 = nullptr, e3 = nullptr;
    if (!s2) {
        cudaStreamCreateWithFlags(&s2, cudaStreamNonBlocking);
        cudaEventCreateWithFlags(&e0, cudaEventDisableTiming);
        cudaEventCreateWithFlags(&e1, cudaEventDisableTiming);
        cudaEventCreateWithFlags(&e2, cudaEventDisableTiming);
        cudaEventCreateWithFlags(&e3, cudaEventDisableTiming);
        cudaFuncSetAttribute(mma_gemm_kernel,
                             cudaFuncAttributeMaxDynamicSharedMemorySize, 8 * BUFE * 2);
    }

    const int GEMM_GRID = (N_NODES + 127) / 128;
    const int GEMM_SMEM = 8 * BUFE * 2;

    cudaEventRecord(e0, 0);
    cudaStreamWaitEvent(s2, e0, 0);

    // legacy: convx; s2: asmax reset + prep0 concurrently
    convx_kernel<<<(N_NODES * HIDDIM / 4 + 255) / 256, 256>>>(x);
    cudaMemsetAsync(p_asmax, 0, 3 * NHEADS * sizeof(unsigned), s2);
    prep_kernel<<<65, 256, 0, s2>>>(bn_feat, w_feat, b_feat, 0);
    cudaEventRecord(e3, s2);
    cudaMemsetAsync(p_deg, 0, N_NODES * sizeof(int), s2);
    for (int i = 0; i < 3; i++)
        prep_kernel<<<65, 256, 0, s2>>>(bns_conv + i * 512, gat_w + i * 16384,
                                        (const float*)nullptr, i + 1);
    cudaEventRecord(e2, s2);
    count_kernel<<<(N_EDGES + 255) / 256, 256, 0, s2>>>(ei);
    scanA_kernel<<<NSCH, SCHUNK, 0, s2>>>();
    scanB_kernel<<<1, 512, 0, s2>>>();
    scanC_kernel<<<(N_NODES + 255) / 256, 256, 0, s2>>>();
    fill_kernel <<<(N_TOT + 255) / 256, 256, 0, s2>>>(ei);
    cudaMemsetAsync(p_pool, 0, NGROUP * HIDDIM * sizeof(float), s2);
    cudaEventRecord(e1, s2);

    cudaStreamWaitEvent(0, e3, 0);   // prep0 + asmax reset ready
    // feature GEMM (layer 0)
    mma_gemm_kernel<<<GEMM_GRID, 256, GEMM_SMEM>>>(p_hiA, p_loA,
                                                   p_wthi, p_wtlo, p_bp,
                                                   (__half*)nullptr, p_hiB, p_loB,
                                                   (const float*)nullptr,
                                                   (const float*)nullptr,
                                                   (unsigned*)nullptr, 1);
    cudaStreamWaitEvent(0, e2, 0);   // conv weights ready

    __nv_bfloat16* inhi[3] = {p_hiB, p_hiA, p_hiB};
    __nv_bfloat16* inlo[3] = {p_loB, p_loA, p_loB};
    __nv_bfloat16* othi[3] = {p_hiA, p_hiB, (__nv_bfloat16*)nullptr};
    __nv_bfloat16* otlo[3] = {p_loA, p_loB, (__nv_bfloat16*)nullptr};

    // conv0 GEMM
    mma_gemm_kernel<<<GEMM_GRID, 256, GEMM_SMEM>>>(inhi[0], inlo[0],
                                                   p_wthi + 16384, p_wtlo + 16384, p_bp + 128,
                                                   p_hm,
                                                   (__nv_bfloat16*)nullptr, (__nv_bfloat16*)nullptr,
                                                   att_s, att_d, p_asmax, 0);
    cudaStreamWaitEvent(0, e1, 0);   // CSR + pool-memset ready

    for (int i = 0; i < 3; i++) {
        if (i > 0) {
            mma_gemm_kernel<<<GEMM_GRID, 256, GEMM_SMEM>>>(inhi[i], inlo[i],
                                                           p_wthi + (i + 1) * 16384,
                                                           p_wtlo + (i + 1) * 16384,
                                                           p_bp + (i + 1) * 128,
                                                           p_hm,
                                                           (__nv_bfloat16*)nullptr, (__nv_bfloat16*)nullptr,
                                                           att_s + i * 128, att_d + i * 128,
                                                           p_asmax + i * NHEADS, 0);
        }
        gather_kernel<<<(N_NODES * 16 + 255) / 256, 256>>>(gat_b + i * 128,
                                            p_asmax + i * NHEADS,
                                            (i == 2) ? p_h : (float*)nullptr,
                                            othi[i], otlo[i]);
    }

    pool_kernel <<<NSCH, 128>>>(batch);
    fccls_kernel<<<NGROUP, 128>>>(bns_fc, fc_w, fc_b, bn_hid, w_cls, b_cls, out);
}

// round 12
// speedup vs baseline: 1.6060x; 1.0819x over previous
#include <cuda_runtime.h>
#include <cuda_bf16.h>
#include <cuda_fp16.h>
#include <stdint.h>
#include <math.h>

#define N_NODES 50000
#define N_EDGES 800000
#define N_TOT   (N_EDGES + N_NODES)
#define HIDDIM  128
#define NHEADS  8
#define NGROUP  64
#define NCLASS  10
#define BN_EPS  1e-5f
#define SLOPE   0.2f
#define SCHUNK  128
#define NSCH    ((N_NODES + SCHUNK - 1) / SCHUNK)

// ---------------- device scratch ----------------
static __device__ float g_h   [N_NODES * HIDDIM];
static __device__ __align__(16) __half g_hm [N_NODES * HIDDIM];   // fp16 messages
static __device__ __align__(16) __nv_bfloat16 g_hiA[N_NODES * HIDDIM];
static __device__ __align__(16) __nv_bfloat16 g_hiB[N_NODES * HIDDIM];
static __device__ __align__(16) __nv_bfloat16 g_wthi[4][HIDDIM * HIDDIM];
static __device__ __align__(16) __nv_bfloat16 g_wtlo[4][HIDDIM * HIDDIM];
static __device__ float g_bpv [4][HIDDIM];
static __device__ float g_as  [N_NODES * NHEADS];
static __device__ float g_ad  [N_NODES * NHEADS];
static __device__ unsigned g_asmax[3][NHEADS];
static __device__ int   g_rowptr[N_NODES + 1];
static __device__ int   g_cursor[N_NODES];
static __device__ int   g_deg   [N_NODES];
static __device__ int   g_part  [512];
static __device__ int   g_col   [N_TOT];
static __device__ float g_pool [NGROUP * HIDDIM];

// order-preserving float<->uint encoding for atomicMax
__device__ __forceinline__ unsigned fenc(float f) {
    unsigned u = __float_as_uint(f);
    return (u & 0x80000000u) ? ~u : (u | 0x80000000u);
}
__device__ __forceinline__ float fdec(unsigned e) {
    return (e & 0x80000000u) ? __uint_as_float(e ^ 0x80000000u) : __uint_as_float(~e);
}

// ---------------- CSR build ----------------
__global__ void count_kernel(const int* __restrict__ ei) {
    int e = blockIdx.x * blockDim.x + threadIdx.x;
    if (e < N_EDGES) atomicAdd(&g_deg[ei[N_EDGES + e]], 1);
}

__global__ void scanA_kernel() {
    __shared__ int sh[SCHUNK];
    int b = blockIdx.x, t = threadIdx.x;
    int i = b * SCHUNK + t;
    int v = (i < N_NODES) ? (g_deg[i] + 1) : 0;
    sh[t] = v; __syncthreads();
    for (int off = 1; off < SCHUNK; off <<= 1) {
        int x = (t >= off) ? sh[t - off] : 0; __syncthreads();
        sh[t] += x; __syncthreads();
    }
    if (i < N_NODES) g_cursor[i] = sh[t];
    if (t == SCHUNK - 1) g_part[b] = sh[t];
}

__global__ void scanB_kernel() {
    __shared__ int sh[512];
    int t = threadIdx.x;
    int v = (t < NSCH) ? g_part[t] : 0;
    sh[t] = v; __syncthreads();
    for (int off = 1; off < 512; off <<= 1) {
        int x = (t >= off) ? sh[t - off] : 0; __syncthreads();
        sh[t] += x; __syncthreads();
    }
    if (t < NSCH) g_part[t] = sh[t] - v;
    if (t == 511) g_rowptr[N_NODES] = sh[511];
}

__global__ void scanC_kernel() {
    int i = blockIdx.x * blockDim.x + threadIdx.x;
    if (i >= N_NODES) return;
    int excl = g_cursor[i] - (g_deg[i] + 1) + g_part[i / SCHUNK];
    g_rowptr[i] = excl;
    g_cursor[i] = excl;
}

__global__ void fill_kernel(const int* __restrict__ ei) {
    int e = blockIdx.x * blockDim.x + threadIdx.x;
    if (e >= N_TOT) return;
    int s, d;
    if (e < N_EDGES) { s = ei[e]; d = ei[N_EDGES + e]; }
    else             { s = d = e - N_EDGES; }
    int p = atomicAdd(&g_cursor[d], 1);
    g_col[p] = s;
}

// ---------------- bf16 split helpers ----------------
__device__ __forceinline__ void split_bf16(float x, __nv_bfloat16& h, __nv_bfloat16& l) {
    h = __float2bfloat16(x);
    l = __float2bfloat16(x - __bfloat162float(h));
}

// ---------------- input conversion (hi only) ----------------
__global__ void convx_kernel(const float* __restrict__ x) {
    int i = blockIdx.x * blockDim.x + threadIdx.x;
    float4 v = ((const float4*)x)[i];
    __nv_bfloat162 a; a.x = __float2bfloat16(v.x); a.y = __float2bfloat16(v.y);
    __nv_bfloat162 b; b.x = __float2bfloat16(v.z); b.y = __float2bfloat16(v.w);
    ((__nv_bfloat162*)g_hiA)[i*2]   = a;
    ((__nv_bfloat162*)g_hiA)[i*2+1] = b;
}

// ---------------- weight prep: fast bias fold ----------------
__global__ void prep_kernel(const float* __restrict__ bnp, const float* __restrict__ W,
                            const float* __restrict__ extra, int layer) {
    int b = blockIdx.x;
    if (b < 64) {
        int i = b * 256 + threadIdx.x;
        int k = i >> 7, n = i & 127;
        float s = bnp[k] * rsqrtf(bnp[384 + k] + BN_EPS);
        float w = s * W[i];
        __nv_bfloat16 h, l;
        split_bf16(w, h, l);
        g_wthi[layer][n * 128 + k] = h;
        g_wtlo[layer][n * 128 + k] = l;
    } else {
        __shared__ float cs[128];
        __shared__ float part[256];
        int t = threadIdx.x;
        if (t < 128) {
            float s = bnp[t] * rsqrtf(bnp[384 + t] + BN_EPS);
            cs[t] = bnp[128 + t] - s * bnp[256 + t];
        }
        __syncthreads();
        int j = t & 127, half = t >> 7;
        float acc = 0.f;
        int k0 = half * 64;
#pragma unroll 8
        for (int k = k0; k < k0 + 64; k++) acc += cs[k] * W[k * HIDDIM + j];
        part[t] = acc;
        __syncthreads();
        if (t < 128) g_bpv[layer][j] = part[j] + part[j + 128] + (extra ? extra[j] : 0.f);
    }
}

// ---------------- cp.async helpers ----------------
__device__ __forceinline__ void cpa16(void* sdst, const void* gsrc, int srcbytes) {
    uint32_t s = (uint32_t)__cvta_generic_to_shared(sdst);
    asm volatile("cp.async.ca.shared.global [%0], [%1], 16, %2;"
                 :: "r"(s), "l"(gsrc), "r"(srcbytes));
}
__device__ __forceinline__ void cpa_commit() {
    asm volatile("cp.async.commit_group;");
}

__device__ __forceinline__ void mma16816(float c[4], uint32_t a0, uint32_t a1,
                                         uint32_t a2, uint32_t a3,
                                         uint32_t b0, uint32_t b1) {
    asm volatile(
        "mma.sync.aligned.m16n8k16.row.col.f32.bf16.bf16.f32 "
        "{%0,%1,%2,%3}, {%4,%5,%6,%7}, {%8,%9}, {%0,%1,%2,%3};"
        : "+f"(c[0]), "+f"(c[1]), "+f"(c[2]), "+f"(c[3])
        : "r"(a0), "r"(a1), "r"(a2), "r"(a3), "r"(b0), "r"(b1));
}

// ---------------- tensor-core GEMM: 2-term split (Ah*(Bh+Bl)), cp.async pipeline ----------------
#define SMS   40
#define BUFE  (128 * SMS)
__global__ void __launch_bounds__(256)
mma_gemm_kernel(const __nv_bfloat16* __restrict__ Ahi,
                const __nv_bfloat16* __restrict__ Bhg,
                const __nv_bfloat16* __restrict__ Blg,
                const float* __restrict__ bp,
                __half* __restrict__ Cm,
                __nv_bfloat16* __restrict__ Ohi,
                const float* __restrict__ att_s,
                const float* __restrict__ att_d,
                unsigned* __restrict__ asmax,
                int do_relu) {
    extern __shared__ __nv_bfloat16 dsm[];
    __nv_bfloat16* sAhi = dsm;              // [2][BUFE]
    __nv_bfloat16* sBhi = dsm + 2 * BUFE;
    __nv_bfloat16* sBlo = dsm + 4 * BUFE;
    __shared__ unsigned smax[NHEADS];

    int tid = threadIdx.x;
    int wid = tid >> 5, lane = tid & 31;
    int g = lane >> 2, tc = lane & 3;
    int wr = (wid & 3) * 32, wc = (wid >> 2) * 64;
    int row0 = blockIdx.x * 128;

    if (tid < NHEADS) smax[tid] = 0u;

    float c[2][8][4];
#pragma unroll
    for (int a = 0; a < 2; a++)
#pragma unroll
        for (int b = 0; b < 8; b++)
#pragma unroll
            for (int q = 0; q < 4; q++) c[a][b][q] = 0.f;

    int lr = tid >> 1, half = tid & 1;
    int gr = row0 + lr;
    int vb = (gr < N_NODES) ? 16 : 0;
    size_t abase = (size_t)(gr < N_NODES ? gr : 0) * 128 + half * 16;
    int bbase = lr * 128 + half * 16;
    int soff = lr * SMS + half * 16;

    auto issue = [&](int k, int buf) {
        int k0 = k * 32;
        cpa16(sAhi + buf * BUFE + soff,     Ahi + abase + k0,     vb);
        cpa16(sAhi + buf * BUFE + soff + 8, Ahi + abase + k0 + 8, vb);
        cpa16(sBhi + buf * BUFE + soff,     Bhg + bbase + k0,     16);
        cpa16(sBhi + buf * BUFE + soff + 8, Bhg + bbase + k0 + 8, 16);
        cpa16(sBlo + buf * BUFE + soff,     Blg + bbase + k0,     16);
        cpa16(sBlo + buf * BUFE + soff + 8, Blg + bbase + k0 + 8, 16);
        cpa_commit();
    };

    issue(0, 0);
    for (int k = 0; k < 4; k++) {
        int cur = k & 1;
        if (k < 3) {
            issue(k + 1, cur ^ 1);
            asm volatile("cp.async.wait_group 1;");
        } else {
            asm volatile("cp.async.wait_group 0;");
        }
        __syncthreads();

        const __nv_bfloat16* Ah = sAhi + cur * BUFE;
        const __nv_bfloat16* Bh = sBhi + cur * BUFE;
        const __nv_bfloat16* Bl = sBlo + cur * BUFE;
#pragma unroll
        for (int s = 0; s < 2; s++) {
            int kb = s * 16;
            uint32_t ah[2][4];
#pragma unroll
            for (int mf = 0; mf < 2; mf++) {
                int m = wr + mf * 16 + g;
                ah[mf][0] = *(const uint32_t*)(Ah + m * SMS + kb + tc * 2);
                ah[mf][1] = *(const uint32_t*)(Ah + (m + 8) * SMS + kb + tc * 2);
                ah[mf][2] = *(const uint32_t*)(Ah + m * SMS + kb + tc * 2 + 8);
                ah[mf][3] = *(const uint32_t*)(Ah + (m + 8) * SMS + kb + tc * 2 + 8);
            }
            uint32_t bh[8][2];
#pragma unroll
            for (int nf = 0; nf < 8; nf++) {
                int n = wc + nf * 8 + g;
                bh[nf][0] = *(const uint32_t*)(Bh + n * SMS + kb + tc * 2);
                bh[nf][1] = *(const uint32_t*)(Bh + n * SMS + kb + tc * 2 + 8);
            }
#pragma unroll
            for (int mf = 0; mf < 2; mf++)
#pragma unroll
                for (int nf = 0; nf < 8; nf++)
                    mma16816(c[mf][nf], ah[mf][0], ah[mf][1], ah[mf][2], ah[mf][3],
                             bh[nf][0], bh[nf][1]);
            uint32_t bl[8][2];
#pragma unroll
            for (int nf = 0; nf < 8; nf++) {
                int n = wc + nf * 8 + g;
                bl[nf][0] = *(const uint32_t*)(Bl + n * SMS + kb + tc * 2);
                bl[nf][1] = *(const uint32_t*)(Bl + n * SMS + kb + tc * 2 + 8);
            }
#pragma unroll
            for (int mf = 0; mf < 2; mf++)
#pragma unroll
                for (int nf = 0; nf < 8; nf++)
                    mma16816(c[mf][nf], ah[mf][0], ah[mf][1], ah[mf][2], ah[mf][3],
                             bl[nf][0], bl[nf][1]);
        }
        __syncthreads();
    }

    // epilogue
#pragma unroll
    for (int mf = 0; mf < 2; mf++) {
        int r0 = row0 + wr + mf * 16 + g;
        int r1 = r0 + 8;
        float ps0[4] = {0,0,0,0}, pd0[4] = {0,0,0,0};
        float ps1[4] = {0,0,0,0}, pd1[4] = {0,0,0,0};
#pragma unroll
        for (int nf = 0; nf < 8; nf++) {
            int cc = wc + nf * 8 + tc * 2;
            float b0 = bp[cc], b1 = bp[cc + 1];
            float v00 = c[mf][nf][0] + b0, v01 = c[mf][nf][1] + b1;
            float v10 = c[mf][nf][2] + b0, v11 = c[mf][nf][3] + b1;
            if (do_relu) {
                v00 = fmaxf(v00, 0.f); v01 = fmaxf(v01, 0.f);
                v10 = fmaxf(v10, 0.f); v11 = fmaxf(v11, 0.f);
            }
            if (att_s) {
                int hl = nf >> 1;
                float as0 = att_s[cc], as1 = att_s[cc + 1];
                float ad0 = att_d[cc], ad1 = att_d[cc + 1];
                ps0[hl] += v00 * as0 + v01 * as1;
                pd0[hl] += v00 * ad0 + v01 * ad1;
                ps1[hl] += v10 * as0 + v11 * as1;
                pd1[hl] += v10 * ad0 + v11 * ad1;
            }
            if (Cm) {
                if (r0 < N_NODES)
                    *(__half2*)(Cm + (size_t)r0 * 128 + cc) = __floats2half2_rn(v00, v01);
                if (r1 < N_NODES)
                    *(__half2*)(Cm + (size_t)r1 * 128 + cc) = __floats2half2_rn(v10, v11);
            }
            if (Ohi) {
                if (r0 < N_NODES) {
                    __nv_bfloat162 th;
                    th.x = __float2bfloat16(v00); th.y = __float2bfloat16(v01);
                    *(__nv_bfloat162*)(Ohi + (size_t)r0 * 128 + cc) = th;
                }
                if (r1 < N_NODES) {
                    __nv_bfloat162 th;
                    th.x = __float2bfloat16(v10); th.y = __float2bfloat16(v11);
                    *(__nv_bfloat162*)(Ohi + (size_t)r1 * 128 + cc) = th;
                }
            }
        }
        if (att_s) {
#pragma unroll
            for (int h = 0; h < 4; h++) {
                ps0[h] += __shfl_xor_sync(0xffffffffu, ps0[h], 1);
                ps0[h] += __shfl_xor_sync(0xffffffffu, ps0[h], 2);
                pd0[h] += __shfl_xor_sync(0xffffffffu, pd0[h], 1);
                pd0[h] += __shfl_xor_sync(0xffffffffu, pd0[h], 2);
                ps1[h] += __shfl_xor_sync(0xffffffffu, ps1[h], 1);
                ps1[h] += __shfl_xor_sync(0xffffffffu, ps1[h], 2);
                pd1[h] += __shfl_xor_sync(0xffffffffu, pd1[h], 1);
                pd1[h] += __shfl_xor_sync(0xffffffffu, pd1[h], 2);
            }
            if (tc == 0) {
                int hb = wc >> 4;
                if (r0 < N_NODES) {
#pragma unroll
                    for (int h = 0; h < 4; h++) {
                        g_as[r0 * 8 + hb + h] = ps0[h];
                        g_ad[r0 * 8 + hb + h] = pd0[h];
                        atomicMax(&smax[hb + h], fenc(ps0[h]));
                    }
                }
                if (r1 < N_NODES) {
#pragma unroll
                    for (int h = 0; h < 4; h++) {
                        g_as[r1 * 8 + hb + h] = ps1[h];
                        g_ad[r1 * 8 + hb + h] = pd1[h];
                        atomicMax(&smax[hb + h], fenc(ps1[h]));
                    }
                }
            }
        }
    }
    if (att_s) {
        __syncthreads();
        if (tid < NHEADS) atomicMax(&asmax[tid], smax[tid]);
    }
}

// ---------------- GAT gather: bound-based softmax, fp16 messages ----------------
__global__ void gather_kernel(const float* __restrict__ bias,
                              const unsigned* __restrict__ asmax,
                              float* __restrict__ outF,
                              __nv_bfloat16* __restrict__ Ohi) {
    int node = (blockIdx.x * blockDim.x + threadIdx.x) >> 4;
    if (node >= N_NODES) return;
    int l16 = threadIdx.x & 15;
    int head = l16 >> 1;
    int beg = g_rowptr[node];
    int end = g_rowptr[node + 1];

    float adh = g_ad[node * 8 + head];
    float bnd = fdec(asmax[head]) + adh;
    bnd = bnd > 0.f ? bnd : SLOPE * bnd;

    float s = 0.f;
    float a0 = 0.f, a1 = 0.f, a2 = 0.f, a3 = 0.f;
    float a4 = 0.f, a5 = 0.f, a6 = 0.f, a7 = 0.f;

#pragma unroll 2
    for (int e = beg; e < end; e++) {
        int src = g_col[e];
        float l = __ldg(g_as + src * 8 + head) + adh;
        l = l > 0.f ? l : SLOPE * l;
        float w = __expf(l - bnd);
        uint4 raw = *(const uint4*)(g_hm + (size_t)src * 128 + l16 * 8);
        __half2* ph = (__half2*)&raw;
        float2 f0 = __half22float2(ph[0]);
        float2 f1 = __half22float2(ph[1]);
        float2 f2 = __half22float2(ph[2]);
        float2 f3 = __half22float2(ph[3]);
        s  += w;
        a0 += w * f0.x; a1 += w * f0.y;
        a2 += w * f1.x; a3 += w * f1.y;
        a4 += w * f2.x; a5 += w * f2.y;
        a6 += w * f3.x; a7 += w * f3.y;
    }
    float inv = 1.f / (s + 1e-16f);
    float4 b0 = ((const float4*)bias)[l16 * 2];
    float4 b1 = ((const float4*)bias)[l16 * 2 + 1];
    float4 o0, o1;
    o0.x = fmaxf(a0 * inv + b0.x, 0.f);
    o0.y = fmaxf(a1 * inv + b0.y, 0.f);
    o0.z = fmaxf(a2 * inv + b0.z, 0.f);
    o0.w = fmaxf(a3 * inv + b0.w, 0.f);
    o1.x = fmaxf(a4 * inv + b1.x, 0.f);
    o1.y = fmaxf(a5 * inv + b1.y, 0.f);
    o1.z = fmaxf(a6 * inv + b1.z, 0.f);
    o1.w = fmaxf(a7 * inv + b1.w, 0.f);

    if (outF) {
        ((float4*)(outF + (size_t)node * 128))[l16 * 2]     = o0;
        ((float4*)(outF + (size_t)node * 128))[l16 * 2 + 1] = o1;
    }
    if (Ohi) {
        __nv_bfloat16 hv[8];
        hv[0] = __float2bfloat16(o0.x); hv[1] = __float2bfloat16(o0.y);
        hv[2] = __float2bfloat16(o0.z); hv[3] = __float2bfloat16(o0.w);
        hv[4] = __float2bfloat16(o1.x); hv[5] = __float2bfloat16(o1.y);
        hv[6] = __float2bfloat16(o1.z); hv[7] = __float2bfloat16(o1.w);
        *(uint4*)(Ohi + (size_t)node * 128 + l16 * 8) = *(const uint4*)hv;
    }
}

// ---------------- pooling ----------------
__global__ void pool_kernel(const int* __restrict__ batch) {
    int b = blockIdx.x, c = threadIdx.x;
    int r0 = b * SCHUNK, r1 = min(r0 + SCHUNK, N_NODES);
    float acc = 0.f;
    int cur = batch[r0];
    for (int r = r0; r < r1; r++) {
        int gb = batch[r];
        if (gb != cur) { atomicAdd(&g_pool[cur * 128 + c], acc); acc = 0.f; cur = gb; }
        acc += g_h[(size_t)r * 128 + c];
    }
    atomicAdd(&g_pool[cur * 128 + c], acc);
}

// ---------------- fused FC + classifier + log_softmax ----------------
__global__ void fccls_kernel(const float* __restrict__ bnfc, const float* __restrict__ fcW,
                             const float* __restrict__ fcb,
                             const float* __restrict__ bnh, const float* __restrict__ Wc,
                             const float* __restrict__ bc, float* __restrict__ out) {
    __shared__ float sh[128];
    __shared__ float sh2[128];
    __shared__ float lg[NCLASS];
    __shared__ float s_mx, s_ls;
    int g = blockIdx.x, t = threadIdx.x;
    float x = g_pool[g * 128 + t];
    float s = bnfc[t] * rsqrtf(bnfc[384 + t] + BN_EPS);
    sh[t] = s * (x - bnfc[256 + t]) + bnfc[128 + t];
    __syncthreads();
    float acc = fcb[t];
    for (int k = 0; k < 128; k++) acc += sh[k] * fcW[k * 128 + t];
    float fo = fmaxf(acc, 0.f);
    float s2 = bnh[t] * rsqrtf(bnh[384 + t] + BN_EPS);
    sh2[t] = s2 * (fo - bnh[256 + t]) + bnh[128 + t];
    __syncthreads();
    if (t < NCLASS) {
        float a2 = bc[t];
        for (int k = 0; k < 128; k++) a2 += sh2[k] * Wc[k * NCLASS + t];
        lg[t] = a2;
    }
    __syncthreads();
    if (t == 0) {
        float mx = lg[0];
        for (int j = 1; j < NCLASS; j++) mx = fmaxf(mx, lg[j]);
        float se = 0.f;
        for (int j = 0; j < NCLASS; j++) se += expf(lg[j] - mx);
        s_mx = mx; s_ls = logf(se);
    }
    __syncthreads();
    if (t < NCLASS) out[g * NCLASS + t] = lg[t] - s_mx - s_ls;
}

// ---------------- launch ----------------
extern "C" void kernel_launch(void* const* d_in, const int* in_sizes, int n_in,
                              void* d_out, int out_size) {
    const float* x        = (const float*)d_in[0];
    const int*   ei       = (const int*)d_in[1];
    const int*   batch    = (const int*)d_in[2];
    const float* bn_feat  = (const float*)d_in[3];
    const float* w_feat   = (const float*)d_in[4];
    const float* b_feat   = (const float*)d_in[5];
    const float* bns_conv = (const float*)d_in[6];
    const float* gat_w    = (const float*)d_in[7];
    const float* att_s    = (const float*)d_in[8];
    const float* att_d    = (const float*)d_in[9];
    const float* gat_b    = (const float*)d_in[10];
    const float* bns_fc   = (const float*)d_in[11];
    const float* fc_w     = (const float*)d_in[12];
    const float* fc_b     = (const float*)d_in[13];
    const float* bn_hid   = (const float*)d_in[14];
    const float* w_cls    = (const float*)d_in[15];
    const float* b_cls    = (const float*)d_in[16];
    float* out = (float*)d_out;

    float *p_h = nullptr, *p_pool = nullptr, *p_bp = nullptr;
    __half* p_hm = nullptr;
    int* p_deg = nullptr;
    unsigned* p_asmax = nullptr;
    __nv_bfloat16 *p_hiA = nullptr, *p_hiB = nullptr;
    __nv_bfloat16 *p_wthi = nullptr, *p_wtlo = nullptr;
    cudaGetSymbolAddress((void**)&p_h,    g_h);
    cudaGetSymbolAddress((void**)&p_hm,   g_hm);
    cudaGetSymbolAddress((void**)&p_pool, g_pool);
    cudaGetSymbolAddress((void**)&p_deg,  g_deg);
    cudaGetSymbolAddress((void**)&p_asmax, g_asmax);
    cudaGetSymbolAddress((void**)&p_hiA,  g_hiA);
    cudaGetSymbolAddress((void**)&p_hiB,  g_hiB);
    cudaGetSymbolAddress((void**)&p_wthi, g_wthi);
    cudaGetSymbolAddress((void**)&p_wtlo, g_wtlo);
    cudaGetSymbolAddress((void**)&p_bp,   g_bpv);

    static cudaStream_t s2 = nullptr;
    static cudaEvent_t e0 = nullptr, e1 = nullptr, e2 = nullptr, e3 = nullptr;
    if (!s2) {
        cudaStreamCreateWithFlags(&s2, cudaStreamNonBlocking);
        cudaEventCreateWithFlags(&e0, cudaEventDisableTiming);
        cudaEventCreateWithFlags(&e1, cudaEventDisableTiming);
        cudaEventCreateWithFlags(&e2, cudaEventDisableTiming);
        cudaEventCreateWithFlags(&e3, cudaEventDisableTiming);
        cudaFuncSetAttribute(mma_gemm_kernel,
                             cudaFuncAttributeMaxDynamicSharedMemorySize, 6 * BUFE * 2);
    }

    const int GEMM_GRID = (N_NODES + 127) / 128;
    const int GEMM_SMEM = 6 * BUFE * 2;   // 61440 bytes

    cudaEventRecord(e0, 0);
    cudaStreamWaitEvent(s2, e0, 0);

    // legacy: convx; s2: asmax reset + prep0 concurrently
    convx_kernel<<<(N_NODES * HIDDIM / 4 + 255) / 256, 256>>>(x);
    cudaMemsetAsync(p_asmax, 0, 3 * NHEADS * sizeof(unsigned), s2);
    prep_kernel<<<65, 256, 0, s2>>>(bn_feat, w_feat, b_feat, 0);
    cudaEventRecord(e3, s2);
    cudaMemsetAsync(p_deg, 0, N_NODES * sizeof(int), s2);
    for (int i = 0; i < 3; i++)
        prep_kernel<<<65, 256, 0, s2>>>(bns_conv + i * 512, gat_w + i * 16384,
                                        (const float*)nullptr, i + 1);
    cudaEventRecord(e2, s2);
    count_kernel<<<(N_EDGES + 255) / 256, 256, 0, s2>>>(ei);
    scanA_kernel<<<NSCH, SCHUNK, 0, s2>>>();
    scanB_kernel<<<1, 512, 0, s2>>>();
    scanC_kernel<<<(N_NODES + 255) / 256, 256, 0, s2>>>();
    fill_kernel <<<(N_TOT + 255) / 256, 256, 0, s2>>>(ei);
    cudaMemsetAsync(p_pool, 0, NGROUP * HIDDIM * sizeof(float), s2);
    cudaEventRecord(e1, s2);

    cudaStreamWaitEvent(0, e3, 0);   // prep0 + asmax reset ready
    // feature GEMM (layer 0): writes bf16-hi features for conv0
    mma_gemm_kernel<<<GEMM_GRID, 256, GEMM_SMEM>>>(p_hiA,
                                                   p_wthi, p_wtlo, p_bp,
                                                   (__half*)nullptr, p_hiB,
                                                   (const float*)nullptr,
                                                   (const float*)nullptr,
                                                   (unsigned*)nullptr, 1);
    cudaStreamWaitEvent(0, e2, 0);   // conv weights ready

    __nv_bfloat16* inhi[3] = {p_hiB, p_hiA, p_hiB};
    __nv_bfloat16* othi[3] = {p_hiA, p_hiB, (__nv_bfloat16*)nullptr};

    // conv0 GEMM
    mma_gemm_kernel<<<GEMM_GRID, 256, GEMM_SMEM>>>(inhi[0],
                                                   p_wthi + 16384, p_wtlo + 16384, p_bp + 128,
                                                   p_hm, (__nv_bfloat16*)nullptr,
                                                   att_s, att_d, p_asmax, 0);
    cudaStreamWaitEvent(0, e1, 0);   // CSR + pool-memset ready

    for (int i = 0; i < 3; i++) {
        if (i > 0) {
            mma_gemm_kernel<<<GEMM_GRID, 256, GEMM_SMEM>>>(inhi[i],
                                                           p_wthi + (i + 1) * 16384,
                                                           p_wtlo + (i + 1) * 16384,
                                                           p_bp + (i + 1) * 128,
                                                           p_hm, (__nv_bfloat16*)nullptr,
                                                           att_s + i * 128, att_d + i * 128,
                                                           p_asmax + i * NHEADS, 0);
        }
        gather_kernel<<<(N_NODES * 16 + 255) / 256, 256>>>(gat_b + i * 128,
                                            p_asmax + i * NHEADS,
                                            (i == 2) ? p_h : (float*)nullptr,
                                            othi[i]);
    }

    pool_kernel <<<NSCH, 128>>>(batch);
    fccls_kernel<<<NGROUP, 128>>>(bns_fc, fc_w, fc_b, bn_hid, w_cls, b_cls, out);
}

// round 13
// speedup vs baseline: 1.7338x; 1.0796x over previous
#include <cuda_runtime.h>
#include <cuda_fp16.h>
#include <stdint.h>
#include <math.h>

#define N_NODES 50000
#define N_EDGES 800000
#define N_TOT   (N_EDGES + N_NODES)
#define HIDDIM  128
#define NHEADS  8
#define NGROUP  64
#define NCLASS  10
#define BN_EPS  1e-5f
#define SLOPE   0.2f
#define SCHUNK  128
#define NSCH    ((N_NODES + SCHUNK - 1) / SCHUNK)

// ---------------- device scratch ----------------
static __device__ float g_h   [N_NODES * HIDDIM];                 // fp32 pool input
static __device__ __align__(16) __half g_hm [N_NODES * HIDDIM];   // fp16 messages
static __device__ __align__(16) __half g_fA [N_NODES * HIDDIM];   // fp16 features ping
static __device__ __align__(16) __half g_fB [N_NODES * HIDDIM];   // fp16 features pong
static __device__ __align__(16) __half g_wt [4][HIDDIM * HIDDIM]; // fp16 W' transposed [n][k]
static __device__ float g_bpv [4][HIDDIM];
static __device__ float g_as  [N_NODES * NHEADS];
static __device__ float g_ad  [N_NODES * NHEADS];
static __device__ unsigned g_asmax[3][NHEADS];
static __device__ int   g_rowptr[N_NODES + 1];
static __device__ int   g_cursor[N_NODES];
static __device__ int   g_deg   [N_NODES];
static __device__ int   g_part  [512];
static __device__ int   g_col   [N_TOT];
static __device__ float g_pool [NGROUP * HIDDIM];

// order-preserving float<->uint encoding for atomicMax
__device__ __forceinline__ unsigned fenc(float f) {
    unsigned u = __float_as_uint(f);
    return (u & 0x80000000u) ? ~u : (u | 0x80000000u);
}
__device__ __forceinline__ float fdec(unsigned e) {
    return (e & 0x80000000u) ? __uint_as_float(e ^ 0x80000000u) : __uint_as_float(~e);
}

// ---------------- CSR build ----------------
__global__ void count_kernel(const int* __restrict__ ei) {
    int e = blockIdx.x * blockDim.x + threadIdx.x;
    if (e < N_EDGES) atomicAdd(&g_deg[ei[N_EDGES + e]], 1);
}

__global__ void scanA_kernel() {
    __shared__ int sh[SCHUNK];
    int b = blockIdx.x, t = threadIdx.x;
    int i = b * SCHUNK + t;
    int v = (i < N_NODES) ? (g_deg[i] + 1) : 0;
    sh[t] = v; __syncthreads();
    for (int off = 1; off < SCHUNK; off <<= 1) {
        int x = (t >= off) ? sh[t - off] : 0; __syncthreads();
        sh[t] += x; __syncthreads();
    }
    if (i < N_NODES) g_cursor[i] = sh[t];
    if (t == SCHUNK - 1) g_part[b] = sh[t];
}

__global__ void scanB_kernel() {
    __shared__ int sh[512];
    int t = threadIdx.x;
    int v = (t < NSCH) ? g_part[t] : 0;
    sh[t] = v; __syncthreads();
    for (int off = 1; off < 512; off <<= 1) {
        int x = (t >= off) ? sh[t - off] : 0; __syncthreads();
        sh[t] += x; __syncthreads();
    }
    if (t < NSCH) g_part[t] = sh[t] - v;
    if (t == 511) g_rowptr[N_NODES] = sh[511];
}

__global__ void scanC_kernel() {
    int i = blockIdx.x * blockDim.x + threadIdx.x;
    if (i >= N_NODES) return;
    int excl = g_cursor[i] - (g_deg[i] + 1) + g_part[i / SCHUNK];
    g_rowptr[i] = excl;
    g_cursor[i] = excl;
}

__global__ void fill_kernel(const int* __restrict__ ei) {
    int e = blockIdx.x * blockDim.x + threadIdx.x;
    if (e >= N_TOT) return;
    int s, d;
    if (e < N_EDGES) { s = ei[e]; d = ei[N_EDGES + e]; }
    else             { s = d = e - N_EDGES; }
    int p = atomicAdd(&g_cursor[d], 1);
    g_col[p] = s;
}

// ---------------- input conversion to fp16 ----------------
__global__ void convx_kernel(const float* __restrict__ x) {
    int i = blockIdx.x * blockDim.x + threadIdx.x;
    float4 v = ((const float4*)x)[i];
    __half2 a = __floats2half2_rn(v.x, v.y);
    __half2 b = __floats2half2_rn(v.z, v.w);
    ((__half2*)g_fA)[i*2]   = a;
    ((__half2*)g_fA)[i*2+1] = b;
}

// ---------------- weight prep: BN fold + transpose + fp16, fast bias fold ----------------
__global__ void prep_kernel(const float* __restrict__ bnp, const float* __restrict__ W,
                            const float* __restrict__ extra, int layer) {
    int b = blockIdx.x;
    if (b < 64) {
        int i = b * 256 + threadIdx.x;
        int k = i >> 7, n = i & 127;
        float s = bnp[k] * rsqrtf(bnp[384 + k] + BN_EPS);
        g_wt[layer][n * 128 + k] = __float2half_rn(s * W[i]);
    } else {
        __shared__ float cs[128];
        __shared__ float part[256];
        int t = threadIdx.x;
        if (t < 128) {
            float s = bnp[t] * rsqrtf(bnp[384 + t] + BN_EPS);
            cs[t] = bnp[128 + t] - s * bnp[256 + t];
        }
        __syncthreads();
        int j = t & 127, half = t >> 7;
        float acc = 0.f;
        int k0 = half * 64;
#pragma unroll 8
        for (int k = k0; k < k0 + 64; k++) acc += cs[k] * W[k * HIDDIM + j];
        part[t] = acc;
        __syncthreads();
        if (t < 128) g_bpv[layer][j] = part[j] + part[j + 128] + (extra ? extra[j] : 0.f);
    }
}

// ---------------- cp.async helpers ----------------
__device__ __forceinline__ void cpa16(void* sdst, const void* gsrc, int srcbytes) {
    uint32_t s = (uint32_t)__cvta_generic_to_shared(sdst);
    asm volatile("cp.async.ca.shared.global [%0], [%1], 16, %2;"
                 :: "r"(s), "l"(gsrc), "r"(srcbytes));
}
__device__ __forceinline__ void cpa_commit() {
    asm volatile("cp.async.commit_group;");
}

__device__ __forceinline__ void mma16816h(float c[4], uint32_t a0, uint32_t a1,
                                          uint32_t a2, uint32_t a3,
                                          uint32_t b0, uint32_t b1) {
    asm volatile(
        "mma.sync.aligned.m16n8k16.row.col.f32.f16.f16.f32 "
        "{%0,%1,%2,%3}, {%4,%5,%6,%7}, {%8,%9}, {%0,%1,%2,%3};"
        : "+f"(c[0]), "+f"(c[1]), "+f"(c[2]), "+f"(c[3])
        : "r"(a0), "r"(a1), "r"(a2), "r"(a3), "r"(b0), "r"(b1));
}

// ---------------- tensor-core GEMM: single-term fp16, cp.async pipeline ----------------
#define SMS   40
#define BUFE  (128 * SMS)
__global__ void __launch_bounds__(256)
mma_gemm_kernel(const __half* __restrict__ Ag,
                const __half* __restrict__ Bg,
                const float* __restrict__ bp,
                __half* __restrict__ Cm,            // fp16 message output
                __half* __restrict__ Of,            // fp16 feature output
                const float* __restrict__ att_s,
                const float* __restrict__ att_d,
                unsigned* __restrict__ asmax,
                int do_relu) {
    extern __shared__ __half dsm[];
    __half* sA = dsm;               // [2][BUFE]
    __half* sB = dsm + 2 * BUFE;
    __shared__ unsigned smax[NHEADS];

    int tid = threadIdx.x;
    int wid = tid >> 5, lane = tid & 31;
    int g = lane >> 2, tc = lane & 3;
    int wr = (wid & 3) * 32, wc = (wid >> 2) * 64;
    int row0 = blockIdx.x * 128;

    if (tid < NHEADS) smax[tid] = 0u;

    float c[2][8][4];
#pragma unroll
    for (int a = 0; a < 2; a++)
#pragma unroll
        for (int b = 0; b < 8; b++)
#pragma unroll
            for (int q = 0; q < 4; q++) c[a][b][q] = 0.f;

    int lr = tid >> 1, half = tid & 1;
    int gr = row0 + lr;
    int vb = (gr < N_NODES) ? 16 : 0;
    size_t abase = (size_t)(gr < N_NODES ? gr : 0) * 128 + half * 16;
    int bbase = lr * 128 + half * 16;
    int soff = lr * SMS + half * 16;

    auto issue = [&](int k, int buf) {
        int k0 = k * 32;
        cpa16(sA + buf * BUFE + soff,     Ag + abase + k0,     vb);
        cpa16(sA + buf * BUFE + soff + 8, Ag + abase + k0 + 8, vb);
        cpa16(sB + buf * BUFE + soff,     Bg + bbase + k0,     16);
        cpa16(sB + buf * BUFE + soff + 8, Bg + bbase + k0 + 8, 16);
        cpa_commit();
    };

    issue(0, 0);
    for (int k = 0; k < 4; k++) {
        int cur = k & 1;
        if (k < 3) {
            issue(k + 1, cur ^ 1);
            asm volatile("cp.async.wait_group 1;");
        } else {
            asm volatile("cp.async.wait_group 0;");
        }
        __syncthreads();

        const __half* Ah = sA + cur * BUFE;
        const __half* Bh = sB + cur * BUFE;
#pragma unroll
        for (int s = 0; s < 2; s++) {
            int kb = s * 16;
            uint32_t ah[2][4];
#pragma unroll
            for (int mf = 0; mf < 2; mf++) {
                int m = wr + mf * 16 + g;
                ah[mf][0] = *(const uint32_t*)(Ah + m * SMS + kb + tc * 2);
                ah[mf][1] = *(const uint32_t*)(Ah + (m + 8) * SMS + kb + tc * 2);
                ah[mf][2] = *(const uint32_t*)(Ah + m * SMS + kb + tc * 2 + 8);
                ah[mf][3] = *(const uint32_t*)(Ah + (m + 8) * SMS + kb + tc * 2 + 8);
            }
            uint32_t bh[8][2];
#pragma unroll
            for (int nf = 0; nf < 8; nf++) {
                int n = wc + nf * 8 + g;
                bh[nf][0] = *(const uint32_t*)(Bh + n * SMS + kb + tc * 2);
                bh[nf][1] = *(const uint32_t*)(Bh + n * SMS + kb + tc * 2 + 8);
            }
#pragma unroll
            for (int mf = 0; mf < 2; mf++)
#pragma unroll
                for (int nf = 0; nf < 8; nf++)
                    mma16816h(c[mf][nf], ah[mf][0], ah[mf][1], ah[mf][2], ah[mf][3],
                              bh[nf][0], bh[nf][1]);
        }
        __syncthreads();
    }

    // epilogue
#pragma unroll
    for (int mf = 0; mf < 2; mf++) {
        int r0 = row0 + wr + mf * 16 + g;
        int r1 = r0 + 8;
        float ps0[4] = {0,0,0,0}, pd0[4] = {0,0,0,0};
        float ps1[4] = {0,0,0,0}, pd1[4] = {0,0,0,0};
#pragma unroll
        for (int nf = 0; nf < 8; nf++) {
            int cc = wc + nf * 8 + tc * 2;
            float b0 = bp[cc], b1 = bp[cc + 1];
            float v00 = c[mf][nf][0] + b0, v01 = c[mf][nf][1] + b1;
            float v10 = c[mf][nf][2] + b0, v11 = c[mf][nf][3] + b1;
            if (do_relu) {
                v00 = fmaxf(v00, 0.f); v01 = fmaxf(v01, 0.f);
                v10 = fmaxf(v10, 0.f); v11 = fmaxf(v11, 0.f);
            }
            if (att_s) {
                int hl = nf >> 1;
                float as0 = att_s[cc], as1 = att_s[cc + 1];
                float ad0 = att_d[cc], ad1 = att_d[cc + 1];
                ps0[hl] += v00 * as0 + v01 * as1;
                pd0[hl] += v00 * ad0 + v01 * ad1;
                ps1[hl] += v10 * as0 + v11 * as1;
                pd1[hl] += v10 * ad0 + v11 * ad1;
            }
            if (Cm) {
                if (r0 < N_NODES)
                    *(__half2*)(Cm + (size_t)r0 * 128 + cc) = __floats2half2_rn(v00, v01);
                if (r1 < N_NODES)
                    *(__half2*)(Cm + (size_t)r1 * 128 + cc) = __floats2half2_rn(v10, v11);
            }
            if (Of) {
                if (r0 < N_NODES)
                    *(__half2*)(Of + (size_t)r0 * 128 + cc) = __floats2half2_rn(v00, v01);
                if (r1 < N_NODES)
                    *(__half2*)(Of + (size_t)r1 * 128 + cc) = __floats2half2_rn(v10, v11);
            }
        }
        if (att_s) {
#pragma unroll
            for (int h = 0; h < 4; h++) {
                ps0[h] += __shfl_xor_sync(0xffffffffu, ps0[h], 1);
                ps0[h] += __shfl_xor_sync(0xffffffffu, ps0[h], 2);
                pd0[h] += __shfl_xor_sync(0xffffffffu, pd0[h], 1);
                pd0[h] += __shfl_xor_sync(0xffffffffu, pd0[h], 2);
                ps1[h] += __shfl_xor_sync(0xffffffffu, ps1[h], 1);
                ps1[h] += __shfl_xor_sync(0xffffffffu, ps1[h], 2);
                pd1[h] += __shfl_xor_sync(0xffffffffu, pd1[h], 1);
                pd1[h] += __shfl_xor_sync(0xffffffffu, pd1[h], 2);
            }
            if (tc == 0) {
                int hb = wc >> 4;
                if (r0 < N_NODES) {
#pragma unroll
                    for (int h = 0; h < 4; h++) {
                        g_as[r0 * 8 + hb + h] = ps0[h];
                        g_ad[r0 * 8 + hb + h] = pd0[h];
                        atomicMax(&smax[hb + h], fenc(ps0[h]));
                    }
                }
                if (r1 < N_NODES) {
#pragma unroll
                    for (int h = 0; h < 4; h++) {
                        g_as[r1 * 8 + hb + h] = ps1[h];
                        g_ad[r1 * 8 + hb + h] = pd1[h];
                        atomicMax(&smax[hb + h], fenc(ps1[h]));
                    }
                }
            }
        }
    }
    if (att_s) {
        __syncthreads();
        if (tid < NHEADS) atomicMax(&asmax[tid], smax[tid]);
    }
}

// ---------------- GAT gather: bound-based softmax, fp16 messages ----------------
__global__ void gather_kernel(const float* __restrict__ bias,
                              const unsigned* __restrict__ asmax,
                              float* __restrict__ outF,
                              __half* __restrict__ Ohf) {
    int node = (blockIdx.x * blockDim.x + threadIdx.x) >> 4;
    if (node >= N_NODES) return;
    int l16 = threadIdx.x & 15;
    int head = l16 >> 1;
    int beg = g_rowptr[node];
    int end = g_rowptr[node + 1];

    float adh = g_ad[node * 8 + head];
    float bnd = fdec(asmax[head]) + adh;
    bnd = bnd > 0.f ? bnd : SLOPE * bnd;

    float s = 0.f;
    float a0 = 0.f, a1 = 0.f, a2 = 0.f, a3 = 0.f;
    float a4 = 0.f, a5 = 0.f, a6 = 0.f, a7 = 0.f;

#pragma unroll 2
    for (int e = beg; e < end; e++) {
        int src = g_col[e];
        float l = __ldg(g_as + src * 8 + head) + adh;
        l = l > 0.f ? l : SLOPE * l;
        float w = __expf(l - bnd);
        uint4 raw = *(const uint4*)(g_hm + (size_t)src * 128 + l16 * 8);
        __half2* ph = (__half2*)&raw;
        float2 f0 = __half22float2(ph[0]);
        float2 f1 = __half22float2(ph[1]);
        float2 f2 = __half22float2(ph[2]);
        float2 f3 = __half22float2(ph[3]);
        s  += w;
        a0 += w * f0.x; a1 += w * f0.y;
        a2 += w * f1.x; a3 += w * f1.y;
        a4 += w * f2.x; a5 += w * f2.y;
        a6 += w * f3.x; a7 += w * f3.y;
    }
    float inv = 1.f / (s + 1e-16f);
    float4 b0 = ((const float4*)bias)[l16 * 2];
    float4 b1 = ((const float4*)bias)[l16 * 2 + 1];
    float4 o0, o1;
    o0.x = fmaxf(a0 * inv + b0.x, 0.f);
    o0.y = fmaxf(a1 * inv + b0.y, 0.f);
    o0.z = fmaxf(a2 * inv + b0.z, 0.f);
    o0.w = fmaxf(a3 * inv + b0.w, 0.f);
    o1.x = fmaxf(a4 * inv + b1.x, 0.f);
    o1.y = fmaxf(a5 * inv + b1.y, 0.f);
    o1.z = fmaxf(a6 * inv + b1.z, 0.f);
    o1.w = fmaxf(a7 * inv + b1.w, 0.f);

    if (outF) {
        ((float4*)(outF + (size_t)node * 128))[l16 * 2]     = o0;
        ((float4*)(outF + (size_t)node * 128))[l16 * 2 + 1] = o1;
    }
    if (Ohf) {
        __half2 hv[4];
        hv[0] = __floats2half2_rn(o0.x, o0.y);
        hv[1] = __floats2half2_rn(o0.z, o0.w);
        hv[2] = __floats2half2_rn(o1.x, o1.y);
        hv[3] = __floats2half2_rn(o1.z, o1.w);
        *(uint4*)(Ohf + (size_t)node * 128 + l16 * 8) = *(const uint4*)hv;
    }
}

// ---------------- pooling ----------------
__global__ void pool_kernel(const int* __restrict__ batch) {
    int b = blockIdx.x, c = threadIdx.x;
    int r0 = b * SCHUNK, r1 = min(r0 + SCHUNK, N_NODES);
    float acc = 0.f;
    int cur = batch[r0];
    for (int r = r0; r < r1; r++) {
        int gb = batch[r];
        if (gb != cur) { atomicAdd(&g_pool[cur * 128 + c], acc); acc = 0.f; cur = gb; }
        acc += g_h[(size_t)r * 128 + c];
    }
    atomicAdd(&g_pool[cur * 128 + c], acc);
}

// ---------------- fused FC + classifier + log_softmax ----------------
__global__ void fccls_kernel(const float* __restrict__ bnfc, const float* __restrict__ fcW,
                             const float* __restrict__ fcb,
                             const float* __restrict__ bnh, const float* __restrict__ Wc,
                             const float* __restrict__ bc, float* __restrict__ out) {
    __shared__ float sh[128];
    __shared__ float sh2[128];
    __shared__ float lg[NCLASS];
    __shared__ float s_mx, s_ls;
    int g = blockIdx.x, t = threadIdx.x;
    float x = g_pool[g * 128 + t];
    float s = bnfc[t] * rsqrtf(bnfc[384 + t] + BN_EPS);
    sh[t] = s * (x - bnfc[256 + t]) + bnfc[128 + t];
    __syncthreads();
    float acc = fcb[t];
    for (int k = 0; k < 128; k++) acc += sh[k] * fcW[k * 128 + t];
    float fo = fmaxf(acc, 0.f);
    float s2 = bnh[t] * rsqrtf(bnh[384 + t] + BN_EPS);
    sh2[t] = s2 * (fo - bnh[256 + t]) + bnh[128 + t];
    __syncthreads();
    if (t < NCLASS) {
        float a2 = bc[t];
        for (int k = 0; k < 128; k++) a2 += sh2[k] * Wc[k * NCLASS + t];
        lg[t] = a2;
    }
    __syncthreads();
    if (t == 0) {
        float mx = lg[0];
        for (int j = 1; j < NCLASS; j++) mx = fmaxf(mx, lg[j]);
        float se = 0.f;
        for (int j = 0; j < NCLASS; j++) se += expf(lg[j] - mx);
        s_mx = mx; s_ls = logf(se);
    }
    __syncthreads();
    if (t < NCLASS) out[g * NCLASS + t] = lg[t] - s_mx - s_ls;
}

// ---------------- launch ----------------
extern "C" void kernel_launch(void* const* d_in, const int* in_sizes, int n_in,
                              void* d_out, int out_size) {
    const float* x        = (const float*)d_in[0];
    const int*   ei       = (const int*)d_in[1];
    const int*   batch    = (const int*)d_in[2];
    const float* bn_feat  = (const float*)d_in[3];
    const float* w_feat   = (const float*)d_in[4];
    const float* b_feat   = (const float*)d_in[5];
    const float* bns_conv = (const float*)d_in[6];
    const float* gat_w    = (const float*)d_in[7];
    const float* att_s    = (const float*)d_in[8];
    const float* att_d    = (const float*)d_in[9];
    const float* gat_b    = (const float*)d_in[10];
    const float* bns_fc   = (const float*)d_in[11];
    const float* fc_w     = (const float*)d_in[12];
    const float* fc_b     = (const float*)d_in[13];
    const float* bn_hid   = (const float*)d_in[14];
    const float* w_cls    = (const float*)d_in[15];
    const float* b_cls    = (const float*)d_in[16];
    float* out = (float*)d_out;

    float *p_h = nullptr, *p_pool = nullptr, *p_bp = nullptr;
    __half *p_hm = nullptr, *p_fA = nullptr, *p_fB = nullptr, *p_wt = nullptr;
    int* p_deg = nullptr;
    unsigned* p_asmax = nullptr;
    cudaGetSymbolAddress((void**)&p_h,    g_h);
    cudaGetSymbolAddress((void**)&p_hm,   g_hm);
    cudaGetSymbolAddress((void**)&p_fA,   g_fA);
    cudaGetSymbolAddress((void**)&p_fB,   g_fB);
    cudaGetSymbolAddress((void**)&p_wt,   g_wt);
    cudaGetSymbolAddress((void**)&p_pool, g_pool);
    cudaGetSymbolAddress((void**)&p_deg,  g_deg);
    cudaGetSymbolAddress((void**)&p_asmax, g_asmax);
    cudaGetSymbolAddress((void**)&p_bp,   g_bpv);

    static cudaStream_t s2 = nullptr;
    static cudaEvent_t e0 = nullptr, e1 = nullptr, e2 = nullptr, e3 = nullptr;
    if (!s2) {
        cudaStreamCreateWithFlags(&s2, cudaStreamNonBlocking);
        cudaEventCreateWithFlags(&e0, cudaEventDisableTiming);
        cudaEventCreateWithFlags(&e1, cudaEventDisableTiming);
        cudaEventCreateWithFlags(&e2, cudaEventDisableTiming);
        cudaEventCreateWithFlags(&e3, cudaEventDisableTiming);
        cudaFuncSetAttribute(mma_gemm_kernel,
                             cudaFuncAttributeMaxDynamicSharedMemorySize, 4 * BUFE * 2);
    }

    const int GEMM_GRID = (N_NODES + 127) / 128;
    const int GEMM_SMEM = 4 * BUFE * 2;   // 40960 bytes

    cudaEventRecord(e0, 0);
    cudaStreamWaitEvent(s2, e0, 0);

    // legacy: convx; s2: asmax reset + prep0 concurrently
    convx_kernel<<<(N_NODES * HIDDIM / 4 + 255) / 256, 256>>>(x);
    cudaMemsetAsync(p_asmax, 0, 3 * NHEADS * sizeof(unsigned), s2);
    prep_kernel<<<65, 256, 0, s2>>>(bn_feat, w_feat, b_feat, 0);
    cudaEventRecord(e3, s2);
    cudaMemsetAsync(p_deg, 0, N_NODES * sizeof(int), s2);
    for (int i = 0; i < 3; i++)
        prep_kernel<<<65, 256, 0, s2>>>(bns_conv + i * 512, gat_w + i * 16384,
                                        (const float*)nullptr, i + 1);
    cudaEventRecord(e2, s2);
    count_kernel<<<(N_EDGES + 255) / 256, 256, 0, s2>>>(ei);
    scanA_kernel<<<NSCH, SCHUNK, 0, s2>>>();
    scanB_kernel<<<1, 512, 0, s2>>>();
    scanC_kernel<<<(N_NODES + 255) / 256, 256, 0, s2>>>();
    fill_kernel <<<(N_TOT + 255) / 256, 256, 0, s2>>>(ei);
    cudaMemsetAsync(p_pool, 0, NGROUP * HIDDIM * sizeof(float), s2);
    cudaEventRecord(e1, s2);

    cudaStreamWaitEvent(0, e3, 0);   // prep0 + asmax reset ready
    // feature GEMM (layer 0): fA -> fB (relu)
    mma_gemm_kernel<<<GEMM_GRID, 256, GEMM_SMEM>>>(p_fA, p_wt, p_bp,
                                                   (__half*)nullptr, p_fB,
                                                   (const float*)nullptr,
                                                   (const float*)nullptr,
                                                   (unsigned*)nullptr, 1);
    cudaStreamWaitEvent(0, e2, 0);   // conv weights ready

    __half* inF[3] = {p_fB, p_fA, p_fB};
    __half* otF[3] = {p_fA, p_fB, (__half*)nullptr};

    // conv0 GEMM: fB -> messages
    mma_gemm_kernel<<<GEMM_GRID, 256, GEMM_SMEM>>>(inF[0],
                                                   p_wt + 16384, p_bp + 128,
                                                   p_hm, (__half*)nullptr,
                                                   att_s, att_d, p_asmax, 0);
    cudaStreamWaitEvent(0, e1, 0);   // CSR + pool-memset ready

    for (int i = 0; i < 3; i++) {
        if (i > 0) {
            mma_gemm_kernel<<<GEMM_GRID, 256, GEMM_SMEM>>>(inF[i],
                                                           p_wt + (i + 1) * 16384,
                                                           p_bp + (i + 1) * 128,
                                                           p_hm, (__half*)nullptr,
                                                           att_s + i * 128, att_d + i * 128,
                                                           p_asmax + i * NHEADS, 0);
        }
        gather_kernel<<<(N_NODES * 16 + 255) / 256, 256>>>(gat_b + i * 128,
                                            p_asmax + i * NHEADS,
                                            (i == 2) ? p_h : (float*)nullptr,
                                            otF[i]);
    }

    pool_kernel <<<NSCH, 128>>>(batch);
    fccls_kernel<<<NGROUP, 128>>>(bns_fc, fc_w, fc_b, bn_hid, w_cls, b_cls, out);
}